// round 8
// baseline (speedup 1.0000x reference)
#include <cuda_runtime.h>
#include <cuda_bf16.h>
#include <cstdint>
#include <math.h>

// ============================ problem constants ============================
#define NPTS 131072          // B*N = 1024*128
#define NEDG 524288          // NPTS * K(=4)

// Concat buffer layout (all segment starts 16B-aligned; pads never written => 0)
#define F_OFS  0
#define O1_OFS 8
#define O2_OFS 72
#define O3_OFS 200
#define XLD    456

// ============================ device scratch ===============================
__device__ float g_X453[(size_t)NPTS * XLD];
__device__ float g_PQ[(size_t)NPTS * 384];
__device__ float g_H1[(size_t)NPTS * 456];
__device__ int   g_idx[NPTS * 4];
__device__ float g_Wt[512 * 480];

__device__ __forceinline__ float eluf(float x) { return x > 0.f ? x : expm1f(x); }

// ============================ small helpers ================================
__device__ __forceinline__ void sp_tf32(float a, float& h, float& l) {
    uint32_t hu;
    asm("cvt.rna.tf32.f32 %0, %1;" : "=r"(hu) : "f"(a));
    h = __uint_as_float(hu);
    float lf = a - h;
    uint32_t lu;
    asm("cvt.rna.tf32.f32 %0, %1;" : "=r"(lu) : "f"(lf));
    l = __uint_as_float(lu);
}
__device__ __forceinline__ void mma8(float* c, const uint32_t* a, const uint32_t* b) {
    asm volatile("mma.sync.aligned.m16n8k8.row.col.f32.tf32.tf32.f32 "
                 "{%0,%1,%2,%3}, {%4,%5,%6,%7}, {%8,%9}, {%0,%1,%2,%3};"
                 : "+f"(c[0]), "+f"(c[1]), "+f"(c[2]), "+f"(c[3])
                 : "r"(a[0]), "r"(a[1]), "r"(a[2]), "r"(a[3]), "r"(b[0]), "r"(b[1]));
}
__device__ __forceinline__ void sp_bf(float a0, float a1, uint32_t& h, uint32_t& l) {
    __nv_bfloat162 hh = __floats2bfloat162_rn(a0, a1);
    float r0 = a0 - __bfloat162float(hh.x);
    float r1 = a1 - __bfloat162float(hh.y);
    __nv_bfloat162 ll = __floats2bfloat162_rn(r0, r1);
    h = *reinterpret_cast<uint32_t*>(&hh);
    l = *reinterpret_cast<uint32_t*>(&ll);
}
__device__ __forceinline__ void mma16(float* c, const uint32_t* a, const uint32_t* b) {
    asm volatile("mma.sync.aligned.m16n8k16.row.col.f32.bf16.bf16.f32 "
                 "{%0,%1,%2,%3}, {%4,%5,%6,%7}, {%8,%9}, {%0,%1,%2,%3};"
                 : "+f"(c[0]), "+f"(c[1]), "+f"(c[2]), "+f"(c[3])
                 : "r"(a[0]), "r"(a[1]), "r"(a[2]), "r"(a[3]), "r"(b[0]), "r"(b[1]));
}

// ============================ elementwise helpers ==========================
__global__ void copy_features_k(const float* __restrict__ f, float* __restrict__ X) {
    int e = blockIdx.x * blockDim.x + threadIdx.x;
    if (e < NPTS * 5) {
        int r = e / 5, c = e % 5;
        X[(size_t)r * XLD + c] = f[e];
    }
}
__global__ void prep_pq_k(const float* __restrict__ w1, float* __restrict__ wt, int C, int H, int Kpad) {
    int e = blockIdx.x * blockDim.x + threadIdx.x;
    if (e >= 2 * H * Kpad) return;
    int n = e / Kpad, k = e % Kpad;
    float v = 0.f;
    if (k < C) v = (n < H) ? (w1[k * H + n] - w1[(C + k) * H + n]) : w1[(C + k) * H + (n - H)];
    wt[(size_t)n * Kpad + k] = v;
}
__global__ void prep_wt_k(const float* __restrict__ w, float* __restrict__ wt, int K, int N, int Kpad) {
    int e = blockIdx.x * blockDim.x + threadIdx.x;
    if (e >= N * Kpad) return;
    int n = e / Kpad, k = e % Kpad;
    wt[(size_t)n * Kpad + k] = (k < K) ? w[(size_t)k * N + n] : 0.f;
}
__global__ void prep_head_k(const float* __restrict__ w, float* __restrict__ wt, int N, int Kpad) {
    int e = blockIdx.x * blockDim.x + threadIdx.x;
    if (e >= N * Kpad) return;
    int n = e / Kpad, kp = e % Kpad;
    float v = 0.f;
    if (kp < 5)                   v = w[(size_t)kp * N + n];
    else if (kp >= 8 && kp < 456) v = w[(size_t)(kp - 3) * N + n];
    wt[(size_t)n * Kpad + kp] = v;
}

// ============================ KNN (k=4; 2 batches per block) ===============
// Per-batch arithmetic identical to prior rounds -> bit-identical indices.
template<int C, int CP>
__global__ void __launch_bounds__(256) knn_k(const float* __restrict__ x, int ld, int cofs,
                                             int* __restrict__ idxout) {
    constexpr int PAD = CP + 4;
    __shared__ __align__(16) float sx[2][32][PAD];
    __shared__ float sn[2][128];
    int half = threadIdx.x >> 7;
    int tid = threadIdx.x & 127;
    int b = blockIdx.x * 2 + half;
    const float* xb = x + (size_t)b * 128 * ld + cofs;
    float4 xi[CP / 4];

    for (int t = 0; t < 4; t++) {
        for (int e = tid; e < 32 * CP; e += 128) {
            int r = e / CP, c = e % CP;
            sx[half][r][c] = (c < C) ? xb[(size_t)(t * 32 + r) * ld + c] : 0.f;
        }
        __syncthreads();
        if ((tid >> 5) == t) {
            int r = tid & 31;
            #pragma unroll
            for (int c4 = 0; c4 < CP / 4; c4++) xi[c4] = *(const float4*)&sx[half][r][4 * c4];
        }
        __syncthreads();
    }
    float ni = 0.f;
    #pragma unroll
    for (int c4 = 0; c4 < CP / 4; c4++)
        ni += xi[c4].x * xi[c4].x + xi[c4].y * xi[c4].y + xi[c4].z * xi[c4].z + xi[c4].w * xi[c4].w;
    sn[half][tid] = ni;
    __syncthreads();

    float bd0 = 1e30f, bd1 = 1e30f, bd2 = 1e30f, bd3 = 1e30f;
    int   bi0 = 0,     bi1 = 0,     bi2 = 0,     bi3 = 0;

    for (int t = 0; t < 4; t++) {
        for (int e = tid; e < 32 * CP; e += 128) {
            int r = e / CP, c = e % CP;
            sx[half][r][c] = (c < C) ? xb[(size_t)(t * 32 + r) * ld + c] : 0.f;
        }
        __syncthreads();
        for (int jl = 0; jl < 32; jl++) {
            int j = t * 32 + jl;
            float dot = 0.f;
            #pragma unroll
            for (int c4 = 0; c4 < CP / 4; c4++) {
                float4 xj = *(const float4*)&sx[half][jl][4 * c4];
                dot += xi[c4].x * xj.x + xi[c4].y * xj.y + xi[c4].z * xj.z + xi[c4].w * xj.w;
            }
            float d = ni + sn[half][j] - 2.f * dot;
            if (j == tid) d = 1e30f;
            if (d < bd3) {
                if (d < bd2) {
                    bd3 = bd2; bi3 = bi2;
                    if (d < bd1) {
                        bd2 = bd1; bi2 = bi1;
                        if (d < bd0) { bd1 = bd0; bi1 = bi0; bd0 = d; bi0 = j; }
                        else         { bd1 = d; bi1 = j; }
                    } else { bd2 = d; bi2 = j; }
                } else { bd3 = d; bi3 = j; }
            }
        }
        __syncthreads();
    }
    int base = (b * 128 + tid) * 4;
    int gb = b * 128;
    idxout[base + 0] = gb + bi0;
    idxout[base + 1] = gb + bi1;
    idxout[base + 2] = gb + bi2;
    idxout[base + 3] = gb + bi3;
}

// ============================ tf32 3-term GEMM (R6 kernel; KNN-feeding) ====
#define AP 36
#define AFLTS (128 * AP)
#define BFLTS (64 * AP)
#define SFL (2 * AFLTS + 2 * BFLTS)
template<int GATHER, int ACT, int RED>
__global__ void __launch_bounds__(256, 2) tfgemm_k(
    const float* __restrict__ A, int lda, int Kval,
    const float* __restrict__ PQ, int ldpq, int qofs,
    const float* __restrict__ b1, const int* __restrict__ eidx,
    const float* __restrict__ Wt, int Kpad,
    const float* __restrict__ bias,
    float* __restrict__ Co, int ldc, int cofs, int Nfull)
{
    extern __shared__ float sm[];
    const int tid = threadIdx.x;
    const int wid = tid >> 5, lane = tid & 31;
    const int g = lane >> 2, q = lane & 3;
    const int warp_m = wid >> 1, warp_n = wid & 1;
    const int m0 = blockIdx.y * 128;
    const int n0 = blockIdx.x * 64;
    const int iters = Kpad >> 5;

    const int lm = tid >> 3, lkc = (tid & 7) << 2;
    const int lr = tid >> 1, lh = (tid & 1) << 4;

    const float *Pp = nullptr, *Qp = nullptr;
    if (GATHER) {
        int mg = m0 + lr;
        Pp = PQ + (size_t)(mg >> 2) * ldpq;
        Qp = PQ + (size_t)eidx[mg] * ldpq + qofs;
    }

    float4 rA[4], rQ[4], rB[2];

    auto ldg_tile = [&](int it) {
        const int k0 = it << 5;
        if (GATHER) {
            #pragma unroll
            for (int qq = 0; qq < 4; qq++) {
                int kk = k0 + lh + (qq << 2);
                rA[qq] = *(const float4*)(Pp + kk);
                rQ[qq] = *(const float4*)(Qp + kk);
            }
        } else {
            #pragma unroll
            for (int i = 0; i < 4; i++) {
                int gk = k0 + lkc;
                const float* src = A + (size_t)(m0 + lm + i * 32) * lda + gk;
                if (gk + 3 < Kval) {
                    rA[i] = *(const float4*)src;
                } else {
                    rA[i] = make_float4(0.f, 0.f, 0.f, 0.f);
                    if (gk + 0 < Kval) rA[i].x = src[0];
                    if (gk + 1 < Kval) rA[i].y = src[1];
                    if (gk + 2 < Kval) rA[i].z = src[2];
                }
            }
        }
        #pragma unroll
        for (int i = 0; i < 2; i++) {
            int gn = n0 + lm + i * 32;
            if (gn < Nfull) rB[i] = *(const float4*)(Wt + (size_t)gn * Kpad + (it << 5) + lkc);
            else            rB[i] = make_float4(0.f, 0.f, 0.f, 0.f);
        }
    };

    auto sts_tile = [&](int s, int it) {
        float* Ah = sm + s * SFL;
        float* Al = Ah + AFLTS;
        float* Bh = sm + s * SFL + 2 * AFLTS;
        float* Bl = Bh + BFLTS;
        if (GATHER) {
            const int k0 = it << 5;
            #pragma unroll
            for (int qq = 0; qq < 4; qq++) {
                int kk = lh + (qq << 2);
                float4 bv = *(const float4*)(b1 + k0 + kk);
                float4 hv, lv;
                sp_tf32(eluf(rA[qq].x + rQ[qq].x + bv.x), hv.x, lv.x);
                sp_tf32(eluf(rA[qq].y + rQ[qq].y + bv.y), hv.y, lv.y);
                sp_tf32(eluf(rA[qq].z + rQ[qq].z + bv.z), hv.z, lv.z);
                sp_tf32(eluf(rA[qq].w + rQ[qq].w + bv.w), hv.w, lv.w);
                *(float4*)&Ah[lr * AP + kk] = hv;
                *(float4*)&Al[lr * AP + kk] = lv;
            }
        } else {
            #pragma unroll
            for (int i = 0; i < 4; i++) {
                float4 hv, lv;
                sp_tf32(rA[i].x, hv.x, lv.x);
                sp_tf32(rA[i].y, hv.y, lv.y);
                sp_tf32(rA[i].z, hv.z, lv.z);
                sp_tf32(rA[i].w, hv.w, lv.w);
                *(float4*)&Ah[(lm + i * 32) * AP + lkc] = hv;
                *(float4*)&Al[(lm + i * 32) * AP + lkc] = lv;
            }
        }
        #pragma unroll
        for (int i = 0; i < 2; i++) {
            float4 hv, lv;
            sp_tf32(rB[i].x, hv.x, lv.x);
            sp_tf32(rB[i].y, hv.y, lv.y);
            sp_tf32(rB[i].z, hv.z, lv.z);
            sp_tf32(rB[i].w, hv.w, lv.w);
            *(float4*)&Bh[(lm + i * 32) * AP + lkc] = hv;
            *(float4*)&Bl[(lm + i * 32) * AP + lkc] = lv;
        }
    };

    float acc[2][4][4];
    #pragma unroll
    for (int mt = 0; mt < 2; mt++)
        #pragma unroll
        for (int nt = 0; nt < 4; nt++)
            #pragma unroll
            for (int i = 0; i < 4; i++) acc[mt][nt][i] = 0.f;

    const int abase = (warp_m * 32 + g) * AP;
    const int bbase = (warp_n * 32 + g) * AP;

    ldg_tile(0);
    sts_tile(0, 0);
    for (int it = 0; it < iters; it++) {
        if (it + 1 < iters) ldg_tile(it + 1);
        __syncthreads();
        const int s = it & 1;
        const float* Ah = sm + s * SFL;
        const float* Al = Ah + AFLTS;
        const float* Bh = sm + s * SFL + 2 * AFLTS;
        const float* Bl = Bh + BFLTS;
        #pragma unroll
        for (int ks = 0; ks < 4; ks++) {
            const int kb = (ks << 3) + q;
            uint32_t ah[2][4], al[2][4];
            #pragma unroll
            for (int mt = 0; mt < 2; mt++) {
                int rb = abase + mt * 16 * AP;
                ah[mt][0] = __float_as_uint(Ah[rb + kb]);
                al[mt][0] = __float_as_uint(Al[rb + kb]);
                ah[mt][1] = __float_as_uint(Ah[rb + 8 * AP + kb]);
                al[mt][1] = __float_as_uint(Al[rb + 8 * AP + kb]);
                ah[mt][2] = __float_as_uint(Ah[rb + kb + 4]);
                al[mt][2] = __float_as_uint(Al[rb + kb + 4]);
                ah[mt][3] = __float_as_uint(Ah[rb + 8 * AP + kb + 4]);
                al[mt][3] = __float_as_uint(Al[rb + 8 * AP + kb + 4]);
            }
            uint32_t bh[4][2], bl[4][2];
            #pragma unroll
            for (int nt = 0; nt < 4; nt++) {
                int rb = bbase + nt * 8 * AP;
                bh[nt][0] = __float_as_uint(Bh[rb + kb]);
                bl[nt][0] = __float_as_uint(Bl[rb + kb]);
                bh[nt][1] = __float_as_uint(Bh[rb + kb + 4]);
                bl[nt][1] = __float_as_uint(Bl[rb + kb + 4]);
            }
            #pragma unroll
            for (int mt = 0; mt < 2; mt++)
                #pragma unroll
                for (int nt = 0; nt < 4; nt++) {
                    mma8(acc[mt][nt], ah[mt], bh[nt]);
                    mma8(acc[mt][nt], al[mt], bh[nt]);
                    mma8(acc[mt][nt], ah[mt], bl[nt]);
                }
        }
        if (it + 1 < iters) sts_tile((it + 1) & 1, it + 1);
    }

    #pragma unroll
    for (int mt = 0; mt < 2; mt++) {
        const int rbase = m0 + warp_m * 32 + mt * 16;
        #pragma unroll
        for (int nt = 0; nt < 4; nt++) {
            const int cl = warp_n * 32 + nt * 8 + 2 * q;
            const int gc = n0 + cl;
            float bb0 = 0.f, bb1 = 0.f;
            if (bias != nullptr) {
                if (gc < Nfull)     bb0 = bias[gc];
                if (gc + 1 < Nfull) bb1 = bias[gc + 1];
            }
            if (!RED) {
                float v0 = acc[mt][nt][0] + bb0, v1 = acc[mt][nt][1] + bb1;
                float v2 = acc[mt][nt][2] + bb0, v3 = acc[mt][nt][3] + bb1;
                if (ACT) { v0 = eluf(v0); v1 = eluf(v1); v2 = eluf(v2); v3 = eluf(v3); }
                float* r0 = Co + (size_t)(rbase + g) * ldc + cofs;
                float* r1 = r0 + (size_t)8 * ldc;
                if (gc < Nfull)     { r0[gc] = v0;     r1[gc] = v2; }
                if (gc + 1 < Nfull) { r0[gc + 1] = v1; r1[gc + 1] = v3; }
            } else {
                #pragma unroll
                for (int half = 0; half < 2; half++) {
                    float v0 = (gc < Nfull)     ? eluf(acc[mt][nt][2 * half + 0] + bb0) : 0.f;
                    float v1 = (gc + 1 < Nfull) ? eluf(acc[mt][nt][2 * half + 1] + bb1) : 0.f;
                    v0 += __shfl_xor_sync(0xffffffffu, v0, 4);
                    v0 += __shfl_xor_sync(0xffffffffu, v0, 8);
                    v1 += __shfl_xor_sync(0xffffffffu, v1, 4);
                    v1 += __shfl_xor_sync(0xffffffffu, v1, 8);
                    if ((lane & 12) == 0) {
                        int p = (rbase + half * 8 + g) >> 2;
                        float* op = Co + (size_t)p * ldc + cofs;
                        if (gc < Nfull)     op[gc] = 0.25f * v0;
                        if (gc + 1 < Nfull) op[gc + 1] = 0.25f * v1;
                    }
                }
            }
        }
    }
}

// ============================ bf16 3-term GEMM (R7 kernel; post-KNN) =======
#define APU 20
#define AHLU (128 * APU)
#define BHLU (64 * APU)
#define SFLU (2 * AHLU + 2 * BHLU)
template<int GATHER, int ACT, int RED>
__global__ void __launch_bounds__(256, 2) bfgemm_k(
    const float* __restrict__ A, int lda, int Kval,
    const float* __restrict__ PQ, int ldpq, int qofs,
    const float* __restrict__ b1, const int* __restrict__ eidx,
    const float* __restrict__ Wt, int Kpad,
    const float* __restrict__ bias,
    float* __restrict__ Co, int ldc, int cofs, int Nfull)
{
    extern __shared__ uint32_t smu[];
    const int tid = threadIdx.x;
    const int wid = tid >> 5, lane = tid & 31;
    const int g = lane >> 2, q = lane & 3;
    const int warp_m = wid >> 1, warp_n = wid & 1;
    const int m0 = blockIdx.y * 128;
    const int n0 = blockIdx.x * 64;
    const int iters = Kpad >> 5;

    const int lm = tid >> 3, lkc = (tid & 7) << 2;
    const int luc = (tid & 7) << 1;
    const int lr = tid >> 1, lh = (tid & 1) << 4;
    const int lgu = (tid & 1) << 3;

    const float *Pp = nullptr, *Qp = nullptr;
    if (GATHER) {
        int mg = m0 + lr;
        Pp = PQ + (size_t)(mg >> 2) * ldpq;
        Qp = PQ + (size_t)eidx[mg] * ldpq + qofs;
    }

    float4 rA[4], rQ[4], rB[2];

    auto ldg_tile = [&](int it) {
        const int k0 = it << 5;
        if (GATHER) {
            #pragma unroll
            for (int qq = 0; qq < 4; qq++) {
                int kk = k0 + lh + (qq << 2);
                rA[qq] = *(const float4*)(Pp + kk);
                rQ[qq] = *(const float4*)(Qp + kk);
            }
        } else {
            #pragma unroll
            for (int i = 0; i < 4; i++) {
                int gk = k0 + lkc;
                const float* src = A + (size_t)(m0 + lm + i * 32) * lda + gk;
                if (gk + 3 < Kval) {
                    rA[i] = *(const float4*)src;
                } else {
                    rA[i] = make_float4(0.f, 0.f, 0.f, 0.f);
                    if (gk + 0 < Kval) rA[i].x = src[0];
                    if (gk + 1 < Kval) rA[i].y = src[1];
                    if (gk + 2 < Kval) rA[i].z = src[2];
                }
            }
        }
        #pragma unroll
        for (int i = 0; i < 2; i++) {
            int gn = n0 + lm + i * 32;
            if (gn < Nfull) rB[i] = *(const float4*)(Wt + (size_t)gn * Kpad + (it << 5) + lkc);
            else            rB[i] = make_float4(0.f, 0.f, 0.f, 0.f);
        }
    };

    auto sts_tile = [&](int s, int it) {
        uint32_t* Ah = smu + s * SFLU;
        uint32_t* Al = Ah + AHLU;
        uint32_t* Bh = smu + s * SFLU + 2 * AHLU;
        uint32_t* Bl = Bh + BHLU;
        if (GATHER) {
            const int k0 = it << 5;
            #pragma unroll
            for (int qq = 0; qq < 4; qq++) {
                int kk = lh + (qq << 2);
                float4 bv = *(const float4*)(b1 + k0 + kk);
                float v0 = eluf(rA[qq].x + rQ[qq].x + bv.x);
                float v1 = eluf(rA[qq].y + rQ[qq].y + bv.y);
                float v2 = eluf(rA[qq].z + rQ[qq].z + bv.z);
                float v3 = eluf(rA[qq].w + rQ[qq].w + bv.w);
                uint32_t h0, l0, h1, l1;
                sp_bf(v0, v1, h0, l0);
                sp_bf(v2, v3, h1, l1);
                *(uint2*)&Ah[lr * APU + lgu + (qq << 1)] = make_uint2(h0, h1);
                *(uint2*)&Al[lr * APU + lgu + (qq << 1)] = make_uint2(l0, l1);
            }
        } else {
            #pragma unroll
            for (int i = 0; i < 4; i++) {
                uint32_t h0, l0, h1, l1;
                sp_bf(rA[i].x, rA[i].y, h0, l0);
                sp_bf(rA[i].z, rA[i].w, h1, l1);
                *(uint2*)&Ah[(lm + i * 32) * APU + luc] = make_uint2(h0, h1);
                *(uint2*)&Al[(lm + i * 32) * APU + luc] = make_uint2(l0, l1);
            }
        }
        #pragma unroll
        for (int i = 0; i < 2; i++) {
            uint32_t h0, l0, h1, l1;
            sp_bf(rB[i].x, rB[i].y, h0, l0);
            sp_bf(rB[i].z, rB[i].w, h1, l1);
            *(uint2*)&Bh[(lm + i * 32) * APU + luc] = make_uint2(h0, h1);
            *(uint2*)&Bl[(lm + i * 32) * APU + luc] = make_uint2(l0, l1);
        }
    };

    float acc[2][4][4];
    #pragma unroll
    for (int mt = 0; mt < 2; mt++)
        #pragma unroll
        for (int nt = 0; nt < 4; nt++)
            #pragma unroll
            for (int i = 0; i < 4; i++) acc[mt][nt][i] = 0.f;

    const int abase = (warp_m * 32 + g) * APU;
    const int bbase = (warp_n * 32 + g) * APU;

    ldg_tile(0);
    sts_tile(0, 0);
    for (int it = 0; it < iters; it++) {
        if (it + 1 < iters) ldg_tile(it + 1);
        __syncthreads();
        const int s = it & 1;
        const uint32_t* Ah = smu + s * SFLU;
        const uint32_t* Al = Ah + AHLU;
        const uint32_t* Bh = smu + s * SFLU + 2 * AHLU;
        const uint32_t* Bl = Bh + BHLU;
        #pragma unroll
        for (int ks = 0; ks < 2; ks++) {
            const int koff = (ks << 3) + q;
            uint32_t ah[2][4], al[2][4];
            #pragma unroll
            for (int mt = 0; mt < 2; mt++) {
                int rb = abase + mt * 16 * APU;
                ah[mt][0] = Ah[rb + koff];
                ah[mt][1] = Ah[rb + 8 * APU + koff];
                ah[mt][2] = Ah[rb + koff + 4];
                ah[mt][3] = Ah[rb + 8 * APU + koff + 4];
                al[mt][0] = Al[rb + koff];
                al[mt][1] = Al[rb + 8 * APU + koff];
                al[mt][2] = Al[rb + koff + 4];
                al[mt][3] = Al[rb + 8 * APU + koff + 4];
            }
            uint32_t bh[4][2], bl[4][2];
            #pragma unroll
            for (int nt = 0; nt < 4; nt++) {
                int rb = bbase + nt * 8 * APU;
                bh[nt][0] = Bh[rb + koff];
                bh[nt][1] = Bh[rb + koff + 4];
                bl[nt][0] = Bl[rb + koff];
                bl[nt][1] = Bl[rb + koff + 4];
            }
            #pragma unroll
            for (int mt = 0; mt < 2; mt++)
                #pragma unroll
                for (int nt = 0; nt < 4; nt++) {
                    mma16(acc[mt][nt], ah[mt], bh[nt]);
                    mma16(acc[mt][nt], al[mt], bh[nt]);
                    mma16(acc[mt][nt], ah[mt], bl[nt]);
                }
        }
        if (it + 1 < iters) sts_tile((it + 1) & 1, it + 1);
    }

    #pragma unroll
    for (int mt = 0; mt < 2; mt++) {
        const int rbase = m0 + warp_m * 32 + mt * 16;
        #pragma unroll
        for (int nt = 0; nt < 4; nt++) {
            const int cl = warp_n * 32 + nt * 8 + 2 * q;
            const int gc = n0 + cl;
            float bb0 = 0.f, bb1 = 0.f;
            if (bias != nullptr) {
                if (gc < Nfull)     bb0 = bias[gc];
                if (gc + 1 < Nfull) bb1 = bias[gc + 1];
            }
            if (!RED) {
                float v0 = acc[mt][nt][0] + bb0, v1 = acc[mt][nt][1] + bb1;
                float v2 = acc[mt][nt][2] + bb0, v3 = acc[mt][nt][3] + bb1;
                if (ACT) { v0 = eluf(v0); v1 = eluf(v1); v2 = eluf(v2); v3 = eluf(v3); }
                float* r0 = Co + (size_t)(rbase + g) * ldc + cofs;
                float* r1 = r0 + (size_t)8 * ldc;
                if (gc < Nfull)     { r0[gc] = v0;     r1[gc] = v2; }
                if (gc + 1 < Nfull) { r0[gc + 1] = v1; r1[gc + 1] = v3; }
            } else {
                #pragma unroll
                for (int half = 0; half < 2; half++) {
                    float v0 = (gc < Nfull)     ? eluf(acc[mt][nt][2 * half + 0] + bb0) : 0.f;
                    float v1 = (gc + 1 < Nfull) ? eluf(acc[mt][nt][2 * half + 1] + bb1) : 0.f;
                    v0 += __shfl_xor_sync(0xffffffffu, v0, 4);
                    v0 += __shfl_xor_sync(0xffffffffu, v0, 8);
                    v1 += __shfl_xor_sync(0xffffffffu, v1, 4);
                    v1 += __shfl_xor_sync(0xffffffffu, v1, 8);
                    if ((lane & 12) == 0) {
                        int p = (rbase + half * 8 + g) >> 2;
                        float* op = Co + (size_t)p * ldc + cofs;
                        if (gc < Nfull)     op[gc] = 0.25f * v0;
                        if (gc + 1 < Nfull) op[gc + 1] = 0.25f * v1;
                    }
                }
            }
        }
    }
}

// ============================ final tiny GEMM ==============================
__global__ void head3_k(const float* __restrict__ H2, const float* __restrict__ w,
                        const float* __restrict__ b, float* __restrict__ out) {
    int gtid = blockIdx.x * blockDim.x + threadIdx.x;
    int warp = gtid >> 5;
    int lane = threadIdx.x & 31;
    if (warp >= NPTS) return;
    const float* hr = H2 + (size_t)warp * 228;
    float a0 = 0.f, a1 = 0.f;
    for (int c = lane; c < 226; c += 32) {
        float h = hr[c];
        a0 += h * w[2 * c];
        a1 += h * w[2 * c + 1];
    }
    #pragma unroll
    for (int o = 16; o; o >>= 1) {
        a0 += __shfl_xor_sync(0xffffffffu, a0, o);
        a1 += __shfl_xor_sync(0xffffffffu, a1, o);
    }
    if (lane == 0) {
        out[2 * warp + 0] = a0 + b[0];
        out[2 * warp + 1] = a1 + b[1];
    }
}

// ============================ launcher =====================================
extern "C" void kernel_launch(void* const* d_in, const int* in_sizes, int n_in,
                              void* d_out, int out_size) {
    const float* coords   = (const float*)d_in[0];
    const float* features = (const float*)d_in[1];
    const float* c1w1 = (const float*)d_in[2];
    const float* c1b1 = (const float*)d_in[3];
    const float* c1w2 = (const float*)d_in[4];
    const float* c1b2 = (const float*)d_in[5];
    const float* c2w1 = (const float*)d_in[6];
    const float* c2b1 = (const float*)d_in[7];
    const float* c2w2 = (const float*)d_in[8];
    const float* c2b2 = (const float*)d_in[9];
    const float* c3w1 = (const float*)d_in[10];
    const float* c3b1 = (const float*)d_in[11];
    const float* c3w2 = (const float*)d_in[12];
    const float* c3b2 = (const float*)d_in[13];
    const float* ow1  = (const float*)d_in[14];
    const float* ob1  = (const float*)d_in[15];
    const float* ow2  = (const float*)d_in[16];
    const float* ob2  = (const float*)d_in[17];
    const float* ow3  = (const float*)d_in[18];
    const float* ob3  = (const float*)d_in[19];

    float *pX, *pPQ, *pH1, *pWt; int* pidx;
    cudaGetSymbolAddress((void**)&pX,  g_X453);
    cudaGetSymbolAddress((void**)&pPQ, g_PQ);
    cudaGetSymbolAddress((void**)&pH1, g_H1);
    cudaGetSymbolAddress((void**)&pWt, g_Wt);
    cudaGetSymbolAddress((void**)&pidx, g_idx);

    const int SMEM_TF = 2 * SFL * 4;    // 110,592 B
    const int SMEM_BF = 2 * SFLU * 4;   // 61,440 B
    cudaFuncSetAttribute(tfgemm_k<0, 0, 0>, cudaFuncAttributeMaxDynamicSharedMemorySize, SMEM_TF);
    cudaFuncSetAttribute(tfgemm_k<1, 1, 1>, cudaFuncAttributeMaxDynamicSharedMemorySize, SMEM_TF);
    cudaFuncSetAttribute(bfgemm_k<0, 0, 0>, cudaFuncAttributeMaxDynamicSharedMemorySize, SMEM_BF);
    cudaFuncSetAttribute(bfgemm_k<1, 1, 1>, cudaFuncAttributeMaxDynamicSharedMemorySize, SMEM_BF);
    cudaFuncSetAttribute(bfgemm_k<0, 1, 0>, cudaFuncAttributeMaxDynamicSharedMemorySize, SMEM_BF);

    const int MT_P = NPTS / 128;   // 1024
    const int MT_E = NEDG / 128;   // 4096

    copy_features_k<<<(NPTS * 5 + 255) / 256, 256>>>(features, pX);

    // ===== EdgeConv 1 (C=5, H=32, O=64) — feeds knn2: tf32 3-term =====
    knn_k<2, 4><<<512, 256>>>(coords, 2, 0, pidx);
    prep_pq_k<<<(64 * 32 + 255) / 256, 256>>>(c1w1, pWt, 5, 32, 32);
    tfgemm_k<0, 0, 0><<<dim3(1, MT_P), 256, SMEM_TF>>>(pX, XLD, 5, nullptr, 0, 0, nullptr, nullptr,
                                                       pWt, 32, nullptr, pPQ, 64, 0, 64);
    prep_wt_k<<<(64 * 32 + 255) / 256, 256>>>(c1w2, pWt, 32, 64, 32);
    tfgemm_k<1, 1, 1><<<dim3(1, MT_E), 256, SMEM_TF>>>(nullptr, 0, 32, pPQ, 64, 32, c1b1, pidx,
                                                       pWt, 32, c1b2, pX, XLD, O1_OFS, 64);

    // ===== EdgeConv 2 (C=64, H=96, O=128) — feeds knn3: tf32 3-term =====
    knn_k<64, 64><<<512, 256>>>(pX, XLD, O1_OFS, pidx);
    prep_pq_k<<<(192 * 64 + 255) / 256, 256>>>(c2w1, pWt, 64, 96, 64);
    tfgemm_k<0, 0, 0><<<dim3(3, MT_P), 256, SMEM_TF>>>(pX + O1_OFS, XLD, 64, nullptr, 0, 0, nullptr, nullptr,
                                                       pWt, 64, nullptr, pPQ, 192, 0, 192);
    prep_wt_k<<<(128 * 96 + 255) / 256, 256>>>(c2w2, pWt, 96, 128, 96);
    tfgemm_k<1, 1, 1><<<dim3(2, MT_E), 256, SMEM_TF>>>(nullptr, 0, 96, pPQ, 192, 96, c2b1, pidx,
                                                       pWt, 96, c2b2, pX, XLD, O2_OFS, 128);

    // ===== EdgeConv 3 (C=128, H=192, O=256) — post-KNN: bf16 3-term =====
    knn_k<128, 128><<<512, 256>>>(pX, XLD, O2_OFS, pidx);
    prep_pq_k<<<(384 * 128 + 255) / 256, 256>>>(c3w1, pWt, 128, 192, 128);
    bfgemm_k<0, 0, 0><<<dim3(6, MT_P), 256, SMEM_BF>>>(pX + O2_OFS, XLD, 128, nullptr, 0, 0, nullptr, nullptr,
                                                       pWt, 128, nullptr, pPQ, 384, 0, 384);
    prep_wt_k<<<(256 * 192 + 255) / 256, 256>>>(c3w2, pWt, 192, 256, 192);
    bfgemm_k<1, 1, 1><<<dim3(4, MT_E), 256, SMEM_BF>>>(nullptr, 0, 192, pPQ, 384, 192, c3b1, pidx,
                                                       pWt, 192, c3b2, pX, XLD, O3_OFS, 256);

    // ===== Head — post-KNN: bf16 3-term =====
    prep_head_k<<<(453 * 480 + 255) / 256, 256>>>(ow1, pWt, 453, 480);
    bfgemm_k<0, 1, 0><<<dim3(8, MT_P), 256, SMEM_BF>>>(pX, XLD, 456, nullptr, 0, 0, nullptr, nullptr,
                                                       pWt, 480, ob1, pH1, 456, 0, 453);
    prep_wt_k<<<(226 * 480 + 255) / 256, 256>>>(ow2, pWt, 453, 226, 480);
    bfgemm_k<0, 1, 0><<<dim3(4, MT_P), 256, SMEM_BF>>>(pH1, 456, 456, nullptr, 0, 0, nullptr, nullptr,
                                                       pWt, 480, ob2, pPQ, 228, 0, 226);
    head3_k<<<(NPTS * 32) / 256, 256>>>(pPQ, ow3, ob3, (float*)d_out);
}

// round 9
// speedup vs baseline: 1.0907x; 1.0907x over previous
#include <cuda_runtime.h>
#include <cuda_fp16.h>
#include <cstdint>
#include <math.h>

// ============================ problem constants ============================
#define NPTS 131072          // B*N = 1024*128
#define NEDG 524288          // NPTS * K(=4)

// Concat buffer layout (all segment starts 16B-aligned; pads never written => 0)
#define F_OFS  0
#define O1_OFS 8
#define O2_OFS 72
#define O3_OFS 200
#define XLD    456

// ============================ device scratch ===============================
__device__ float g_X453[(size_t)NPTS * XLD];
__device__ float g_PQ[(size_t)NPTS * 384];
__device__ float g_H1[(size_t)NPTS * 456];
__device__ int   g_idx[NPTS * 4];
__device__ float g_Wt[512 * 480];

__device__ __forceinline__ float eluf(float x) { return x > 0.f ? x : expm1f(x); }

// ============================ small helpers ================================
__device__ __forceinline__ void sp_tf32(float a, float& h, float& l) {
    uint32_t hu;
    asm("cvt.rna.tf32.f32 %0, %1;" : "=r"(hu) : "f"(a));
    h = __uint_as_float(hu);
    float lf = a - h;
    uint32_t lu;
    asm("cvt.rna.tf32.f32 %0, %1;" : "=r"(lu) : "f"(lf));
    l = __uint_as_float(lu);
}
__device__ __forceinline__ void mma8(float* c, const uint32_t* a, const uint32_t* b) {
    asm volatile("mma.sync.aligned.m16n8k8.row.col.f32.tf32.tf32.f32 "
                 "{%0,%1,%2,%3}, {%4,%5,%6,%7}, {%8,%9}, {%0,%1,%2,%3};"
                 : "+f"(c[0]), "+f"(c[1]), "+f"(c[2]), "+f"(c[3])
                 : "r"(a[0]), "r"(a[1]), "r"(a[2]), "r"(a[3]), "r"(b[0]), "r"(b[1]));
}
// fp16 split: hi = fp16(a), lo = fp16(a - hi); packed pairs (k_even low half)
__device__ __forceinline__ void sp_hf(float a0, float a1, uint32_t& h, uint32_t& l) {
    __half2 hh = __floats2half2_rn(a0, a1);
    float r0 = a0 - __half2float(__low2half(hh));
    float r1 = a1 - __half2float(__high2half(hh));
    __half2 ll = __floats2half2_rn(r0, r1);
    h = *reinterpret_cast<uint32_t*>(&hh);
    l = *reinterpret_cast<uint32_t*>(&ll);
}
__device__ __forceinline__ uint32_t hf1(float a0, float a1) {
    __half2 hh = __floats2half2_rn(a0, a1);
    return *reinterpret_cast<uint32_t*>(&hh);
}
__device__ __forceinline__ void mma16h(float* c, const uint32_t* a, const uint32_t* b) {
    asm volatile("mma.sync.aligned.m16n8k16.row.col.f32.f16.f16.f32 "
                 "{%0,%1,%2,%3}, {%4,%5,%6,%7}, {%8,%9}, {%0,%1,%2,%3};"
                 : "+f"(c[0]), "+f"(c[1]), "+f"(c[2]), "+f"(c[3])
                 : "r"(a[0]), "r"(a[1]), "r"(a[2]), "r"(a[3]), "r"(b[0]), "r"(b[1]));
}

// ============================ elementwise helpers ==========================
__global__ void copy_features_k(const float* __restrict__ f, float* __restrict__ X) {
    int e = blockIdx.x * blockDim.x + threadIdx.x;
    if (e < NPTS * 5) {
        int r = e / 5, c = e % 5;
        X[(size_t)r * XLD + c] = f[e];
    }
}
__global__ void prep_pq_k(const float* __restrict__ w1, float* __restrict__ wt, int C, int H, int Kpad) {
    int e = blockIdx.x * blockDim.x + threadIdx.x;
    if (e >= 2 * H * Kpad) return;
    int n = e / Kpad, k = e % Kpad;
    float v = 0.f;
    if (k < C) v = (n < H) ? (w1[k * H + n] - w1[(C + k) * H + n]) : w1[(C + k) * H + (n - H)];
    wt[(size_t)n * Kpad + k] = v;
}
__global__ void prep_wt_k(const float* __restrict__ w, float* __restrict__ wt, int K, int N, int Kpad) {
    int e = blockIdx.x * blockDim.x + threadIdx.x;
    if (e >= N * Kpad) return;
    int n = e / Kpad, k = e % Kpad;
    wt[(size_t)n * Kpad + k] = (k < K) ? w[(size_t)k * N + n] : 0.f;
}
__global__ void prep_head_k(const float* __restrict__ w, float* __restrict__ wt, int N, int Kpad) {
    int e = blockIdx.x * blockDim.x + threadIdx.x;
    if (e >= N * Kpad) return;
    int n = e / Kpad, kp = e % Kpad;
    float v = 0.f;
    if (kp < 5)                   v = w[(size_t)kp * N + n];
    else if (kp >= 8 && kp < 456) v = w[(size_t)(kp - 3) * N + n];
    wt[(size_t)n * Kpad + kp] = v;
}

// ============================ KNN (k=4; 2 batches per block) ===============
template<int C, int CP>
__global__ void __launch_bounds__(256) knn_k(const float* __restrict__ x, int ld, int cofs,
                                             int* __restrict__ idxout) {
    constexpr int PAD = CP + 4;
    __shared__ __align__(16) float sx[2][32][PAD];
    __shared__ float sn[2][128];
    int half = threadIdx.x >> 7;
    int tid = threadIdx.x & 127;
    int b = blockIdx.x * 2 + half;
    const float* xb = x + (size_t)b * 128 * ld + cofs;
    float4 xi[CP / 4];

    for (int t = 0; t < 4; t++) {
        for (int e = tid; e < 32 * CP; e += 128) {
            int r = e / CP, c = e % CP;
            sx[half][r][c] = (c < C) ? xb[(size_t)(t * 32 + r) * ld + c] : 0.f;
        }
        __syncthreads();
        if ((tid >> 5) == t) {
            int r = tid & 31;
            #pragma unroll
            for (int c4 = 0; c4 < CP / 4; c4++) xi[c4] = *(const float4*)&sx[half][r][4 * c4];
        }
        __syncthreads();
    }
    float ni = 0.f;
    #pragma unroll
    for (int c4 = 0; c4 < CP / 4; c4++)
        ni += xi[c4].x * xi[c4].x + xi[c4].y * xi[c4].y + xi[c4].z * xi[c4].z + xi[c4].w * xi[c4].w;
    sn[half][tid] = ni;
    __syncthreads();

    float bd0 = 1e30f, bd1 = 1e30f, bd2 = 1e30f, bd3 = 1e30f;
    int   bi0 = 0,     bi1 = 0,     bi2 = 0,     bi3 = 0;

    for (int t = 0; t < 4; t++) {
        for (int e = tid; e < 32 * CP; e += 128) {
            int r = e / CP, c = e % CP;
            sx[half][r][c] = (c < C) ? xb[(size_t)(t * 32 + r) * ld + c] : 0.f;
        }
        __syncthreads();
        for (int jl = 0; jl < 32; jl++) {
            int j = t * 32 + jl;
            float dot = 0.f;
            #pragma unroll
            for (int c4 = 0; c4 < CP / 4; c4++) {
                float4 xj = *(const float4*)&sx[half][jl][4 * c4];
                dot += xi[c4].x * xj.x + xi[c4].y * xj.y + xi[c4].z * xj.z + xi[c4].w * xj.w;
            }
            float d = ni + sn[half][j] - 2.f * dot;
            if (j == tid) d = 1e30f;
            if (d < bd3) {
                if (d < bd2) {
                    bd3 = bd2; bi3 = bi2;
                    if (d < bd1) {
                        bd2 = bd1; bi2 = bi1;
                        if (d < bd0) { bd1 = bd0; bi1 = bi0; bd0 = d; bi0 = j; }
                        else         { bd1 = d; bi1 = j; }
                    } else { bd2 = d; bi2 = j; }
                } else { bd3 = d; bi3 = j; }
            }
        }
        __syncthreads();
    }
    int base = (b * 128 + tid) * 4;
    int gb = b * 128;
    idxout[base + 0] = gb + bi0;
    idxout[base + 1] = gb + bi1;
    idxout[base + 2] = gb + bi2;
    idxout[base + 3] = gb + bi3;
}

// ============================ tf32 3-term GEMM (KNN-feeding; FROZEN) =======
#define AP 36
#define AFLTS (128 * AP)
#define BFLTS (64 * AP)
#define SFL (2 * AFLTS + 2 * BFLTS)
template<int GATHER, int ACT, int RED>
__global__ void __launch_bounds__(256, 2) tfgemm_k(
    const float* __restrict__ A, int lda, int Kval,
    const float* __restrict__ PQ, int ldpq, int qofs,
    const float* __restrict__ b1, const int* __restrict__ eidx,
    const float* __restrict__ Wt, int Kpad,
    const float* __restrict__ bias,
    float* __restrict__ Co, int ldc, int cofs, int Nfull)
{
    extern __shared__ float sm[];
    const int tid = threadIdx.x;
    const int wid = tid >> 5, lane = tid & 31;
    const int g = lane >> 2, q = lane & 3;
    const int warp_m = wid >> 1, warp_n = wid & 1;
    const int m0 = blockIdx.y * 128;
    const int n0 = blockIdx.x * 64;
    const int iters = Kpad >> 5;

    const int lm = tid >> 3, lkc = (tid & 7) << 2;
    const int lr = tid >> 1, lh = (tid & 1) << 4;

    const float *Pp = nullptr, *Qp = nullptr;
    if (GATHER) {
        int mg = m0 + lr;
        Pp = PQ + (size_t)(mg >> 2) * ldpq;
        Qp = PQ + (size_t)eidx[mg] * ldpq + qofs;
    }

    float4 rA[4], rQ[4], rB[2];

    auto ldg_tile = [&](int it) {
        const int k0 = it << 5;
        if (GATHER) {
            #pragma unroll
            for (int qq = 0; qq < 4; qq++) {
                int kk = k0 + lh + (qq << 2);
                rA[qq] = *(const float4*)(Pp + kk);
                rQ[qq] = *(const float4*)(Qp + kk);
            }
        } else {
            #pragma unroll
            for (int i = 0; i < 4; i++) {
                int gk = k0 + lkc;
                const float* src = A + (size_t)(m0 + lm + i * 32) * lda + gk;
                if (gk + 3 < Kval) {
                    rA[i] = *(const float4*)src;
                } else {
                    rA[i] = make_float4(0.f, 0.f, 0.f, 0.f);
                    if (gk + 0 < Kval) rA[i].x = src[0];
                    if (gk + 1 < Kval) rA[i].y = src[1];
                    if (gk + 2 < Kval) rA[i].z = src[2];
                }
            }
        }
        #pragma unroll
        for (int i = 0; i < 2; i++) {
            int gn = n0 + lm + i * 32;
            if (gn < Nfull) rB[i] = *(const float4*)(Wt + (size_t)gn * Kpad + (it << 5) + lkc);
            else            rB[i] = make_float4(0.f, 0.f, 0.f, 0.f);
        }
    };

    auto sts_tile = [&](int s, int it) {
        float* Ah = sm + s * SFL;
        float* Al = Ah + AFLTS;
        float* Bh = sm + s * SFL + 2 * AFLTS;
        float* Bl = Bh + BFLTS;
        if (GATHER) {
            const int k0 = it << 5;
            #pragma unroll
            for (int qq = 0; qq < 4; qq++) {
                int kk = lh + (qq << 2);
                float4 bv = *(const float4*)(b1 + k0 + kk);
                float4 hv, lv;
                sp_tf32(eluf(rA[qq].x + rQ[qq].x + bv.x), hv.x, lv.x);
                sp_tf32(eluf(rA[qq].y + rQ[qq].y + bv.y), hv.y, lv.y);
                sp_tf32(eluf(rA[qq].z + rQ[qq].z + bv.z), hv.z, lv.z);
                sp_tf32(eluf(rA[qq].w + rQ[qq].w + bv.w), hv.w, lv.w);
                *(float4*)&Ah[lr * AP + kk] = hv;
                *(float4*)&Al[lr * AP + kk] = lv;
            }
        } else {
            #pragma unroll
            for (int i = 0; i < 4; i++) {
                float4 hv, lv;
                sp_tf32(rA[i].x, hv.x, lv.x);
                sp_tf32(rA[i].y, hv.y, lv.y);
                sp_tf32(rA[i].z, hv.z, lv.z);
                sp_tf32(rA[i].w, hv.w, lv.w);
                *(float4*)&Ah[(lm + i * 32) * AP + lkc] = hv;
                *(float4*)&Al[(lm + i * 32) * AP + lkc] = lv;
            }
        }
        #pragma unroll
        for (int i = 0; i < 2; i++) {
            float4 hv, lv;
            sp_tf32(rB[i].x, hv.x, lv.x);
            sp_tf32(rB[i].y, hv.y, lv.y);
            sp_tf32(rB[i].z, hv.z, lv.z);
            sp_tf32(rB[i].w, hv.w, lv.w);
            *(float4*)&Bh[(lm + i * 32) * AP + lkc] = hv;
            *(float4*)&Bl[(lm + i * 32) * AP + lkc] = lv;
        }
    };

    float acc[2][4][4];
    #pragma unroll
    for (int mt = 0; mt < 2; mt++)
        #pragma unroll
        for (int nt = 0; nt < 4; nt++)
            #pragma unroll
            for (int i = 0; i < 4; i++) acc[mt][nt][i] = 0.f;

    const int abase = (warp_m * 32 + g) * AP;
    const int bbase = (warp_n * 32 + g) * AP;

    ldg_tile(0);
    sts_tile(0, 0);
    for (int it = 0; it < iters; it++) {
        if (it + 1 < iters) ldg_tile(it + 1);
        __syncthreads();
        const int s = it & 1;
        const float* Ah = sm + s * SFL;
        const float* Al = Ah + AFLTS;
        const float* Bh = sm + s * SFL + 2 * AFLTS;
        const float* Bl = Bh + BFLTS;
        #pragma unroll
        for (int ks = 0; ks < 4; ks++) {
            const int kb = (ks << 3) + q;
            uint32_t ah[2][4], al[2][4];
            #pragma unroll
            for (int mt = 0; mt < 2; mt++) {
                int rb = abase + mt * 16 * AP;
                ah[mt][0] = __float_as_uint(Ah[rb + kb]);
                al[mt][0] = __float_as_uint(Al[rb + kb]);
                ah[mt][1] = __float_as_uint(Ah[rb + 8 * AP + kb]);
                al[mt][1] = __float_as_uint(Al[rb + 8 * AP + kb]);
                ah[mt][2] = __float_as_uint(Ah[rb + kb + 4]);
                al[mt][2] = __float_as_uint(Al[rb + kb + 4]);
                ah[mt][3] = __float_as_uint(Ah[rb + 8 * AP + kb + 4]);
                al[mt][3] = __float_as_uint(Al[rb + 8 * AP + kb + 4]);
            }
            uint32_t bh[4][2], bl[4][2];
            #pragma unroll
            for (int nt = 0; nt < 4; nt++) {
                int rb = bbase + nt * 8 * AP;
                bh[nt][0] = __float_as_uint(Bh[rb + kb]);
                bl[nt][0] = __float_as_uint(Bl[rb + kb]);
                bh[nt][1] = __float_as_uint(Bh[rb + kb + 4]);
                bl[nt][1] = __float_as_uint(Bl[rb + kb + 4]);
            }
            #pragma unroll
            for (int mt = 0; mt < 2; mt++)
                #pragma unroll
                for (int nt = 0; nt < 4; nt++) {
                    mma8(acc[mt][nt], ah[mt], bh[nt]);
                    mma8(acc[mt][nt], al[mt], bh[nt]);
                    mma8(acc[mt][nt], ah[mt], bl[nt]);
                }
        }
        if (it + 1 < iters) sts_tile((it + 1) & 1, it + 1);
    }

    #pragma unroll
    for (int mt = 0; mt < 2; mt++) {
        const int rbase = m0 + warp_m * 32 + mt * 16;
        #pragma unroll
        for (int nt = 0; nt < 4; nt++) {
            const int cl = warp_n * 32 + nt * 8 + 2 * q;
            const int gc = n0 + cl;
            float bb0 = 0.f, bb1 = 0.f;
            if (bias != nullptr) {
                if (gc < Nfull)     bb0 = bias[gc];
                if (gc + 1 < Nfull) bb1 = bias[gc + 1];
            }
            if (!RED) {
                float v0 = acc[mt][nt][0] + bb0, v1 = acc[mt][nt][1] + bb1;
                float v2 = acc[mt][nt][2] + bb0, v3 = acc[mt][nt][3] + bb1;
                if (ACT) { v0 = eluf(v0); v1 = eluf(v1); v2 = eluf(v2); v3 = eluf(v3); }
                float* r0 = Co + (size_t)(rbase + g) * ldc + cofs;
                float* r1 = r0 + (size_t)8 * ldc;
                if (gc < Nfull)     { r0[gc] = v0;     r1[gc] = v2; }
                if (gc + 1 < Nfull) { r0[gc + 1] = v1; r1[gc + 1] = v3; }
            } else {
                #pragma unroll
                for (int half = 0; half < 2; half++) {
                    float v0 = (gc < Nfull)     ? eluf(acc[mt][nt][2 * half + 0] + bb0) : 0.f;
                    float v1 = (gc + 1 < Nfull) ? eluf(acc[mt][nt][2 * half + 1] + bb1) : 0.f;
                    v0 += __shfl_xor_sync(0xffffffffu, v0, 4);
                    v0 += __shfl_xor_sync(0xffffffffu, v0, 8);
                    v1 += __shfl_xor_sync(0xffffffffu, v1, 4);
                    v1 += __shfl_xor_sync(0xffffffffu, v1, 8);
                    if ((lane & 12) == 0) {
                        int p = (rbase + half * 8 + g) >> 2;
                        float* op = Co + (size_t)p * ldc + cofs;
                        if (gc < Nfull)     op[gc] = 0.25f * v0;
                        if (gc + 1 < Nfull) op[gc + 1] = 0.25f * v1;
                    }
                }
            }
        }
    }
}

// ============================ fp16 2-term GEMM (post-KNN) ==================
// A = hi+lo fp16 planes (exact to ~2^-22); B = single fp16 plane (~2^-12 RMS).
// 2 mma per fragment pair instead of 3.
#define APU 20
#define AHLU (128 * APU)
#define BHLU (64 * APU)
#define SFLU (2 * AHLU + BHLU)     // 6400 u32 per stage
template<int GATHER, int ACT, int RED>
__global__ void __launch_bounds__(256, 2) hfgemm_k(
    const float* __restrict__ A, int lda, int Kval,
    const float* __restrict__ PQ, int ldpq, int qofs,
    const float* __restrict__ b1, const int* __restrict__ eidx,
    const float* __restrict__ Wt, int Kpad,
    const float* __restrict__ bias,
    float* __restrict__ Co, int ldc, int cofs, int Nfull)
{
    extern __shared__ uint32_t smu[];
    const int tid = threadIdx.x;
    const int wid = tid >> 5, lane = tid & 31;
    const int g = lane >> 2, q = lane & 3;
    const int warp_m = wid >> 1, warp_n = wid & 1;
    const int m0 = blockIdx.y * 128;
    const int n0 = blockIdx.x * 64;
    const int iters = Kpad >> 5;

    const int lm = tid >> 3, lkc = (tid & 7) << 2;
    const int luc = (tid & 7) << 1;
    const int lr = tid >> 1, lh = (tid & 1) << 4;
    const int lgu = (tid & 1) << 3;

    const float *Pp = nullptr, *Qp = nullptr;
    if (GATHER) {
        int mg = m0 + lr;
        Pp = PQ + (size_t)(mg >> 2) * ldpq;
        Qp = PQ + (size_t)eidx[mg] * ldpq + qofs;
    }

    float4 rA[4], rQ[4], rB[2];

    auto ldg_tile = [&](int it) {
        const int k0 = it << 5;
        if (GATHER) {
            #pragma unroll
            for (int qq = 0; qq < 4; qq++) {
                int kk = k0 + lh + (qq << 2);
                rA[qq] = *(const float4*)(Pp + kk);
                rQ[qq] = *(const float4*)(Qp + kk);
            }
        } else {
            #pragma unroll
            for (int i = 0; i < 4; i++) {
                int gk = k0 + lkc;
                const float* src = A + (size_t)(m0 + lm + i * 32) * lda + gk;
                if (gk + 3 < Kval) {
                    rA[i] = *(const float4*)src;
                } else {
                    rA[i] = make_float4(0.f, 0.f, 0.f, 0.f);
                    if (gk + 0 < Kval) rA[i].x = src[0];
                    if (gk + 1 < Kval) rA[i].y = src[1];
                    if (gk + 2 < Kval) rA[i].z = src[2];
                }
            }
        }
        #pragma unroll
        for (int i = 0; i < 2; i++) {
            int gn = n0 + lm + i * 32;
            if (gn < Nfull) rB[i] = *(const float4*)(Wt + (size_t)gn * Kpad + (it << 5) + lkc);
            else            rB[i] = make_float4(0.f, 0.f, 0.f, 0.f);
        }
    };

    auto sts_tile = [&](int s, int it) {
        uint32_t* Ah = smu + s * SFLU;
        uint32_t* Al = Ah + AHLU;
        uint32_t* Bh = smu + s * SFLU + 2 * AHLU;
        if (GATHER) {
            const int k0 = it << 5;
            #pragma unroll
            for (int qq = 0; qq < 4; qq++) {
                int kk = lh + (qq << 2);
                float4 bv = *(const float4*)(b1 + k0 + kk);
                float v0 = eluf(rA[qq].x + rQ[qq].x + bv.x);
                float v1 = eluf(rA[qq].y + rQ[qq].y + bv.y);
                float v2 = eluf(rA[qq].z + rQ[qq].z + bv.z);
                float v3 = eluf(rA[qq].w + rQ[qq].w + bv.w);
                uint32_t h0, l0, h1, l1;
                sp_hf(v0, v1, h0, l0);
                sp_hf(v2, v3, h1, l1);
                *(uint2*)&Ah[lr * APU + lgu + (qq << 1)] = make_uint2(h0, h1);
                *(uint2*)&Al[lr * APU + lgu + (qq << 1)] = make_uint2(l0, l1);
            }
        } else {
            #pragma unroll
            for (int i = 0; i < 4; i++) {
                uint32_t h0, l0, h1, l1;
                sp_hf(rA[i].x, rA[i].y, h0, l0);
                sp_hf(rA[i].z, rA[i].w, h1, l1);
                *(uint2*)&Ah[(lm + i * 32) * APU + luc] = make_uint2(h0, h1);
                *(uint2*)&Al[(lm + i * 32) * APU + luc] = make_uint2(l0, l1);
            }
        }
        #pragma unroll
        for (int i = 0; i < 2; i++) {
            uint32_t h0 = hf1(rB[i].x, rB[i].y);
            uint32_t h1 = hf1(rB[i].z, rB[i].w);
            *(uint2*)&Bh[(lm + i * 32) * APU + luc] = make_uint2(h0, h1);
        }
    };

    float acc[2][4][4];
    #pragma unroll
    for (int mt = 0; mt < 2; mt++)
        #pragma unroll
        for (int nt = 0; nt < 4; nt++)
            #pragma unroll
            for (int i = 0; i < 4; i++) acc[mt][nt][i] = 0.f;

    const int abase = (warp_m * 32 + g) * APU;
    const int bbase = (warp_n * 32 + g) * APU;

    ldg_tile(0);
    sts_tile(0, 0);
    for (int it = 0; it < iters; it++) {
        if (it + 1 < iters) ldg_tile(it + 1);
        __syncthreads();
        const int s = it & 1;
        const uint32_t* Ah = smu + s * SFLU;
        const uint32_t* Al = Ah + AHLU;
        const uint32_t* Bh = smu + s * SFLU + 2 * AHLU;
        #pragma unroll
        for (int ks = 0; ks < 2; ks++) {
            const int koff = (ks << 3) + q;
            uint32_t ah[2][4], al[2][4];
            #pragma unroll
            for (int mt = 0; mt < 2; mt++) {
                int rb = abase + mt * 16 * APU;
                ah[mt][0] = Ah[rb + koff];
                ah[mt][1] = Ah[rb + 8 * APU + koff];
                ah[mt][2] = Ah[rb + koff + 4];
                ah[mt][3] = Ah[rb + 8 * APU + koff + 4];
                al[mt][0] = Al[rb + koff];
                al[mt][1] = Al[rb + 8 * APU + koff];
                al[mt][2] = Al[rb + koff + 4];
                al[mt][3] = Al[rb + 8 * APU + koff + 4];
            }
            uint32_t bh[4][2];
            #pragma unroll
            for (int nt = 0; nt < 4; nt++) {
                int rb = bbase + nt * 8 * APU;
                bh[nt][0] = Bh[rb + koff];
                bh[nt][1] = Bh[rb + koff + 4];
            }
            #pragma unroll
            for (int mt = 0; mt < 2; mt++)
                #pragma unroll
                for (int nt = 0; nt < 4; nt++) {
                    mma16h(acc[mt][nt], ah[mt], bh[nt]);
                    mma16h(acc[mt][nt], al[mt], bh[nt]);
                }
        }
        if (it + 1 < iters) sts_tile((it + 1) & 1, it + 1);
    }

    #pragma unroll
    for (int mt = 0; mt < 2; mt++) {
        const int rbase = m0 + warp_m * 32 + mt * 16;
        #pragma unroll
        for (int nt = 0; nt < 4; nt++) {
            const int cl = warp_n * 32 + nt * 8 + 2 * q;
            const int gc = n0 + cl;
            float bb0 = 0.f, bb1 = 0.f;
            if (bias != nullptr) {
                if (gc < Nfull)     bb0 = bias[gc];
                if (gc + 1 < Nfull) bb1 = bias[gc + 1];
            }
            if (!RED) {
                float v0 = acc[mt][nt][0] + bb0, v1 = acc[mt][nt][1] + bb1;
                float v2 = acc[mt][nt][2] + bb0, v3 = acc[mt][nt][3] + bb1;
                if (ACT) { v0 = eluf(v0); v1 = eluf(v1); v2 = eluf(v2); v3 = eluf(v3); }
                float* r0 = Co + (size_t)(rbase + g) * ldc + cofs;
                float* r1 = r0 + (size_t)8 * ldc;
                if (gc < Nfull)     { r0[gc] = v0;     r1[gc] = v2; }
                if (gc + 1 < Nfull) { r0[gc + 1] = v1; r1[gc + 1] = v3; }
            } else {
                #pragma unroll
                for (int half = 0; half < 2; half++) {
                    float v0 = (gc < Nfull)     ? eluf(acc[mt][nt][2 * half + 0] + bb0) : 0.f;
                    float v1 = (gc + 1 < Nfull) ? eluf(acc[mt][nt][2 * half + 1] + bb1) : 0.f;
                    v0 += __shfl_xor_sync(0xffffffffu, v0, 4);
                    v0 += __shfl_xor_sync(0xffffffffu, v0, 8);
                    v1 += __shfl_xor_sync(0xffffffffu, v1, 4);
                    v1 += __shfl_xor_sync(0xffffffffu, v1, 8);
                    if ((lane & 12) == 0) {
                        int p = (rbase + half * 8 + g) >> 2;
                        float* op = Co + (size_t)p * ldc + cofs;
                        if (gc < Nfull)     op[gc] = 0.25f * v0;
                        if (gc + 1 < Nfull) op[gc + 1] = 0.25f * v1;
                    }
                }
            }
        }
    }
}

// ============================ final tiny GEMM ==============================
__global__ void head3_k(const float* __restrict__ H2, const float* __restrict__ w,
                        const float* __restrict__ b, float* __restrict__ out) {
    int gtid = blockIdx.x * blockDim.x + threadIdx.x;
    int warp = gtid >> 5;
    int lane = threadIdx.x & 31;
    if (warp >= NPTS) return;
    const float* hr = H2 + (size_t)warp * 228;
    float a0 = 0.f, a1 = 0.f;
    for (int c = lane; c < 226; c += 32) {
        float h = hr[c];
        a0 += h * w[2 * c];
        a1 += h * w[2 * c + 1];
    }
    #pragma unroll
    for (int o = 16; o; o >>= 1) {
        a0 += __shfl_xor_sync(0xffffffffu, a0, o);
        a1 += __shfl_xor_sync(0xffffffffu, a1, o);
    }
    if (lane == 0) {
        out[2 * warp + 0] = a0 + b[0];
        out[2 * warp + 1] = a1 + b[1];
    }
}

// ============================ launcher =====================================
extern "C" void kernel_launch(void* const* d_in, const int* in_sizes, int n_in,
                              void* d_out, int out_size) {
    const float* coords   = (const float*)d_in[0];
    const float* features = (const float*)d_in[1];
    const float* c1w1 = (const float*)d_in[2];
    const float* c1b1 = (const float*)d_in[3];
    const float* c1w2 = (const float*)d_in[4];
    const float* c1b2 = (const float*)d_in[5];
    const float* c2w1 = (const float*)d_in[6];
    const float* c2b1 = (const float*)d_in[7];
    const float* c2w2 = (const float*)d_in[8];
    const float* c2b2 = (const float*)d_in[9];
    const float* c3w1 = (const float*)d_in[10];
    const float* c3b1 = (const float*)d_in[11];
    const float* c3w2 = (const float*)d_in[12];
    const float* c3b2 = (const float*)d_in[13];
    const float* ow1  = (const float*)d_in[14];
    const float* ob1  = (const float*)d_in[15];
    const float* ow2  = (const float*)d_in[16];
    const float* ob2  = (const float*)d_in[17];
    const float* ow3  = (const float*)d_in[18];
    const float* ob3  = (const float*)d_in[19];

    float *pX, *pPQ, *pH1, *pWt; int* pidx;
    cudaGetSymbolAddress((void**)&pX,  g_X453);
    cudaGetSymbolAddress((void**)&pPQ, g_PQ);
    cudaGetSymbolAddress((void**)&pH1, g_H1);
    cudaGetSymbolAddress((void**)&pWt, g_Wt);
    cudaGetSymbolAddress((void**)&pidx, g_idx);

    const int SMEM_TF = 2 * SFL * 4;    // 110,592 B
    const int SMEM_HF = 2 * SFLU * 4;   // 51,200 B
    cudaFuncSetAttribute(tfgemm_k<0, 0, 0>, cudaFuncAttributeMaxDynamicSharedMemorySize, SMEM_TF);
    cudaFuncSetAttribute(tfgemm_k<1, 1, 1>, cudaFuncAttributeMaxDynamicSharedMemorySize, SMEM_TF);
    cudaFuncSetAttribute(hfgemm_k<0, 0, 0>, cudaFuncAttributeMaxDynamicSharedMemorySize, SMEM_HF);
    cudaFuncSetAttribute(hfgemm_k<1, 1, 1>, cudaFuncAttributeMaxDynamicSharedMemorySize, SMEM_HF);
    cudaFuncSetAttribute(hfgemm_k<0, 1, 0>, cudaFuncAttributeMaxDynamicSharedMemorySize, SMEM_HF);

    const int MT_P = NPTS / 128;   // 1024
    const int MT_E = NEDG / 128;   // 4096

    copy_features_k<<<(NPTS * 5 + 255) / 256, 256>>>(features, pX);

    // ===== EdgeConv 1 (C=5, H=32, O=64) — feeds knn2: tf32 3-term =====
    knn_k<2, 4><<<512, 256>>>(coords, 2, 0, pidx);
    prep_pq_k<<<(64 * 32 + 255) / 256, 256>>>(c1w1, pWt, 5, 32, 32);
    tfgemm_k<0, 0, 0><<<dim3(1, MT_P), 256, SMEM_TF>>>(pX, XLD, 5, nullptr, 0, 0, nullptr, nullptr,
                                                       pWt, 32, nullptr, pPQ, 64, 0, 64);
    prep_wt_k<<<(64 * 32 + 255) / 256, 256>>>(c1w2, pWt, 32, 64, 32);
    tfgemm_k<1, 1, 1><<<dim3(1, MT_E), 256, SMEM_TF>>>(nullptr, 0, 32, pPQ, 64, 32, c1b1, pidx,
                                                       pWt, 32, c1b2, pX, XLD, O1_OFS, 64);

    // ===== EdgeConv 2 (C=64, H=96, O=128) — feeds knn3: tf32 3-term =====
    knn_k<64, 64><<<512, 256>>>(pX, XLD, O1_OFS, pidx);
    prep_pq_k<<<(192 * 64 + 255) / 256, 256>>>(c2w1, pWt, 64, 96, 64);
    tfgemm_k<0, 0, 0><<<dim3(3, MT_P), 256, SMEM_TF>>>(pX + O1_OFS, XLD, 64, nullptr, 0, 0, nullptr, nullptr,
                                                       pWt, 64, nullptr, pPQ, 192, 0, 192);
    prep_wt_k<<<(128 * 96 + 255) / 256, 256>>>(c2w2, pWt, 96, 128, 96);
    tfgemm_k<1, 1, 1><<<dim3(2, MT_E), 256, SMEM_TF>>>(nullptr, 0, 96, pPQ, 192, 96, c2b1, pidx,
                                                       pWt, 96, c2b2, pX, XLD, O2_OFS, 128);

    // ===== EdgeConv 3 (C=128, H=192, O=256) — post-KNN: fp16 2-term =====
    knn_k<128, 128><<<512, 256>>>(pX, XLD, O2_OFS, pidx);
    prep_pq_k<<<(384 * 128 + 255) / 256, 256>>>(c3w1, pWt, 128, 192, 128);
    hfgemm_k<0, 0, 0><<<dim3(6, MT_P), 256, SMEM_HF>>>(pX + O2_OFS, XLD, 128, nullptr, 0, 0, nullptr, nullptr,
                                                       pWt, 128, nullptr, pPQ, 384, 0, 384);
    prep_wt_k<<<(256 * 192 + 255) / 256, 256>>>(c3w2, pWt, 192, 256, 192);
    hfgemm_k<1, 1, 1><<<dim3(4, MT_E), 256, SMEM_HF>>>(nullptr, 0, 192, pPQ, 384, 192, c3b1, pidx,
                                                       pWt, 192, c3b2, pX, XLD, O3_OFS, 256);

    // ===== Head — post-KNN: fp16 2-term =====
    prep_head_k<<<(453 * 480 + 255) / 256, 256>>>(ow1, pWt, 453, 480);
    hfgemm_k<0, 1, 0><<<dim3(8, MT_P), 256, SMEM_HF>>>(pX, XLD, 456, nullptr, 0, 0, nullptr, nullptr,
                                                       pWt, 480, ob1, pH1, 456, 0, 453);
    prep_wt_k<<<(226 * 480 + 255) / 256, 256>>>(ow2, pWt, 453, 226, 480);
    hfgemm_k<0, 1, 0><<<dim3(4, MT_P), 256, SMEM_HF>>>(pH1, 456, 456, nullptr, 0, 0, nullptr, nullptr,
                                                       pWt, 480, ob2, pPQ, 228, 0, 226);
    head3_k<<<(NPTS * 32) / 256, 256>>>(pPQ, ow3, ob3, (float*)d_out);
}

// round 10
// speedup vs baseline: 1.1491x; 1.0535x over previous
#include <cuda_runtime.h>
#include <cuda_fp16.h>
#include <cstdint>
#include <math.h>

// ============================ problem constants ============================
#define NPTS 131072          // B*N = 1024*128
#define NEDG 524288          // NPTS * K(=4)

// Concat buffer layout (all segment starts 16B-aligned; pads never written => 0)
#define F_OFS  0
#define O1_OFS 8
#define O2_OFS 72
#define O3_OFS 200
#define XLD    456

// ============================ device scratch ===============================
__device__ float g_X453[(size_t)NPTS * XLD];
__device__ float g_PQ[(size_t)NPTS * 384];   // fp32 PQ1/PQ2; reused as fp16 PQ3 and fp32 H2 (ld 228)
__device__ float g_H1[(size_t)NPTS * 456];   // reused as fp16 H1 (ld 456 halfs)
__device__ int   g_idx[NPTS * 4];
__device__ float g_Wt[512 * 480];

__device__ __forceinline__ float eluf(float x) { return x > 0.f ? x : expm1f(x); }

// ============================ small helpers ================================
__device__ __forceinline__ void sp_tf32(float a, float& h, float& l) {
    uint32_t hu;
    asm("cvt.rna.tf32.f32 %0, %1;" : "=r"(hu) : "f"(a));
    h = __uint_as_float(hu);
    float lf = a - h;
    uint32_t lu;
    asm("cvt.rna.tf32.f32 %0, %1;" : "=r"(lu) : "f"(lf));
    l = __uint_as_float(lu);
}
__device__ __forceinline__ void mma8(float* c, const uint32_t* a, const uint32_t* b) {
    asm volatile("mma.sync.aligned.m16n8k8.row.col.f32.tf32.tf32.f32 "
                 "{%0,%1,%2,%3}, {%4,%5,%6,%7}, {%8,%9}, {%0,%1,%2,%3};"
                 : "+f"(c[0]), "+f"(c[1]), "+f"(c[2]), "+f"(c[3])
                 : "r"(a[0]), "r"(a[1]), "r"(a[2]), "r"(a[3]), "r"(b[0]), "r"(b[1]));
}
__device__ __forceinline__ void sp_hf(float a0, float a1, uint32_t& h, uint32_t& l) {
    __half2 hh = __floats2half2_rn(a0, a1);
    float r0 = a0 - __half2float(__low2half(hh));
    float r1 = a1 - __half2float(__high2half(hh));
    __half2 ll = __floats2half2_rn(r0, r1);
    h = *reinterpret_cast<uint32_t*>(&hh);
    l = *reinterpret_cast<uint32_t*>(&ll);
}
__device__ __forceinline__ uint32_t hf1(float a0, float a1) {
    __half2 hh = __floats2half2_rn(a0, a1);
    return *reinterpret_cast<uint32_t*>(&hh);
}
__device__ __forceinline__ void mma16h(float* c, const uint32_t* a, const uint32_t* b) {
    asm volatile("mma.sync.aligned.m16n8k16.row.col.f32.f16.f16.f32 "
                 "{%0,%1,%2,%3}, {%4,%5,%6,%7}, {%8,%9}, {%0,%1,%2,%3};"
                 : "+f"(c[0]), "+f"(c[1]), "+f"(c[2]), "+f"(c[3])
                 : "r"(a[0]), "r"(a[1]), "r"(a[2]), "r"(a[3]), "r"(b[0]), "r"(b[1]));
}

// ============================ elementwise helpers ==========================
__global__ void copy_features_k(const float* __restrict__ f, float* __restrict__ X) {
    int e = blockIdx.x * blockDim.x + threadIdx.x;
    if (e < NPTS * 5) {
        int r = e / 5, c = e % 5;
        X[(size_t)r * XLD + c] = f[e];
    }
}
__global__ void prep_pq_k(const float* __restrict__ w1, float* __restrict__ wt, int C, int H, int Kpad) {
    int e = blockIdx.x * blockDim.x + threadIdx.x;
    if (e >= 2 * H * Kpad) return;
    int n = e / Kpad, k = e % Kpad;
    float v = 0.f;
    if (k < C) v = (n < H) ? (w1[k * H + n] - w1[(C + k) * H + n]) : w1[(C + k) * H + (n - H)];
    wt[(size_t)n * Kpad + k] = v;
}
__global__ void prep_wt_k(const float* __restrict__ w, float* __restrict__ wt, int K, int N, int Kpad) {
    int e = blockIdx.x * blockDim.x + threadIdx.x;
    if (e >= N * Kpad) return;
    int n = e / Kpad, k = e % Kpad;
    wt[(size_t)n * Kpad + k] = (k < K) ? w[(size_t)k * N + n] : 0.f;
}
__global__ void prep_head_k(const float* __restrict__ w, float* __restrict__ wt, int N, int Kpad) {
    int e = blockIdx.x * blockDim.x + threadIdx.x;
    if (e >= N * Kpad) return;
    int n = e / Kpad, kp = e % Kpad;
    float v = 0.f;
    if (kp < 5)                   v = w[(size_t)kp * N + n];
    else if (kp >= 8 && kp < 456) v = w[(size_t)(kp - 3) * N + n];
    wt[(size_t)n * Kpad + kp] = v;
}

// ============================ KNN (k=4; 2 batches per block; FROZEN) =======
template<int C, int CP>
__global__ void __launch_bounds__(256) knn_k(const float* __restrict__ x, int ld, int cofs,
                                             int* __restrict__ idxout) {
    constexpr int PAD = CP + 4;
    __shared__ __align__(16) float sx[2][32][PAD];
    __shared__ float sn[2][128];
    int half = threadIdx.x >> 7;
    int tid = threadIdx.x & 127;
    int b = blockIdx.x * 2 + half;
    const float* xb = x + (size_t)b * 128 * ld + cofs;
    float4 xi[CP / 4];

    for (int t = 0; t < 4; t++) {
        for (int e = tid; e < 32 * CP; e += 128) {
            int r = e / CP, c = e % CP;
            sx[half][r][c] = (c < C) ? xb[(size_t)(t * 32 + r) * ld + c] : 0.f;
        }
        __syncthreads();
        if ((tid >> 5) == t) {
            int r = tid & 31;
            #pragma unroll
            for (int c4 = 0; c4 < CP / 4; c4++) xi[c4] = *(const float4*)&sx[half][r][4 * c4];
        }
        __syncthreads();
    }
    float ni = 0.f;
    #pragma unroll
    for (int c4 = 0; c4 < CP / 4; c4++)
        ni += xi[c4].x * xi[c4].x + xi[c4].y * xi[c4].y + xi[c4].z * xi[c4].z + xi[c4].w * xi[c4].w;
    sn[half][tid] = ni;
    __syncthreads();

    float bd0 = 1e30f, bd1 = 1e30f, bd2 = 1e30f, bd3 = 1e30f;
    int   bi0 = 0,     bi1 = 0,     bi2 = 0,     bi3 = 0;

    for (int t = 0; t < 4; t++) {
        for (int e = tid; e < 32 * CP; e += 128) {
            int r = e / CP, c = e % CP;
            sx[half][r][c] = (c < C) ? xb[(size_t)(t * 32 + r) * ld + c] : 0.f;
        }
        __syncthreads();
        for (int jl = 0; jl < 32; jl++) {
            int j = t * 32 + jl;
            float dot = 0.f;
            #pragma unroll
            for (int c4 = 0; c4 < CP / 4; c4++) {
                float4 xj = *(const float4*)&sx[half][jl][4 * c4];
                dot += xi[c4].x * xj.x + xi[c4].y * xj.y + xi[c4].z * xj.z + xi[c4].w * xj.w;
            }
            float d = ni + sn[half][j] - 2.f * dot;
            if (j == tid) d = 1e30f;
            if (d < bd3) {
                if (d < bd2) {
                    bd3 = bd2; bi3 = bi2;
                    if (d < bd1) {
                        bd2 = bd1; bi2 = bi1;
                        if (d < bd0) { bd1 = bd0; bi1 = bi0; bd0 = d; bi0 = j; }
                        else         { bd1 = d; bi1 = j; }
                    } else { bd2 = d; bi2 = j; }
                } else { bd3 = d; bi3 = j; }
            }
        }
        __syncthreads();
    }
    int base = (b * 128 + tid) * 4;
    int gb = b * 128;
    idxout[base + 0] = gb + bi0;
    idxout[base + 1] = gb + bi1;
    idxout[base + 2] = gb + bi2;
    idxout[base + 3] = gb + bi3;
}

// ============================ tf32 3-term GEMM (KNN-feeding; FROZEN) =======
#define AP 36
#define AFLTS (128 * AP)
#define BFLTS (64 * AP)
#define SFL (2 * AFLTS + 2 * BFLTS)
template<int GATHER, int ACT, int RED>
__global__ void __launch_bounds__(256, 2) tfgemm_k(
    const float* __restrict__ A, int lda, int Kval,
    const float* __restrict__ PQ, int ldpq, int qofs,
    const float* __restrict__ b1, const int* __restrict__ eidx,
    const float* __restrict__ Wt, int Kpad,
    const float* __restrict__ bias,
    float* __restrict__ Co, int ldc, int cofs, int Nfull)
{
    extern __shared__ float sm[];
    const int tid = threadIdx.x;
    const int wid = tid >> 5, lane = tid & 31;
    const int g = lane >> 2, q = lane & 3;
    const int warp_m = wid >> 1, warp_n = wid & 1;
    const int m0 = blockIdx.y * 128;
    const int n0 = blockIdx.x * 64;
    const int iters = Kpad >> 5;

    const int lm = tid >> 3, lkc = (tid & 7) << 2;
    const int lr = tid >> 1, lh = (tid & 1) << 4;

    const float *Pp = nullptr, *Qp = nullptr;
    if (GATHER) {
        int mg = m0 + lr;
        Pp = PQ + (size_t)(mg >> 2) * ldpq;
        Qp = PQ + (size_t)eidx[mg] * ldpq + qofs;
    }

    float4 rA[4], rQ[4], rB[2];

    auto ldg_tile = [&](int it) {
        const int k0 = it << 5;
        if (GATHER) {
            #pragma unroll
            for (int qq = 0; qq < 4; qq++) {
                int kk = k0 + lh + (qq << 2);
                rA[qq] = *(const float4*)(Pp + kk);
                rQ[qq] = *(const float4*)(Qp + kk);
            }
        } else {
            #pragma unroll
            for (int i = 0; i < 4; i++) {
                int gk = k0 + lkc;
                const float* src = A + (size_t)(m0 + lm + i * 32) * lda + gk;
                if (gk + 3 < Kval) {
                    rA[i] = *(const float4*)src;
                } else {
                    rA[i] = make_float4(0.f, 0.f, 0.f, 0.f);
                    if (gk + 0 < Kval) rA[i].x = src[0];
                    if (gk + 1 < Kval) rA[i].y = src[1];
                    if (gk + 2 < Kval) rA[i].z = src[2];
                }
            }
        }
        #pragma unroll
        for (int i = 0; i < 2; i++) {
            int gn = n0 + lm + i * 32;
            if (gn < Nfull) rB[i] = *(const float4*)(Wt + (size_t)gn * Kpad + (it << 5) + lkc);
            else            rB[i] = make_float4(0.f, 0.f, 0.f, 0.f);
        }
    };

    auto sts_tile = [&](int s, int it) {
        float* Ah = sm + s * SFL;
        float* Al = Ah + AFLTS;
        float* Bh = sm + s * SFL + 2 * AFLTS;
        float* Bl = Bh + BFLTS;
        if (GATHER) {
            const int k0 = it << 5;
            #pragma unroll
            for (int qq = 0; qq < 4; qq++) {
                int kk = lh + (qq << 2);
                float4 bv = *(const float4*)(b1 + k0 + kk);
                float4 hv, lv;
                sp_tf32(eluf(rA[qq].x + rQ[qq].x + bv.x), hv.x, lv.x);
                sp_tf32(eluf(rA[qq].y + rQ[qq].y + bv.y), hv.y, lv.y);
                sp_tf32(eluf(rA[qq].z + rQ[qq].z + bv.z), hv.z, lv.z);
                sp_tf32(eluf(rA[qq].w + rQ[qq].w + bv.w), hv.w, lv.w);
                *(float4*)&Ah[lr * AP + kk] = hv;
                *(float4*)&Al[lr * AP + kk] = lv;
            }
        } else {
            #pragma unroll
            for (int i = 0; i < 4; i++) {
                float4 hv, lv;
                sp_tf32(rA[i].x, hv.x, lv.x);
                sp_tf32(rA[i].y, hv.y, lv.y);
                sp_tf32(rA[i].z, hv.z, lv.z);
                sp_tf32(rA[i].w, hv.w, lv.w);
                *(float4*)&Ah[(lm + i * 32) * AP + lkc] = hv;
                *(float4*)&Al[(lm + i * 32) * AP + lkc] = lv;
            }
        }
        #pragma unroll
        for (int i = 0; i < 2; i++) {
            float4 hv, lv;
            sp_tf32(rB[i].x, hv.x, lv.x);
            sp_tf32(rB[i].y, hv.y, lv.y);
            sp_tf32(rB[i].z, hv.z, lv.z);
            sp_tf32(rB[i].w, hv.w, lv.w);
            *(float4*)&Bh[(lm + i * 32) * AP + lkc] = hv;
            *(float4*)&Bl[(lm + i * 32) * AP + lkc] = lv;
        }
    };

    float acc[2][4][4];
    #pragma unroll
    for (int mt = 0; mt < 2; mt++)
        #pragma unroll
        for (int nt = 0; nt < 4; nt++)
            #pragma unroll
            for (int i = 0; i < 4; i++) acc[mt][nt][i] = 0.f;

    const int abase = (warp_m * 32 + g) * AP;
    const int bbase = (warp_n * 32 + g) * AP;

    ldg_tile(0);
    sts_tile(0, 0);
    for (int it = 0; it < iters; it++) {
        if (it + 1 < iters) ldg_tile(it + 1);
        __syncthreads();
        const int s = it & 1;
        const float* Ah = sm + s * SFL;
        const float* Al = Ah + AFLTS;
        const float* Bh = sm + s * SFL + 2 * AFLTS;
        const float* Bl = Bh + BFLTS;
        #pragma unroll
        for (int ks = 0; ks < 4; ks++) {
            const int kb = (ks << 3) + q;
            uint32_t ah[2][4], al[2][4];
            #pragma unroll
            for (int mt = 0; mt < 2; mt++) {
                int rb = abase + mt * 16 * AP;
                ah[mt][0] = __float_as_uint(Ah[rb + kb]);
                al[mt][0] = __float_as_uint(Al[rb + kb]);
                ah[mt][1] = __float_as_uint(Ah[rb + 8 * AP + kb]);
                al[mt][1] = __float_as_uint(Al[rb + 8 * AP + kb]);
                ah[mt][2] = __float_as_uint(Ah[rb + kb + 4]);
                al[mt][2] = __float_as_uint(Al[rb + kb + 4]);
                ah[mt][3] = __float_as_uint(Ah[rb + 8 * AP + kb + 4]);
                al[mt][3] = __float_as_uint(Al[rb + 8 * AP + kb + 4]);
            }
            uint32_t bh[4][2], bl[4][2];
            #pragma unroll
            for (int nt = 0; nt < 4; nt++) {
                int rb = bbase + nt * 8 * AP;
                bh[nt][0] = __float_as_uint(Bh[rb + kb]);
                bl[nt][0] = __float_as_uint(Bl[rb + kb]);
                bh[nt][1] = __float_as_uint(Bh[rb + kb + 4]);
                bl[nt][1] = __float_as_uint(Bl[rb + kb + 4]);
            }
            #pragma unroll
            for (int mt = 0; mt < 2; mt++)
                #pragma unroll
                for (int nt = 0; nt < 4; nt++) {
                    mma8(acc[mt][nt], ah[mt], bh[nt]);
                    mma8(acc[mt][nt], al[mt], bh[nt]);
                    mma8(acc[mt][nt], ah[mt], bl[nt]);
                }
        }
        if (it + 1 < iters) sts_tile((it + 1) & 1, it + 1);
    }

    #pragma unroll
    for (int mt = 0; mt < 2; mt++) {
        const int rbase = m0 + warp_m * 32 + mt * 16;
        #pragma unroll
        for (int nt = 0; nt < 4; nt++) {
            const int cl = warp_n * 32 + nt * 8 + 2 * q;
            const int gc = n0 + cl;
            float bb0 = 0.f, bb1 = 0.f;
            if (bias != nullptr) {
                if (gc < Nfull)     bb0 = bias[gc];
                if (gc + 1 < Nfull) bb1 = bias[gc + 1];
            }
            if (!RED) {
                float v0 = acc[mt][nt][0] + bb0, v1 = acc[mt][nt][1] + bb1;
                float v2 = acc[mt][nt][2] + bb0, v3 = acc[mt][nt][3] + bb1;
                if (ACT) { v0 = eluf(v0); v1 = eluf(v1); v2 = eluf(v2); v3 = eluf(v3); }
                float* r0 = Co + (size_t)(rbase + g) * ldc + cofs;
                float* r1 = r0 + (size_t)8 * ldc;
                if (gc < Nfull)     { r0[gc] = v0;     r1[gc] = v2; }
                if (gc + 1 < Nfull) { r0[gc + 1] = v1; r1[gc + 1] = v3; }
            } else {
                #pragma unroll
                for (int half = 0; half < 2; half++) {
                    float v0 = (gc < Nfull)     ? eluf(acc[mt][nt][2 * half + 0] + bb0) : 0.f;
                    float v1 = (gc + 1 < Nfull) ? eluf(acc[mt][nt][2 * half + 1] + bb1) : 0.f;
                    v0 += __shfl_xor_sync(0xffffffffu, v0, 4);
                    v0 += __shfl_xor_sync(0xffffffffu, v0, 8);
                    v1 += __shfl_xor_sync(0xffffffffu, v1, 4);
                    v1 += __shfl_xor_sync(0xffffffffu, v1, 8);
                    if ((lane & 12) == 0) {
                        int p = (rbase + half * 8 + g) >> 2;
                        float* op = Co + (size_t)p * ldc + cofs;
                        if (gc < Nfull)     op[gc] = 0.25f * v0;
                        if (gc + 1 < Nfull) op[gc + 1] = 0.25f * v1;
                    }
                }
            }
        }
    }
}

// ============================ fp16 GEMM (post-KNN) =========================
// A: fp32 source -> hi+lo fp16 planes (2-term); fp16 source (INH) -> exact,
// single plane (1-term for dense; gather INH re-splits after elu in fp32).
// B: single fp16 plane. OUTH: write output as fp16 (ldc/cofs in half units).
#define APU 20
#define AHLU (128 * APU)
#define BHLU (64 * APU)
#define SFLU (2 * AHLU + BHLU)     // 6400 u32 per stage
template<int GATHER, int ACT, int RED, int INH, int OUTH>
__global__ void __launch_bounds__(256, 2) hfgemm_k(
    const float* __restrict__ A, int lda, int Kval,
    const float* __restrict__ PQ, int ldpq, int qofs,
    const float* __restrict__ b1, const int* __restrict__ eidx,
    const float* __restrict__ Wt, int Kpad,
    const float* __restrict__ bias,
    float* __restrict__ Co, int ldc, int cofs, int Nfull)
{
    constexpr int ATERMS = (INH && !GATHER) ? 1 : 2;
    extern __shared__ uint32_t smu[];
    const int tid = threadIdx.x;
    const int wid = tid >> 5, lane = tid & 31;
    const int g = lane >> 2, q = lane & 3;
    const int warp_m = wid >> 1, warp_n = wid & 1;
    const int m0 = blockIdx.y * 128;
    const int n0 = blockIdx.x * 64;
    const int iters = Kpad >> 5;

    const int lm = tid >> 3, lkc = (tid & 7) << 2;
    const int luc = (tid & 7) << 1;
    const int lr = tid >> 1, lh = (tid & 1) << 4;
    const int lgu = (tid & 1) << 3;

    const float *Pp = nullptr, *Qp = nullptr;
    const __half *Pph = nullptr, *Qph = nullptr;
    if (GATHER) {
        int mg = m0 + lr;
        if (INH) {
            Pph = (const __half*)PQ + (size_t)(mg >> 2) * ldpq;
            Qph = (const __half*)PQ + (size_t)eidx[mg] * ldpq + qofs;
        } else {
            Pp = PQ + (size_t)(mg >> 2) * ldpq;
            Qp = PQ + (size_t)eidx[mg] * ldpq + qofs;
        }
    }

    float4 rA[4], rQ[4], rB[2];
    uint2 rAh[4];
    uint4 rPh[2], rQh[2];

    auto ldg_tile = [&](int it) {
        const int k0 = it << 5;
        if (GATHER) {
            if (INH) {
                rPh[0] = *(const uint4*)(Pph + k0 + lh);
                rPh[1] = *(const uint4*)(Pph + k0 + lh + 8);
                rQh[0] = *(const uint4*)(Qph + k0 + lh);
                rQh[1] = *(const uint4*)(Qph + k0 + lh + 8);
            } else {
                #pragma unroll
                for (int qq = 0; qq < 4; qq++) {
                    int kk = k0 + lh + (qq << 2);
                    rA[qq] = *(const float4*)(Pp + kk);
                    rQ[qq] = *(const float4*)(Qp + kk);
                }
            }
        } else if (INH) {
            #pragma unroll
            for (int i = 0; i < 4; i++) {
                int gk = k0 + lkc;
                const __half* src = (const __half*)A + (size_t)(m0 + lm + i * 32) * lda + gk;
                if (gk + 3 < Kval) rAh[i] = *(const uint2*)src;
                else               rAh[i] = make_uint2(0u, 0u);
            }
        } else {
            #pragma unroll
            for (int i = 0; i < 4; i++) {
                int gk = k0 + lkc;
                const float* src = A + (size_t)(m0 + lm + i * 32) * lda + gk;
                if (gk + 3 < Kval) {
                    rA[i] = *(const float4*)src;
                } else {
                    rA[i] = make_float4(0.f, 0.f, 0.f, 0.f);
                    if (gk + 0 < Kval) rA[i].x = src[0];
                    if (gk + 1 < Kval) rA[i].y = src[1];
                    if (gk + 2 < Kval) rA[i].z = src[2];
                }
            }
        }
        #pragma unroll
        for (int i = 0; i < 2; i++) {
            int gn = n0 + lm + i * 32;
            if (gn < Nfull) rB[i] = *(const float4*)(Wt + (size_t)gn * Kpad + (it << 5) + lkc);
            else            rB[i] = make_float4(0.f, 0.f, 0.f, 0.f);
        }
    };

    auto sts_tile = [&](int s, int it) {
        uint32_t* Ah = smu + s * SFLU;
        uint32_t* Al = Ah + AHLU;
        uint32_t* Bh = smu + s * SFLU + 2 * AHLU;
        if (GATHER) {
            const int k0 = it << 5;
            if (INH) {
                const uint32_t* pw = (const uint32_t*)rPh;
                const uint32_t* qw = (const uint32_t*)rQh;
                #pragma unroll
                for (int qq = 0; qq < 4; qq++) {
                    int kk = lh + (qq << 2);
                    float4 bv = *(const float4*)(b1 + k0 + kk);
                    float2 p0 = __half22float2(*(const __half2*)&pw[2 * qq]);
                    float2 p1 = __half22float2(*(const __half2*)&pw[2 * qq + 1]);
                    float2 q0 = __half22float2(*(const __half2*)&qw[2 * qq]);
                    float2 q1 = __half22float2(*(const __half2*)&qw[2 * qq + 1]);
                    float v0 = eluf(p0.x + q0.x + bv.x);
                    float v1 = eluf(p0.y + q0.y + bv.y);
                    float v2 = eluf(p1.x + q1.x + bv.z);
                    float v3 = eluf(p1.y + q1.y + bv.w);
                    uint32_t h0, l0, h1, l1;
                    sp_hf(v0, v1, h0, l0);
                    sp_hf(v2, v3, h1, l1);
                    *(uint2*)&Ah[lr * APU + lgu + (qq << 1)] = make_uint2(h0, h1);
                    *(uint2*)&Al[lr * APU + lgu + (qq << 1)] = make_uint2(l0, l1);
                }
            } else {
                #pragma unroll
                for (int qq = 0; qq < 4; qq++) {
                    int kk = lh + (qq << 2);
                    float4 bv = *(const float4*)(b1 + k0 + kk);
                    float v0 = eluf(rA[qq].x + rQ[qq].x + bv.x);
                    float v1 = eluf(rA[qq].y + rQ[qq].y + bv.y);
                    float v2 = eluf(rA[qq].z + rQ[qq].z + bv.z);
                    float v3 = eluf(rA[qq].w + rQ[qq].w + bv.w);
                    uint32_t h0, l0, h1, l1;
                    sp_hf(v0, v1, h0, l0);
                    sp_hf(v2, v3, h1, l1);
                    *(uint2*)&Ah[lr * APU + lgu + (qq << 1)] = make_uint2(h0, h1);
                    *(uint2*)&Al[lr * APU + lgu + (qq << 1)] = make_uint2(l0, l1);
                }
            }
        } else if (INH) {
            #pragma unroll
            for (int i = 0; i < 4; i++)
                *(uint2*)&Ah[(lm + i * 32) * APU + luc] = rAh[i];
        } else {
            #pragma unroll
            for (int i = 0; i < 4; i++) {
                uint32_t h0, l0, h1, l1;
                sp_hf(rA[i].x, rA[i].y, h0, l0);
                sp_hf(rA[i].z, rA[i].w, h1, l1);
                *(uint2*)&Ah[(lm + i * 32) * APU + luc] = make_uint2(h0, h1);
                *(uint2*)&Al[(lm + i * 32) * APU + luc] = make_uint2(l0, l1);
            }
        }
        #pragma unroll
        for (int i = 0; i < 2; i++) {
            uint32_t h0 = hf1(rB[i].x, rB[i].y);
            uint32_t h1 = hf1(rB[i].z, rB[i].w);
            *(uint2*)&Bh[(lm + i * 32) * APU + luc] = make_uint2(h0, h1);
        }
    };

    float acc[2][4][4];
    #pragma unroll
    for (int mt = 0; mt < 2; mt++)
        #pragma unroll
        for (int nt = 0; nt < 4; nt++)
            #pragma unroll
            for (int i = 0; i < 4; i++) acc[mt][nt][i] = 0.f;

    const int abase = (warp_m * 32 + g) * APU;
    const int bbase = (warp_n * 32 + g) * APU;

    ldg_tile(0);
    sts_tile(0, 0);
    for (int it = 0; it < iters; it++) {
        if (it + 1 < iters) ldg_tile(it + 1);
        __syncthreads();
        const int s = it & 1;
        const uint32_t* Ah = smu + s * SFLU;
        const uint32_t* Al = Ah + AHLU;
        const uint32_t* Bh = smu + s * SFLU + 2 * AHLU;
        #pragma unroll
        for (int ks = 0; ks < 2; ks++) {
            const int koff = (ks << 3) + q;
            uint32_t ah[2][4], al[2][4];
            #pragma unroll
            for (int mt = 0; mt < 2; mt++) {
                int rb = abase + mt * 16 * APU;
                ah[mt][0] = Ah[rb + koff];
                ah[mt][1] = Ah[rb + 8 * APU + koff];
                ah[mt][2] = Ah[rb + koff + 4];
                ah[mt][3] = Ah[rb + 8 * APU + koff + 4];
                if (ATERMS == 2) {
                    al[mt][0] = Al[rb + koff];
                    al[mt][1] = Al[rb + 8 * APU + koff];
                    al[mt][2] = Al[rb + koff + 4];
                    al[mt][3] = Al[rb + 8 * APU + koff + 4];
                }
            }
            uint32_t bh[4][2];
            #pragma unroll
            for (int nt = 0; nt < 4; nt++) {
                int rb = bbase + nt * 8 * APU;
                bh[nt][0] = Bh[rb + koff];
                bh[nt][1] = Bh[rb + koff + 4];
            }
            #pragma unroll
            for (int mt = 0; mt < 2; mt++)
                #pragma unroll
                for (int nt = 0; nt < 4; nt++) {
                    mma16h(acc[mt][nt], ah[mt], bh[nt]);
                    if (ATERMS == 2) mma16h(acc[mt][nt], al[mt], bh[nt]);
                }
        }
        if (it + 1 < iters) sts_tile((it + 1) & 1, it + 1);
    }

    #pragma unroll
    for (int mt = 0; mt < 2; mt++) {
        const int rbase = m0 + warp_m * 32 + mt * 16;
        #pragma unroll
        for (int nt = 0; nt < 4; nt++) {
            const int cl = warp_n * 32 + nt * 8 + 2 * q;
            const int gc = n0 + cl;
            float bb0 = 0.f, bb1 = 0.f;
            if (bias != nullptr) {
                if (gc < Nfull)     bb0 = bias[gc];
                if (gc + 1 < Nfull) bb1 = bias[gc + 1];
            }
            if (!RED) {
                float v0 = acc[mt][nt][0] + bb0, v1 = acc[mt][nt][1] + bb1;
                float v2 = acc[mt][nt][2] + bb0, v3 = acc[mt][nt][3] + bb1;
                if (ACT) { v0 = eluf(v0); v1 = eluf(v1); v2 = eluf(v2); v3 = eluf(v3); }
                if (OUTH) {
                    __half* o0 = (__half*)Co + (size_t)(rbase + g) * ldc + cofs;
                    __half* o1 = o0 + (size_t)8 * ldc;
                    if (gc + 1 < Nfull) {
                        *(__half2*)(o0 + gc) = __floats2half2_rn(v0, v1);
                        *(__half2*)(o1 + gc) = __floats2half2_rn(v2, v3);
                    } else if (gc < Nfull) {
                        o0[gc] = __float2half(v0);
                        o1[gc] = __float2half(v2);
                    }
                } else {
                    float* r0 = Co + (size_t)(rbase + g) * ldc + cofs;
                    float* r1 = r0 + (size_t)8 * ldc;
                    if (gc < Nfull)     { r0[gc] = v0;     r1[gc] = v2; }
                    if (gc + 1 < Nfull) { r0[gc + 1] = v1; r1[gc + 1] = v3; }
                }
            } else {
                #pragma unroll
                for (int half = 0; half < 2; half++) {
                    float v0 = (gc < Nfull)     ? eluf(acc[mt][nt][2 * half + 0] + bb0) : 0.f;
                    float v1 = (gc + 1 < Nfull) ? eluf(acc[mt][nt][2 * half + 1] + bb1) : 0.f;
                    v0 += __shfl_xor_sync(0xffffffffu, v0, 4);
                    v0 += __shfl_xor_sync(0xffffffffu, v0, 8);
                    v1 += __shfl_xor_sync(0xffffffffu, v1, 4);
                    v1 += __shfl_xor_sync(0xffffffffu, v1, 8);
                    if ((lane & 12) == 0) {
                        int p = (rbase + half * 8 + g) >> 2;
                        float* op = Co + (size_t)p * ldc + cofs;
                        if (gc < Nfull)     op[gc] = 0.25f * v0;
                        if (gc + 1 < Nfull) op[gc + 1] = 0.25f * v1;
                    }
                }
            }
        }
    }
}

// ============================ final tiny GEMM ==============================
__global__ void head3_k(const float* __restrict__ H2, const float* __restrict__ w,
                        const float* __restrict__ b, float* __restrict__ out) {
    int gtid = blockIdx.x * blockDim.x + threadIdx.x;
    int warp = gtid >> 5;
    int lane = threadIdx.x & 31;
    if (warp >= NPTS) return;
    const float* hr = H2 + (size_t)warp * 228;
    float a0 = 0.f, a1 = 0.f;
    for (int c = lane; c < 226; c += 32) {
        float h = hr[c];
        a0 += h * w[2 * c];
        a1 += h * w[2 * c + 1];
    }
    #pragma unroll
    for (int o = 16; o; o >>= 1) {
        a0 += __shfl_xor_sync(0xffffffffu, a0, o);
        a1 += __shfl_xor_sync(0xffffffffu, a1, o);
    }
    if (lane == 0) {
        out[2 * warp + 0] = a0 + b[0];
        out[2 * warp + 1] = a1 + b[1];
    }
}

// ============================ launcher =====================================
extern "C" void kernel_launch(void* const* d_in, const int* in_sizes, int n_in,
                              void* d_out, int out_size) {
    const float* coords   = (const float*)d_in[0];
    const float* features = (const float*)d_in[1];
    const float* c1w1 = (const float*)d_in[2];
    const float* c1b1 = (const float*)d_in[3];
    const float* c1w2 = (const float*)d_in[4];
    const float* c1b2 = (const float*)d_in[5];
    const float* c2w1 = (const float*)d_in[6];
    const float* c2b1 = (const float*)d_in[7];
    const float* c2w2 = (const float*)d_in[8];
    const float* c2b2 = (const float*)d_in[9];
    const float* c3w1 = (const float*)d_in[10];
    const float* c3b1 = (const float*)d_in[11];
    const float* c3w2 = (const float*)d_in[12];
    const float* c3b2 = (const float*)d_in[13];
    const float* ow1  = (const float*)d_in[14];
    const float* ob1  = (const float*)d_in[15];
    const float* ow2  = (const float*)d_in[16];
    const float* ob2  = (const float*)d_in[17];
    const float* ow3  = (const float*)d_in[18];
    const float* ob3  = (const float*)d_in[19];

    float *pX, *pPQ, *pH1, *pWt; int* pidx;
    cudaGetSymbolAddress((void**)&pX,  g_X453);
    cudaGetSymbolAddress((void**)&pPQ, g_PQ);
    cudaGetSymbolAddress((void**)&pH1, g_H1);
    cudaGetSymbolAddress((void**)&pWt, g_Wt);
    cudaGetSymbolAddress((void**)&pidx, g_idx);

    const int SMEM_TF = 2 * SFL * 4;    // 110,592 B
    const int SMEM_HF = 2 * SFLU * 4;   // 51,200 B
    cudaFuncSetAttribute(tfgemm_k<0, 0, 0>, cudaFuncAttributeMaxDynamicSharedMemorySize, SMEM_TF);
    cudaFuncSetAttribute(tfgemm_k<1, 1, 1>, cudaFuncAttributeMaxDynamicSharedMemorySize, SMEM_TF);
    cudaFuncSetAttribute(hfgemm_k<0, 0, 0, 0, 1>, cudaFuncAttributeMaxDynamicSharedMemorySize, SMEM_HF);
    cudaFuncSetAttribute(hfgemm_k<1, 1, 1, 1, 0>, cudaFuncAttributeMaxDynamicSharedMemorySize, SMEM_HF);
    cudaFuncSetAttribute(hfgemm_k<0, 1, 0, 0, 1>, cudaFuncAttributeMaxDynamicSharedMemorySize, SMEM_HF);
    cudaFuncSetAttribute(hfgemm_k<0, 1, 0, 1, 0>, cudaFuncAttributeMaxDynamicSharedMemorySize, SMEM_HF);

    const int MT_P = NPTS / 128;   // 1024
    const int MT_E = NEDG / 128;   // 4096

    copy_features_k<<<(NPTS * 5 + 255) / 256, 256>>>(features, pX);

    // ===== EdgeConv 1 (C=5, H=32, O=64) — feeds knn2: tf32 3-term (FROZEN) =====
    knn_k<2, 4><<<512, 256>>>(coords, 2, 0, pidx);
    prep_pq_k<<<(64 * 32 + 255) / 256, 256>>>(c1w1, pWt, 5, 32, 32);
    tfgemm_k<0, 0, 0><<<dim3(1, MT_P), 256, SMEM_TF>>>(pX, XLD, 5, nullptr, 0, 0, nullptr, nullptr,
                                                       pWt, 32, nullptr, pPQ, 64, 0, 64);
    prep_wt_k<<<(64 * 32 + 255) / 256, 256>>>(c1w2, pWt, 32, 64, 32);
    tfgemm_k<1, 1, 1><<<dim3(1, MT_E), 256, SMEM_TF>>>(nullptr, 0, 32, pPQ, 64, 32, c1b1, pidx,
                                                       pWt, 32, c1b2, pX, XLD, O1_OFS, 64);

    // ===== EdgeConv 2 (C=64, H=96, O=128) — feeds knn3: tf32 3-term (FROZEN) =====
    knn_k<64, 64><<<512, 256>>>(pX, XLD, O1_OFS, pidx);
    prep_pq_k<<<(192 * 64 + 255) / 256, 256>>>(c2w1, pWt, 64, 96, 64);
    tfgemm_k<0, 0, 0><<<dim3(3, MT_P), 256, SMEM_TF>>>(pX + O1_OFS, XLD, 64, nullptr, 0, 0, nullptr, nullptr,
                                                       pWt, 64, nullptr, pPQ, 192, 0, 192);
    prep_wt_k<<<(128 * 96 + 255) / 256, 256>>>(c2w2, pWt, 96, 128, 96);
    tfgemm_k<1, 1, 1><<<dim3(2, MT_E), 256, SMEM_TF>>>(nullptr, 0, 96, pPQ, 192, 96, c2b1, pidx,
                                                       pWt, 96, c2b2, pX, XLD, O2_OFS, 128);

    // ===== EdgeConv 3 — post-KNN: fp16, PQ3 stored half =====
    knn_k<128, 128><<<512, 256>>>(pX, XLD, O2_OFS, pidx);
    prep_pq_k<<<(384 * 128 + 255) / 256, 256>>>(c3w1, pWt, 128, 192, 128);
    hfgemm_k<0, 0, 0, 0, 1><<<dim3(6, MT_P), 256, SMEM_HF>>>(pX + O2_OFS, XLD, 128, nullptr, 0, 0, nullptr, nullptr,
                                                             pWt, 128, nullptr, pPQ, 384, 0, 384);
    prep_wt_k<<<(256 * 192 + 255) / 256, 256>>>(c3w2, pWt, 192, 256, 192);
    hfgemm_k<1, 1, 1, 1, 0><<<dim3(4, MT_E), 256, SMEM_HF>>>(nullptr, 0, 192, pPQ, 384, 192, c3b1, pidx,
                                                             pWt, 192, c3b2, pX, XLD, O3_OFS, 256);

    // ===== Head — post-KNN: fp16, H1 stored half, h2 1-term =====
    prep_head_k<<<(453 * 480 + 255) / 256, 256>>>(ow1, pWt, 453, 480);
    hfgemm_k<0, 1, 0, 0, 1><<<dim3(8, MT_P), 256, SMEM_HF>>>(pX, XLD, 456, nullptr, 0, 0, nullptr, nullptr,
                                                             pWt, 480, ob1, pH1, 456, 0, 453);
    prep_wt_k<<<(226 * 480 + 255) / 256, 256>>>(ow2, pWt, 453, 226, 480);
    hfgemm_k<0, 1, 0, 1, 0><<<dim3(4, MT_P), 256, SMEM_HF>>>(pH1, 456, 456, nullptr, 0, 0, nullptr, nullptr,
                                                             pWt, 480, ob2, pPQ, 228, 0, 226);
    head3_k<<<(NPTS * 32) / 256, 256>>>(pPQ, ow3, ob3, (float*)d_out);
}

// round 11
// speedup vs baseline: 1.1830x; 1.0295x over previous
#include <cuda_runtime.h>
#include <cuda_fp16.h>
#include <cstdint>
#include <math.h>

// ============================ problem constants ============================
#define NPTS 131072          // B*N = 1024*128
#define NEDG 524288          // NPTS * K(=4)

// Concat buffer layout (all segment starts 16B-aligned; pads never written => 0)
#define F_OFS  0
#define O1_OFS 8
#define O2_OFS 72
#define O3_OFS 200
#define XLD    456

// ============================ device scratch ===============================
__device__ float  g_X453[(size_t)NPTS * XLD];   // fp32 concat (KNN reads; frozen)
__device__ __half g_Xh[(size_t)NPTS * XLD];     // fp16 mirror (post-KNN A source)
__device__ float  g_PQ[(size_t)NPTS * 384];     // fp32 PQ1/PQ2; fp16 PQ3; fp32 H2 (ld 228)
__device__ float  g_H1[(size_t)NPTS * 456];     // fp16 H1 (ld 456 halves)
__device__ int    g_idx[NPTS * 4];
__device__ float  g_Wt[512 * 480];

__device__ __forceinline__ float eluf(float x) { return x > 0.f ? x : expm1f(x); }

// ============================ small helpers ================================
__device__ __forceinline__ void sp_tf32(float a, float& h, float& l) {
    uint32_t hu;
    asm("cvt.rna.tf32.f32 %0, %1;" : "=r"(hu) : "f"(a));
    h = __uint_as_float(hu);
    float lf = a - h;
    uint32_t lu;
    asm("cvt.rna.tf32.f32 %0, %1;" : "=r"(lu) : "f"(lf));
    l = __uint_as_float(lu);
}
__device__ __forceinline__ void mma8(float* c, const uint32_t* a, const uint32_t* b) {
    asm volatile("mma.sync.aligned.m16n8k8.row.col.f32.tf32.tf32.f32 "
                 "{%0,%1,%2,%3}, {%4,%5,%6,%7}, {%8,%9}, {%0,%1,%2,%3};"
                 : "+f"(c[0]), "+f"(c[1]), "+f"(c[2]), "+f"(c[3])
                 : "r"(a[0]), "r"(a[1]), "r"(a[2]), "r"(a[3]), "r"(b[0]), "r"(b[1]));
}
__device__ __forceinline__ void sp_hf(float a0, float a1, uint32_t& h, uint32_t& l) {
    __half2 hh = __floats2half2_rn(a0, a1);
    float r0 = a0 - __half2float(__low2half(hh));
    float r1 = a1 - __half2float(__high2half(hh));
    __half2 ll = __floats2half2_rn(r0, r1);
    h = *reinterpret_cast<uint32_t*>(&hh);
    l = *reinterpret_cast<uint32_t*>(&ll);
}
__device__ __forceinline__ uint32_t hf1(float a0, float a1) {
    __half2 hh = __floats2half2_rn(a0, a1);
    return *reinterpret_cast<uint32_t*>(&hh);
}
__device__ __forceinline__ void mma16h(float* c, const uint32_t* a, const uint32_t* b) {
    asm volatile("mma.sync.aligned.m16n8k16.row.col.f32.f16.f16.f32 "
                 "{%0,%1,%2,%3}, {%4,%5,%6,%7}, {%8,%9}, {%0,%1,%2,%3};"
                 : "+f"(c[0]), "+f"(c[1]), "+f"(c[2]), "+f"(c[3])
                 : "r"(a[0]), "r"(a[1]), "r"(a[2]), "r"(a[3]), "r"(b[0]), "r"(b[1]));
}

// ============================ elementwise helpers ==========================
__global__ void copy_features_k(const float* __restrict__ f, float* __restrict__ X,
                                __half* __restrict__ Xh) {
    int e = blockIdx.x * blockDim.x + threadIdx.x;
    if (e < NPTS * 5) {
        int r = e / 5, c = e % 5;
        X[(size_t)r * XLD + c] = f[e];
        Xh[(size_t)r * XLD + c] = __float2half(f[e]);
    }
}
__global__ void prep_pq_k(const float* __restrict__ w1, float* __restrict__ wt, int C, int H, int Kpad) {
    int e = blockIdx.x * blockDim.x + threadIdx.x;
    if (e >= 2 * H * Kpad) return;
    int n = e / Kpad, k = e % Kpad;
    float v = 0.f;
    if (k < C) v = (n < H) ? (w1[k * H + n] - w1[(C + k) * H + n]) : w1[(C + k) * H + (n - H)];
    wt[(size_t)n * Kpad + k] = v;
}
__global__ void prep_wt_k(const float* __restrict__ w, float* __restrict__ wt, int K, int N, int Kpad) {
    int e = blockIdx.x * blockDim.x + threadIdx.x;
    if (e >= N * Kpad) return;
    int n = e / Kpad, k = e % Kpad;
    wt[(size_t)n * Kpad + k] = (k < K) ? w[(size_t)k * N + n] : 0.f;
}
__global__ void prep_head_k(const float* __restrict__ w, float* __restrict__ wt, int N, int Kpad) {
    int e = blockIdx.x * blockDim.x + threadIdx.x;
    if (e >= N * Kpad) return;
    int n = e / Kpad, kp = e % Kpad;
    float v = 0.f;
    if (kp < 5)                   v = w[(size_t)kp * N + n];
    else if (kp >= 8 && kp < 456) v = w[(size_t)(kp - 3) * N + n];
    wt[(size_t)n * Kpad + kp] = v;
}

// ============================ KNN (k=4; 2 batches per block; FROZEN) =======
template<int C, int CP>
__global__ void __launch_bounds__(256) knn_k(const float* __restrict__ x, int ld, int cofs,
                                             int* __restrict__ idxout) {
    constexpr int PAD = CP + 4;
    __shared__ __align__(16) float sx[2][32][PAD];
    __shared__ float sn[2][128];
    int half = threadIdx.x >> 7;
    int tid = threadIdx.x & 127;
    int b = blockIdx.x * 2 + half;
    const float* xb = x + (size_t)b * 128 * ld + cofs;
    float4 xi[CP / 4];

    for (int t = 0; t < 4; t++) {
        for (int e = tid; e < 32 * CP; e += 128) {
            int r = e / CP, c = e % CP;
            sx[half][r][c] = (c < C) ? xb[(size_t)(t * 32 + r) * ld + c] : 0.f;
        }
        __syncthreads();
        if ((tid >> 5) == t) {
            int r = tid & 31;
            #pragma unroll
            for (int c4 = 0; c4 < CP / 4; c4++) xi[c4] = *(const float4*)&sx[half][r][4 * c4];
        }
        __syncthreads();
    }
    float ni = 0.f;
    #pragma unroll
    for (int c4 = 0; c4 < CP / 4; c4++)
        ni += xi[c4].x * xi[c4].x + xi[c4].y * xi[c4].y + xi[c4].z * xi[c4].z + xi[c4].w * xi[c4].w;
    sn[half][tid] = ni;
    __syncthreads();

    float bd0 = 1e30f, bd1 = 1e30f, bd2 = 1e30f, bd3 = 1e30f;
    int   bi0 = 0,     bi1 = 0,     bi2 = 0,     bi3 = 0;

    for (int t = 0; t < 4; t++) {
        for (int e = tid; e < 32 * CP; e += 128) {
            int r = e / CP, c = e % CP;
            sx[half][r][c] = (c < C) ? xb[(size_t)(t * 32 + r) * ld + c] : 0.f;
        }
        __syncthreads();
        for (int jl = 0; jl < 32; jl++) {
            int j = t * 32 + jl;
            float dot = 0.f;
            #pragma unroll
            for (int c4 = 0; c4 < CP / 4; c4++) {
                float4 xj = *(const float4*)&sx[half][jl][4 * c4];
                dot += xi[c4].x * xj.x + xi[c4].y * xj.y + xi[c4].z * xj.z + xi[c4].w * xj.w;
            }
            float d = ni + sn[half][j] - 2.f * dot;
            if (j == tid) d = 1e30f;
            if (d < bd3) {
                if (d < bd2) {
                    bd3 = bd2; bi3 = bi2;
                    if (d < bd1) {
                        bd2 = bd1; bi2 = bi1;
                        if (d < bd0) { bd1 = bd0; bi1 = bi0; bd0 = d; bi0 = j; }
                        else         { bd1 = d; bi1 = j; }
                    } else { bd2 = d; bi2 = j; }
                } else { bd3 = d; bi3 = j; }
            }
        }
        __syncthreads();
    }
    int base = (b * 128 + tid) * 4;
    int gb = b * 128;
    idxout[base + 0] = gb + bi0;
    idxout[base + 1] = gb + bi1;
    idxout[base + 2] = gb + bi2;
    idxout[base + 3] = gb + bi3;
}

// ============================ tf32 3-term GEMM (KNN-feeding; numerics FROZEN)
// Xh2 != nullptr (RED path): mirror the fp32 output into the fp16 concat buf.
#define AP 36
#define AFLTS (128 * AP)
#define BFLTS (64 * AP)
#define SFL (2 * AFLTS + 2 * BFLTS)
template<int GATHER, int ACT, int RED>
__global__ void __launch_bounds__(256, 2) tfgemm_k(
    const float* __restrict__ A, int lda, int Kval,
    const float* __restrict__ PQ, int ldpq, int qofs,
    const float* __restrict__ b1, const int* __restrict__ eidx,
    const float* __restrict__ Wt, int Kpad,
    const float* __restrict__ bias,
    float* __restrict__ Co, int ldc, int cofs, int Nfull,
    __half* __restrict__ Xh2)
{
    extern __shared__ float sm[];
    const int tid = threadIdx.x;
    const int wid = tid >> 5, lane = tid & 31;
    const int g = lane >> 2, q = lane & 3;
    const int warp_m = wid >> 1, warp_n = wid & 1;
    const int m0 = blockIdx.y * 128;
    const int n0 = blockIdx.x * 64;
    const int iters = Kpad >> 5;

    const int lm = tid >> 3, lkc = (tid & 7) << 2;
    const int lr = tid >> 1, lh = (tid & 1) << 4;

    const float *Pp = nullptr, *Qp = nullptr;
    if (GATHER) {
        int mg = m0 + lr;
        Pp = PQ + (size_t)(mg >> 2) * ldpq;
        Qp = PQ + (size_t)eidx[mg] * ldpq + qofs;
    }

    float4 rA[4], rQ[4], rB[2];

    auto ldg_tile = [&](int it) {
        const int k0 = it << 5;
        if (GATHER) {
            #pragma unroll
            for (int qq = 0; qq < 4; qq++) {
                int kk = k0 + lh + (qq << 2);
                rA[qq] = *(const float4*)(Pp + kk);
                rQ[qq] = *(const float4*)(Qp + kk);
            }
        } else {
            #pragma unroll
            for (int i = 0; i < 4; i++) {
                int gk = k0 + lkc;
                const float* src = A + (size_t)(m0 + lm + i * 32) * lda + gk;
                if (gk + 3 < Kval) {
                    rA[i] = *(const float4*)src;
                } else {
                    rA[i] = make_float4(0.f, 0.f, 0.f, 0.f);
                    if (gk + 0 < Kval) rA[i].x = src[0];
                    if (gk + 1 < Kval) rA[i].y = src[1];
                    if (gk + 2 < Kval) rA[i].z = src[2];
                }
            }
        }
        #pragma unroll
        for (int i = 0; i < 2; i++) {
            int gn = n0 + lm + i * 32;
            if (gn < Nfull) rB[i] = *(const float4*)(Wt + (size_t)gn * Kpad + (it << 5) + lkc);
            else            rB[i] = make_float4(0.f, 0.f, 0.f, 0.f);
        }
    };

    auto sts_tile = [&](int s, int it) {
        float* Ah = sm + s * SFL;
        float* Al = Ah + AFLTS;
        float* Bh = sm + s * SFL + 2 * AFLTS;
        float* Bl = Bh + BFLTS;
        if (GATHER) {
            const int k0 = it << 5;
            #pragma unroll
            for (int qq = 0; qq < 4; qq++) {
                int kk = lh + (qq << 2);
                float4 bv = *(const float4*)(b1 + k0 + kk);
                float4 hv, lv;
                sp_tf32(eluf(rA[qq].x + rQ[qq].x + bv.x), hv.x, lv.x);
                sp_tf32(eluf(rA[qq].y + rQ[qq].y + bv.y), hv.y, lv.y);
                sp_tf32(eluf(rA[qq].z + rQ[qq].z + bv.z), hv.z, lv.z);
                sp_tf32(eluf(rA[qq].w + rQ[qq].w + bv.w), hv.w, lv.w);
                *(float4*)&Ah[lr * AP + kk] = hv;
                *(float4*)&Al[lr * AP + kk] = lv;
            }
        } else {
            #pragma unroll
            for (int i = 0; i < 4; i++) {
                float4 hv, lv;
                sp_tf32(rA[i].x, hv.x, lv.x);
                sp_tf32(rA[i].y, hv.y, lv.y);
                sp_tf32(rA[i].z, hv.z, lv.z);
                sp_tf32(rA[i].w, hv.w, lv.w);
                *(float4*)&Ah[(lm + i * 32) * AP + lkc] = hv;
                *(float4*)&Al[(lm + i * 32) * AP + lkc] = lv;
            }
        }
        #pragma unroll
        for (int i = 0; i < 2; i++) {
            float4 hv, lv;
            sp_tf32(rB[i].x, hv.x, lv.x);
            sp_tf32(rB[i].y, hv.y, lv.y);
            sp_tf32(rB[i].z, hv.z, lv.z);
            sp_tf32(rB[i].w, hv.w, lv.w);
            *(float4*)&Bh[(lm + i * 32) * AP + lkc] = hv;
            *(float4*)&Bl[(lm + i * 32) * AP + lkc] = lv;
        }
    };

    float acc[2][4][4];
    #pragma unroll
    for (int mt = 0; mt < 2; mt++)
        #pragma unroll
        for (int nt = 0; nt < 4; nt++)
            #pragma unroll
            for (int i = 0; i < 4; i++) acc[mt][nt][i] = 0.f;

    const int abase = (warp_m * 32 + g) * AP;
    const int bbase = (warp_n * 32 + g) * AP;

    ldg_tile(0);
    sts_tile(0, 0);
    for (int it = 0; it < iters; it++) {
        if (it + 1 < iters) ldg_tile(it + 1);
        __syncthreads();
        const int s = it & 1;
        const float* Ah = sm + s * SFL;
        const float* Al = Ah + AFLTS;
        const float* Bh = sm + s * SFL + 2 * AFLTS;
        const float* Bl = Bh + BFLTS;
        #pragma unroll
        for (int ks = 0; ks < 4; ks++) {
            const int kb = (ks << 3) + q;
            uint32_t ah[2][4], al[2][4];
            #pragma unroll
            for (int mt = 0; mt < 2; mt++) {
                int rb = abase + mt * 16 * AP;
                ah[mt][0] = __float_as_uint(Ah[rb + kb]);
                al[mt][0] = __float_as_uint(Al[rb + kb]);
                ah[mt][1] = __float_as_uint(Ah[rb + 8 * AP + kb]);
                al[mt][1] = __float_as_uint(Al[rb + 8 * AP + kb]);
                ah[mt][2] = __float_as_uint(Ah[rb + kb + 4]);
                al[mt][2] = __float_as_uint(Al[rb + kb + 4]);
                ah[mt][3] = __float_as_uint(Ah[rb + 8 * AP + kb + 4]);
                al[mt][3] = __float_as_uint(Al[rb + 8 * AP + kb + 4]);
            }
            uint32_t bh[4][2], bl[4][2];
            #pragma unroll
            for (int nt = 0; nt < 4; nt++) {
                int rb = bbase + nt * 8 * AP;
                bh[nt][0] = __float_as_uint(Bh[rb + kb]);
                bl[nt][0] = __float_as_uint(Bl[rb + kb]);
                bh[nt][1] = __float_as_uint(Bh[rb + kb + 4]);
                bl[nt][1] = __float_as_uint(Bl[rb + kb + 4]);
            }
            #pragma unroll
            for (int mt = 0; mt < 2; mt++)
                #pragma unroll
                for (int nt = 0; nt < 4; nt++) {
                    mma8(acc[mt][nt], ah[mt], bh[nt]);
                    mma8(acc[mt][nt], al[mt], bh[nt]);
                    mma8(acc[mt][nt], ah[mt], bl[nt]);
                }
        }
        if (it + 1 < iters) sts_tile((it + 1) & 1, it + 1);
    }

    #pragma unroll
    for (int mt = 0; mt < 2; mt++) {
        const int rbase = m0 + warp_m * 32 + mt * 16;
        #pragma unroll
        for (int nt = 0; nt < 4; nt++) {
            const int cl = warp_n * 32 + nt * 8 + 2 * q;
            const int gc = n0 + cl;
            float bb0 = 0.f, bb1 = 0.f;
            if (bias != nullptr) {
                if (gc < Nfull)     bb0 = bias[gc];
                if (gc + 1 < Nfull) bb1 = bias[gc + 1];
            }
            if (!RED) {
                float v0 = acc[mt][nt][0] + bb0, v1 = acc[mt][nt][1] + bb1;
                float v2 = acc[mt][nt][2] + bb0, v3 = acc[mt][nt][3] + bb1;
                if (ACT) { v0 = eluf(v0); v1 = eluf(v1); v2 = eluf(v2); v3 = eluf(v3); }
                float* r0 = Co + (size_t)(rbase + g) * ldc + cofs;
                float* r1 = r0 + (size_t)8 * ldc;
                if (gc < Nfull)     { r0[gc] = v0;     r1[gc] = v2; }
                if (gc + 1 < Nfull) { r0[gc + 1] = v1; r1[gc + 1] = v3; }
            } else {
                #pragma unroll
                for (int half = 0; half < 2; half++) {
                    float v0 = (gc < Nfull)     ? eluf(acc[mt][nt][2 * half + 0] + bb0) : 0.f;
                    float v1 = (gc + 1 < Nfull) ? eluf(acc[mt][nt][2 * half + 1] + bb1) : 0.f;
                    v0 += __shfl_xor_sync(0xffffffffu, v0, 4);
                    v0 += __shfl_xor_sync(0xffffffffu, v0, 8);
                    v1 += __shfl_xor_sync(0xffffffffu, v1, 4);
                    v1 += __shfl_xor_sync(0xffffffffu, v1, 8);
                    if ((lane & 12) == 0) {
                        int p = (rbase + half * 8 + g) >> 2;
                        float* op = Co + (size_t)p * ldc + cofs;
                        float o0 = 0.25f * v0, o1 = 0.25f * v1;
                        if (gc < Nfull)     op[gc] = o0;
                        if (gc + 1 < Nfull) op[gc + 1] = o1;
                        if (Xh2 != nullptr) {
                            __half* oh = Xh2 + (size_t)p * XLD + cofs;
                            if (gc + 1 < Nfull) *(__half2*)(oh + gc) = __floats2half2_rn(o0, o1);
                            else if (gc < Nfull) oh[gc] = __float2half(o0);
                        }
                    }
                }
            }
        }
    }
}

// ============================ fp16 GEMM (post-KNN) =========================
// A: fp32 source -> hi+lo fp16 planes (2-term); fp16 source (INH) -> exact,
// single plane (1-term for dense; gather INH re-splits after elu in fp32).
// B: single fp16 plane. OUTH: write output as fp16 (ldc/cofs in half units).
#define APU 20
#define AHLU (128 * APU)
#define BHLU (64 * APU)
#define SFLU (2 * AHLU + BHLU)     // 6400 u32 per stage
template<int GATHER, int ACT, int RED, int INH, int OUTH>
__global__ void __launch_bounds__(256, 2) hfgemm_k(
    const float* __restrict__ A, int lda, int Kval,
    const float* __restrict__ PQ, int ldpq, int qofs,
    const float* __restrict__ b1, const int* __restrict__ eidx,
    const float* __restrict__ Wt, int Kpad,
    const float* __restrict__ bias,
    float* __restrict__ Co, int ldc, int cofs, int Nfull)
{
    constexpr int ATERMS = (INH && !GATHER) ? 1 : 2;
    extern __shared__ uint32_t smu[];
    const int tid = threadIdx.x;
    const int wid = tid >> 5, lane = tid & 31;
    const int g = lane >> 2, q = lane & 3;
    const int warp_m = wid >> 1, warp_n = wid & 1;
    const int m0 = blockIdx.y * 128;
    const int n0 = blockIdx.x * 64;
    const int iters = Kpad >> 5;

    const int lm = tid >> 3, lkc = (tid & 7) << 2;
    const int luc = (tid & 7) << 1;
    const int lr = tid >> 1, lh = (tid & 1) << 4;
    const int lgu = (tid & 1) << 3;

    const float *Pp = nullptr, *Qp = nullptr;
    const __half *Pph = nullptr, *Qph = nullptr;
    if (GATHER) {
        int mg = m0 + lr;
        if (INH) {
            Pph = (const __half*)PQ + (size_t)(mg >> 2) * ldpq;
            Qph = (const __half*)PQ + (size_t)eidx[mg] * ldpq + qofs;
        } else {
            Pp = PQ + (size_t)(mg >> 2) * ldpq;
            Qp = PQ + (size_t)eidx[mg] * ldpq + qofs;
        }
    }

    float4 rA[4], rQ[4], rB[2];
    uint2 rAh[4];
    uint4 rPh[2], rQh[2];

    auto ldg_tile = [&](int it) {
        const int k0 = it << 5;
        if (GATHER) {
            if (INH) {
                rPh[0] = *(const uint4*)(Pph + k0 + lh);
                rPh[1] = *(const uint4*)(Pph + k0 + lh + 8);
                rQh[0] = *(const uint4*)(Qph + k0 + lh);
                rQh[1] = *(const uint4*)(Qph + k0 + lh + 8);
            } else {
                #pragma unroll
                for (int qq = 0; qq < 4; qq++) {
                    int kk = k0 + lh + (qq << 2);
                    rA[qq] = *(const float4*)(Pp + kk);
                    rQ[qq] = *(const float4*)(Qp + kk);
                }
            }
        } else if (INH) {
            #pragma unroll
            for (int i = 0; i < 4; i++) {
                int gk = k0 + lkc;
                const __half* src = (const __half*)A + (size_t)(m0 + lm + i * 32) * lda + gk;
                if (gk + 3 < Kval) rAh[i] = *(const uint2*)src;
                else               rAh[i] = make_uint2(0u, 0u);
            }
        } else {
            #pragma unroll
            for (int i = 0; i < 4; i++) {
                int gk = k0 + lkc;
                const float* src = A + (size_t)(m0 + lm + i * 32) * lda + gk;
                if (gk + 3 < Kval) {
                    rA[i] = *(const float4*)src;
                } else {
                    rA[i] = make_float4(0.f, 0.f, 0.f, 0.f);
                    if (gk + 0 < Kval) rA[i].x = src[0];
                    if (gk + 1 < Kval) rA[i].y = src[1];
                    if (gk + 2 < Kval) rA[i].z = src[2];
                }
            }
        }
        #pragma unroll
        for (int i = 0; i < 2; i++) {
            int gn = n0 + lm + i * 32;
            if (gn < Nfull) rB[i] = *(const float4*)(Wt + (size_t)gn * Kpad + (it << 5) + lkc);
            else            rB[i] = make_float4(0.f, 0.f, 0.f, 0.f);
        }
    };

    auto sts_tile = [&](int s, int it) {
        uint32_t* Ah = smu + s * SFLU;
        uint32_t* Al = Ah + AHLU;
        uint32_t* Bh = smu + s * SFLU + 2 * AHLU;
        if (GATHER) {
            const int k0 = it << 5;
            if (INH) {
                const uint32_t* pw = (const uint32_t*)rPh;
                const uint32_t* qw = (const uint32_t*)rQh;
                #pragma unroll
                for (int qq = 0; qq < 4; qq++) {
                    int kk = lh + (qq << 2);
                    float4 bv = *(const float4*)(b1 + k0 + kk);
                    float2 p0 = __half22float2(*(const __half2*)&pw[2 * qq]);
                    float2 p1 = __half22float2(*(const __half2*)&pw[2 * qq + 1]);
                    float2 q0 = __half22float2(*(const __half2*)&qw[2 * qq]);
                    float2 q1 = __half22float2(*(const __half2*)&qw[2 * qq + 1]);
                    float v0 = eluf(p0.x + q0.x + bv.x);
                    float v1 = eluf(p0.y + q0.y + bv.y);
                    float v2 = eluf(p1.x + q1.x + bv.z);
                    float v3 = eluf(p1.y + q1.y + bv.w);
                    uint32_t h0, l0, h1, l1;
                    sp_hf(v0, v1, h0, l0);
                    sp_hf(v2, v3, h1, l1);
                    *(uint2*)&Ah[lr * APU + lgu + (qq << 1)] = make_uint2(h0, h1);
                    *(uint2*)&Al[lr * APU + lgu + (qq << 1)] = make_uint2(l0, l1);
                }
            } else {
                #pragma unroll
                for (int qq = 0; qq < 4; qq++) {
                    int kk = lh + (qq << 2);
                    float4 bv = *(const float4*)(b1 + k0 + kk);
                    float v0 = eluf(rA[qq].x + rQ[qq].x + bv.x);
                    float v1 = eluf(rA[qq].y + rQ[qq].y + bv.y);
                    float v2 = eluf(rA[qq].z + rQ[qq].z + bv.z);
                    float v3 = eluf(rA[qq].w + rQ[qq].w + bv.w);
                    uint32_t h0, l0, h1, l1;
                    sp_hf(v0, v1, h0, l0);
                    sp_hf(v2, v3, h1, l1);
                    *(uint2*)&Ah[lr * APU + lgu + (qq << 1)] = make_uint2(h0, h1);
                    *(uint2*)&Al[lr * APU + lgu + (qq << 1)] = make_uint2(l0, l1);
                }
            }
        } else if (INH) {
            #pragma unroll
            for (int i = 0; i < 4; i++)
                *(uint2*)&Ah[(lm + i * 32) * APU + luc] = rAh[i];
        } else {
            #pragma unroll
            for (int i = 0; i < 4; i++) {
                uint32_t h0, l0, h1, l1;
                sp_hf(rA[i].x, rA[i].y, h0, l0);
                sp_hf(rA[i].z, rA[i].w, h1, l1);
                *(uint2*)&Ah[(lm + i * 32) * APU + luc] = make_uint2(h0, h1);
                *(uint2*)&Al[(lm + i * 32) * APU + luc] = make_uint2(l0, l1);
            }
        }
        #pragma unroll
        for (int i = 0; i < 2; i++) {
            uint32_t h0 = hf1(rB[i].x, rB[i].y);
            uint32_t h1 = hf1(rB[i].z, rB[i].w);
            *(uint2*)&Bh[(lm + i * 32) * APU + luc] = make_uint2(h0, h1);
        }
    };

    float acc[2][4][4];
    #pragma unroll
    for (int mt = 0; mt < 2; mt++)
        #pragma unroll
        for (int nt = 0; nt < 4; nt++)
            #pragma unroll
            for (int i = 0; i < 4; i++) acc[mt][nt][i] = 0.f;

    const int abase = (warp_m * 32 + g) * APU;
    const int bbase = (warp_n * 32 + g) * APU;

    ldg_tile(0);
    sts_tile(0, 0);
    for (int it = 0; it < iters; it++) {
        if (it + 1 < iters) ldg_tile(it + 1);
        __syncthreads();
        const int s = it & 1;
        const uint32_t* Ah = smu + s * SFLU;
        const uint32_t* Al = Ah + AHLU;
        const uint32_t* Bh = smu + s * SFLU + 2 * AHLU;
        #pragma unroll
        for (int ks = 0; ks < 2; ks++) {
            const int koff = (ks << 3) + q;
            uint32_t ah[2][4], al[2][4];
            #pragma unroll
            for (int mt = 0; mt < 2; mt++) {
                int rb = abase + mt * 16 * APU;
                ah[mt][0] = Ah[rb + koff];
                ah[mt][1] = Ah[rb + 8 * APU + koff];
                ah[mt][2] = Ah[rb + koff + 4];
                ah[mt][3] = Ah[rb + 8 * APU + koff + 4];
                if (ATERMS == 2) {
                    al[mt][0] = Al[rb + koff];
                    al[mt][1] = Al[rb + 8 * APU + koff];
                    al[mt][2] = Al[rb + koff + 4];
                    al[mt][3] = Al[rb + 8 * APU + koff + 4];
                }
            }
            uint32_t bh[4][2];
            #pragma unroll
            for (int nt = 0; nt < 4; nt++) {
                int rb = bbase + nt * 8 * APU;
                bh[nt][0] = Bh[rb + koff];
                bh[nt][1] = Bh[rb + koff + 4];
            }
            #pragma unroll
            for (int mt = 0; mt < 2; mt++)
                #pragma unroll
                for (int nt = 0; nt < 4; nt++) {
                    mma16h(acc[mt][nt], ah[mt], bh[nt]);
                    if (ATERMS == 2) mma16h(acc[mt][nt], al[mt], bh[nt]);
                }
        }
        if (it + 1 < iters) sts_tile((it + 1) & 1, it + 1);
    }

    #pragma unroll
    for (int mt = 0; mt < 2; mt++) {
        const int rbase = m0 + warp_m * 32 + mt * 16;
        #pragma unroll
        for (int nt = 0; nt < 4; nt++) {
            const int cl = warp_n * 32 + nt * 8 + 2 * q;
            const int gc = n0 + cl;
            float bb0 = 0.f, bb1 = 0.f;
            if (bias != nullptr) {
                if (gc < Nfull)     bb0 = bias[gc];
                if (gc + 1 < Nfull) bb1 = bias[gc + 1];
            }
            if (!RED) {
                float v0 = acc[mt][nt][0] + bb0, v1 = acc[mt][nt][1] + bb1;
                float v2 = acc[mt][nt][2] + bb0, v3 = acc[mt][nt][3] + bb1;
                if (ACT) { v0 = eluf(v0); v1 = eluf(v1); v2 = eluf(v2); v3 = eluf(v3); }
                if (OUTH) {
                    __half* o0 = (__half*)Co + (size_t)(rbase + g) * ldc + cofs;
                    __half* o1 = o0 + (size_t)8 * ldc;
                    if (gc + 1 < Nfull) {
                        *(__half2*)(o0 + gc) = __floats2half2_rn(v0, v1);
                        *(__half2*)(o1 + gc) = __floats2half2_rn(v2, v3);
                    } else if (gc < Nfull) {
                        o0[gc] = __float2half(v0);
                        o1[gc] = __float2half(v2);
                    }
                } else {
                    float* r0 = Co + (size_t)(rbase + g) * ldc + cofs;
                    float* r1 = r0 + (size_t)8 * ldc;
                    if (gc < Nfull)     { r0[gc] = v0;     r1[gc] = v2; }
                    if (gc + 1 < Nfull) { r0[gc + 1] = v1; r1[gc + 1] = v3; }
                }
            } else {
                #pragma unroll
                for (int half = 0; half < 2; half++) {
                    float v0 = (gc < Nfull)     ? eluf(acc[mt][nt][2 * half + 0] + bb0) : 0.f;
                    float v1 = (gc + 1 < Nfull) ? eluf(acc[mt][nt][2 * half + 1] + bb1) : 0.f;
                    v0 += __shfl_xor_sync(0xffffffffu, v0, 4);
                    v0 += __shfl_xor_sync(0xffffffffu, v0, 8);
                    v1 += __shfl_xor_sync(0xffffffffu, v1, 4);
                    v1 += __shfl_xor_sync(0xffffffffu, v1, 8);
                    if ((lane & 12) == 0) {
                        int p = (rbase + half * 8 + g) >> 2;
                        float o0 = 0.25f * v0, o1 = 0.25f * v1;
                        if (OUTH) {
                            __half* op = (__half*)Co + (size_t)p * ldc + cofs;
                            if (gc + 1 < Nfull) *(__half2*)(op + gc) = __floats2half2_rn(o0, o1);
                            else if (gc < Nfull) op[gc] = __float2half(o0);
                        } else {
                            float* op = Co + (size_t)p * ldc + cofs;
                            if (gc < Nfull)     op[gc] = o0;
                            if (gc + 1 < Nfull) op[gc + 1] = o1;
                        }
                    }
                }
            }
        }
    }
}

// ============================ final tiny GEMM ==============================
__global__ void head3_k(const float* __restrict__ H2, const float* __restrict__ w,
                        const float* __restrict__ b, float* __restrict__ out) {
    int gtid = blockIdx.x * blockDim.x + threadIdx.x;
    int warp = gtid >> 5;
    int lane = threadIdx.x & 31;
    if (warp >= NPTS) return;
    const float* hr = H2 + (size_t)warp * 228;
    float a0 = 0.f, a1 = 0.f;
    for (int c = lane; c < 226; c += 32) {
        float h = hr[c];
        a0 += h * w[2 * c];
        a1 += h * w[2 * c + 1];
    }
    #pragma unroll
    for (int o = 16; o; o >>= 1) {
        a0 += __shfl_xor_sync(0xffffffffu, a0, o);
        a1 += __shfl_xor_sync(0xffffffffu, a1, o);
    }
    if (lane == 0) {
        out[2 * warp + 0] = a0 + b[0];
        out[2 * warp + 1] = a1 + b[1];
    }
}

// ============================ launcher =====================================
extern "C" void kernel_launch(void* const* d_in, const int* in_sizes, int n_in,
                              void* d_out, int out_size) {
    const float* coords   = (const float*)d_in[0];
    const float* features = (const float*)d_in[1];
    const float* c1w1 = (const float*)d_in[2];
    const float* c1b1 = (const float*)d_in[3];
    const float* c1w2 = (const float*)d_in[4];
    const float* c1b2 = (const float*)d_in[5];
    const float* c2w1 = (const float*)d_in[6];
    const float* c2b1 = (const float*)d_in[7];
    const float* c2w2 = (const float*)d_in[8];
    const float* c2b2 = (const float*)d_in[9];
    const float* c3w1 = (const float*)d_in[10];
    const float* c3b1 = (const float*)d_in[11];
    const float* c3w2 = (const float*)d_in[12];
    const float* c3b2 = (const float*)d_in[13];
    const float* ow1  = (const float*)d_in[14];
    const float* ob1  = (const float*)d_in[15];
    const float* ow2  = (const float*)d_in[16];
    const float* ob2  = (const float*)d_in[17];
    const float* ow3  = (const float*)d_in[18];
    const float* ob3  = (const float*)d_in[19];

    float *pX, *pPQ, *pH1, *pWt; int* pidx; __half* pXh;
    cudaGetSymbolAddress((void**)&pX,  g_X453);
    cudaGetSymbolAddress((void**)&pXh, g_Xh);
    cudaGetSymbolAddress((void**)&pPQ, g_PQ);
    cudaGetSymbolAddress((void**)&pH1, g_H1);
    cudaGetSymbolAddress((void**)&pWt, g_Wt);
    cudaGetSymbolAddress((void**)&pidx, g_idx);

    const int SMEM_TF = 2 * SFL * 4;    // 110,592 B
    const int SMEM_HF = 2 * SFLU * 4;   // 51,200 B
    cudaFuncSetAttribute(tfgemm_k<0, 0, 0>, cudaFuncAttributeMaxDynamicSharedMemorySize, SMEM_TF);
    cudaFuncSetAttribute(tfgemm_k<1, 1, 1>, cudaFuncAttributeMaxDynamicSharedMemorySize, SMEM_TF);
    cudaFuncSetAttribute(hfgemm_k<0, 0, 0, 1, 1>, cudaFuncAttributeMaxDynamicSharedMemorySize, SMEM_HF);
    cudaFuncSetAttribute(hfgemm_k<1, 1, 1, 1, 1>, cudaFuncAttributeMaxDynamicSharedMemorySize, SMEM_HF);
    cudaFuncSetAttribute(hfgemm_k<0, 1, 0, 1, 1>, cudaFuncAttributeMaxDynamicSharedMemorySize, SMEM_HF);
    cudaFuncSetAttribute(hfgemm_k<0, 1, 0, 1, 0>, cudaFuncAttributeMaxDynamicSharedMemorySize, SMEM_HF);

    const int MT_P = NPTS / 128;   // 1024
    const int MT_E = NEDG / 128;   // 4096

    copy_features_k<<<(NPTS * 5 + 255) / 256, 256>>>(features, pX, pXh);

    // ===== EdgeConv 1 (C=5, H=32, O=64) — feeds knn2: tf32 3-term (FROZEN) =====
    knn_k<2, 4><<<512, 256>>>(coords, 2, 0, pidx);
    prep_pq_k<<<(64 * 32 + 255) / 256, 256>>>(c1w1, pWt, 5, 32, 32);
    tfgemm_k<0, 0, 0><<<dim3(1, MT_P), 256, SMEM_TF>>>(pX, XLD, 5, nullptr, 0, 0, nullptr, nullptr,
                                                       pWt, 32, nullptr, pPQ, 64, 0, 64, nullptr);
    prep_wt_k<<<(64 * 32 + 255) / 256, 256>>>(c1w2, pWt, 32, 64, 32);
    tfgemm_k<1, 1, 1><<<dim3(1, MT_E), 256, SMEM_TF>>>(nullptr, 0, 32, pPQ, 64, 32, c1b1, pidx,
                                                       pWt, 32, c1b2, pX, XLD, O1_OFS, 64, pXh);

    // ===== EdgeConv 2 (C=64, H=96, O=128) — feeds knn3: tf32 3-term (FROZEN) =====
    knn_k<64, 64><<<512, 256>>>(pX, XLD, O1_OFS, pidx);
    prep_pq_k<<<(192 * 64 + 255) / 256, 256>>>(c2w1, pWt, 64, 96, 64);
    tfgemm_k<0, 0, 0><<<dim3(3, MT_P), 256, SMEM_TF>>>(pX + O1_OFS, XLD, 64, nullptr, 0, 0, nullptr, nullptr,
                                                       pWt, 64, nullptr, pPQ, 192, 0, 192, nullptr);
    prep_wt_k<<<(128 * 96 + 255) / 256, 256>>>(c2w2, pWt, 96, 128, 96);
    tfgemm_k<1, 1, 1><<<dim3(2, MT_E), 256, SMEM_TF>>>(nullptr, 0, 96, pPQ, 192, 96, c2b1, pidx,
                                                       pWt, 96, c2b2, pX, XLD, O2_OFS, 128, pXh);

    // ===== EdgeConv 3 — post-KNN: fp16; PQ3 from Xh (1-term); out3 fp16-only =====
    knn_k<128, 128><<<512, 256>>>(pX, XLD, O2_OFS, pidx);
    prep_pq_k<<<(384 * 128 + 255) / 256, 256>>>(c3w1, pWt, 128, 192, 128);
    hfgemm_k<0, 0, 0, 1, 1><<<dim3(6, MT_P), 256, SMEM_HF>>>((const float*)(pXh + O2_OFS), XLD, 128,
                                                             nullptr, 0, 0, nullptr, nullptr,
                                                             pWt, 128, nullptr, pPQ, 384, 0, 384);
    prep_wt_k<<<(256 * 192 + 255) / 256, 256>>>(c3w2, pWt, 192, 256, 192);
    hfgemm_k<1, 1, 1, 1, 1><<<dim3(4, MT_E), 256, SMEM_HF>>>(nullptr, 0, 192, pPQ, 384, 192, c3b1, pidx,
                                                             pWt, 192, c3b2, (float*)pXh, XLD, O3_OFS, 256);

    // ===== Head — A from Xh (fp16 exact, 1-term); H1 fp16 =====
    prep_head_k<<<(453 * 480 + 255) / 256, 256>>>(ow1, pWt, 453, 480);
    hfgemm_k<0, 1, 0, 1, 1><<<dim3(8, MT_P), 256, SMEM_HF>>>((const float*)pXh, XLD, 456,
                                                             nullptr, 0, 0, nullptr, nullptr,
                                                             pWt, 480, ob1, pH1, 456, 0, 453);
    prep_wt_k<<<(226 * 480 + 255) / 256, 256>>>(ow2, pWt, 453, 226, 480);
    hfgemm_k<0, 1, 0, 1, 0><<<dim3(4, MT_P), 256, SMEM_HF>>>(pH1, 456, 456, nullptr, 0, 0, nullptr, nullptr,
                                                             pWt, 480, ob2, pPQ, 228, 0, 226);
    head3_k<<<(NPTS * 32) / 256, 256>>>(pPQ, ow3, ob3, (float*)d_out);
}

// round 12
// speedup vs baseline: 1.2356x; 1.0444x over previous
#include <cuda_runtime.h>
#include <cuda_fp16.h>
#include <cstdint>
#include <math.h>

// ============================ problem constants ============================
#define NPTS 131072          // B*N = 1024*128
#define NEDG 524288          // NPTS * K(=4)

// Concat buffer layout (all segment starts 16B-aligned; pads never written => 0)
#define F_OFS  0
#define O1_OFS 8
#define O2_OFS 72
#define O3_OFS 200
#define XLD    456

// ============================ device scratch ===============================
__device__ float  g_X453[(size_t)NPTS * XLD];   // fp32 concat (KNN reads)
__device__ __half g_Xh[(size_t)NPTS * XLD];     // fp16 mirror (post-KNN A source)
__device__ float  g_PQ[(size_t)NPTS * 384];     // fp32 PQ1/PQ2; fp16 PQ3; fp32 H2 (ld 228)
__device__ float  g_H1[(size_t)NPTS * 456];     // fp16 H1 (ld 456 halves)
__device__ int    g_idx[NPTS * 4];
__device__ float  g_Wt[512 * 480];

__device__ __forceinline__ float eluf(float x) { return x > 0.f ? x : expm1f(x); }

// ============================ small helpers ================================
__device__ __forceinline__ void sp_hf(float a0, float a1, uint32_t& h, uint32_t& l) {
    __half2 hh = __floats2half2_rn(a0, a1);
    float r0 = a0 - __half2float(__low2half(hh));
    float r1 = a1 - __half2float(__high2half(hh));
    __half2 ll = __floats2half2_rn(r0, r1);
    h = *reinterpret_cast<uint32_t*>(&hh);
    l = *reinterpret_cast<uint32_t*>(&ll);
}
__device__ __forceinline__ uint32_t hf1(float a0, float a1) {
    __half2 hh = __floats2half2_rn(a0, a1);
    return *reinterpret_cast<uint32_t*>(&hh);
}
__device__ __forceinline__ void mma16h(float* c, const uint32_t* a, const uint32_t* b) {
    asm volatile("mma.sync.aligned.m16n8k16.row.col.f32.f16.f16.f32 "
                 "{%0,%1,%2,%3}, {%4,%5,%6,%7}, {%8,%9}, {%0,%1,%2,%3};"
                 : "+f"(c[0]), "+f"(c[1]), "+f"(c[2]), "+f"(c[3])
                 : "r"(a[0]), "r"(a[1]), "r"(a[2]), "r"(a[3]), "r"(b[0]), "r"(b[1]));
}

// ============================ elementwise helpers ==========================
__global__ void copy_features_k(const float* __restrict__ f, float* __restrict__ X,
                                __half* __restrict__ Xh) {
    int e = blockIdx.x * blockDim.x + threadIdx.x;
    if (e < NPTS * 5) {
        int r = e / 5, c = e % 5;
        X[(size_t)r * XLD + c] = f[e];
        Xh[(size_t)r * XLD + c] = __float2half(f[e]);
    }
}
__global__ void prep_pq_k(const float* __restrict__ w1, float* __restrict__ wt, int C, int H, int Kpad) {
    int e = blockIdx.x * blockDim.x + threadIdx.x;
    if (e >= 2 * H * Kpad) return;
    int n = e / Kpad, k = e % Kpad;
    float v = 0.f;
    if (k < C) v = (n < H) ? (w1[k * H + n] - w1[(C + k) * H + n]) : w1[(C + k) * H + (n - H)];
    wt[(size_t)n * Kpad + k] = v;
}
__global__ void prep_wt_k(const float* __restrict__ w, float* __restrict__ wt, int K, int N, int Kpad) {
    int e = blockIdx.x * blockDim.x + threadIdx.x;
    if (e >= N * Kpad) return;
    int n = e / Kpad, k = e % Kpad;
    wt[(size_t)n * Kpad + k] = (k < K) ? w[(size_t)k * N + n] : 0.f;
}
__global__ void prep_head_k(const float* __restrict__ w, float* __restrict__ wt, int N, int Kpad) {
    int e = blockIdx.x * blockDim.x + threadIdx.x;
    if (e >= N * Kpad) return;
    int n = e / Kpad, kp = e % Kpad;
    float v = 0.f;
    if (kp < 5)                   v = w[(size_t)kp * N + n];
    else if (kp >= 8 && kp < 456) v = w[(size_t)(kp - 3) * N + n];
    wt[(size_t)n * Kpad + kp] = v;
}

// ============================ KNN (k=4; 2 batches per block; FROZEN) =======
template<int C, int CP>
__global__ void __launch_bounds__(256) knn_k(const float* __restrict__ x, int ld, int cofs,
                                             int* __restrict__ idxout) {
    constexpr int PAD = CP + 4;
    __shared__ __align__(16) float sx[2][32][PAD];
    __shared__ float sn[2][128];
    int half = threadIdx.x >> 7;
    int tid = threadIdx.x & 127;
    int b = blockIdx.x * 2 + half;
    const float* xb = x + (size_t)b * 128 * ld + cofs;
    float4 xi[CP / 4];

    for (int t = 0; t < 4; t++) {
        for (int e = tid; e < 32 * CP; e += 128) {
            int r = e / CP, c = e % CP;
            sx[half][r][c] = (c < C) ? xb[(size_t)(t * 32 + r) * ld + c] : 0.f;
        }
        __syncthreads();
        if ((tid >> 5) == t) {
            int r = tid & 31;
            #pragma unroll
            for (int c4 = 0; c4 < CP / 4; c4++) xi[c4] = *(const float4*)&sx[half][r][4 * c4];
        }
        __syncthreads();
    }
    float ni = 0.f;
    #pragma unroll
    for (int c4 = 0; c4 < CP / 4; c4++)
        ni += xi[c4].x * xi[c4].x + xi[c4].y * xi[c4].y + xi[c4].z * xi[c4].z + xi[c4].w * xi[c4].w;
    sn[half][tid] = ni;
    __syncthreads();

    float bd0 = 1e30f, bd1 = 1e30f, bd2 = 1e30f, bd3 = 1e30f;
    int   bi0 = 0,     bi1 = 0,     bi2 = 0,     bi3 = 0;

    for (int t = 0; t < 4; t++) {
        for (int e = tid; e < 32 * CP; e += 128) {
            int r = e / CP, c = e % CP;
            sx[half][r][c] = (c < C) ? xb[(size_t)(t * 32 + r) * ld + c] : 0.f;
        }
        __syncthreads();
        for (int jl = 0; jl < 32; jl++) {
            int j = t * 32 + jl;
            float dot = 0.f;
            #pragma unroll
            for (int c4 = 0; c4 < CP / 4; c4++) {
                float4 xj = *(const float4*)&sx[half][jl][4 * c4];
                dot += xi[c4].x * xj.x + xi[c4].y * xj.y + xi[c4].z * xj.z + xi[c4].w * xj.w;
            }
            float d = ni + sn[half][j] - 2.f * dot;
            if (j == tid) d = 1e30f;
            if (d < bd3) {
                if (d < bd2) {
                    bd3 = bd2; bi3 = bi2;
                    if (d < bd1) {
                        bd2 = bd1; bi2 = bi1;
                        if (d < bd0) { bd1 = bd0; bi1 = bi0; bd0 = d; bi0 = j; }
                        else         { bd1 = d; bi1 = j; }
                    } else { bd2 = d; bi2 = j; }
                } else { bd3 = d; bi3 = j; }
            }
        }
        __syncthreads();
    }
    int base = (b * 128 + tid) * 4;
    int gb = b * 128;
    idxout[base + 0] = gb + bi0;
    idxout[base + 1] = gb + bi1;
    idxout[base + 2] = gb + bi2;
    idxout[base + 3] = gb + bi3;
}

// ============================ fp16 GEMM (unified) ==========================
// A: fp32 source -> hi+lo fp16 planes; fp16 source (INH, dense) -> exact 1 plane.
// B: B3=1 -> hi+lo planes (3-term: ah*bh + al*bh + ah*bl, err ~2^-22);
//    B3=0 -> single plane (2-term / 1-term).
// OUTH: fp16 output (ldc/cofs in half units). Xh2: fp16 mirror for RED fp32 out.
#define APU 20
#define AHLU (128 * APU)
#define BHLU (64 * APU)
template<int GATHER, int ACT, int RED, int INH, int OUTH, int B3>
__global__ void __launch_bounds__(256, 2) hfgemm_k(
    const float* __restrict__ A, int lda, int Kval,
    const float* __restrict__ PQ, int ldpq, int qofs,
    const float* __restrict__ b1, const int* __restrict__ eidx,
    const float* __restrict__ Wt, int Kpad,
    const float* __restrict__ bias,
    float* __restrict__ Co, int ldc, int cofs, int Nfull,
    __half* __restrict__ Xh2)
{
    constexpr int ATERMS = (INH && !GATHER) ? 1 : 2;
    constexpr int STGU = 2 * AHLU + (B3 ? 2 : 1) * BHLU;
    extern __shared__ uint32_t smu[];
    const int tid = threadIdx.x;
    const int wid = tid >> 5, lane = tid & 31;
    const int g = lane >> 2, q = lane & 3;
    const int warp_m = wid >> 1, warp_n = wid & 1;
    const int m0 = blockIdx.y * 128;
    const int n0 = blockIdx.x * 64;
    const int iters = Kpad >> 5;

    const int lm = tid >> 3, lkc = (tid & 7) << 2;
    const int luc = (tid & 7) << 1;
    const int lr = tid >> 1, lh = (tid & 1) << 4;
    const int lgu = (tid & 1) << 3;

    const float *Pp = nullptr, *Qp = nullptr;
    const __half *Pph = nullptr, *Qph = nullptr;
    if (GATHER) {
        int mg = m0 + lr;
        if (INH) {
            Pph = (const __half*)PQ + (size_t)(mg >> 2) * ldpq;
            Qph = (const __half*)PQ + (size_t)eidx[mg] * ldpq + qofs;
        } else {
            Pp = PQ + (size_t)(mg >> 2) * ldpq;
            Qp = PQ + (size_t)eidx[mg] * ldpq + qofs;
        }
    }

    float4 rA[4], rQ[4], rB[2];
    uint2 rAh[4];
    uint4 rPh[2], rQh[2];

    auto ldg_tile = [&](int it) {
        const int k0 = it << 5;
        if (GATHER) {
            if (INH) {
                rPh[0] = *(const uint4*)(Pph + k0 + lh);
                rPh[1] = *(const uint4*)(Pph + k0 + lh + 8);
                rQh[0] = *(const uint4*)(Qph + k0 + lh);
                rQh[1] = *(const uint4*)(Qph + k0 + lh + 8);
            } else {
                #pragma unroll
                for (int qq = 0; qq < 4; qq++) {
                    int kk = k0 + lh + (qq << 2);
                    rA[qq] = *(const float4*)(Pp + kk);
                    rQ[qq] = *(const float4*)(Qp + kk);
                }
            }
        } else if (INH) {
            #pragma unroll
            for (int i = 0; i < 4; i++) {
                int gk = k0 + lkc;
                const __half* src = (const __half*)A + (size_t)(m0 + lm + i * 32) * lda + gk;
                if (gk + 3 < Kval) rAh[i] = *(const uint2*)src;
                else               rAh[i] = make_uint2(0u, 0u);
            }
        } else {
            #pragma unroll
            for (int i = 0; i < 4; i++) {
                int gk = k0 + lkc;
                const float* src = A + (size_t)(m0 + lm + i * 32) * lda + gk;
                if (gk + 3 < Kval) {
                    rA[i] = *(const float4*)src;
                } else {
                    rA[i] = make_float4(0.f, 0.f, 0.f, 0.f);
                    if (gk + 0 < Kval) rA[i].x = src[0];
                    if (gk + 1 < Kval) rA[i].y = src[1];
                    if (gk + 2 < Kval) rA[i].z = src[2];
                }
            }
        }
        #pragma unroll
        for (int i = 0; i < 2; i++) {
            int gn = n0 + lm + i * 32;
            if (gn < Nfull) rB[i] = *(const float4*)(Wt + (size_t)gn * Kpad + (it << 5) + lkc);
            else            rB[i] = make_float4(0.f, 0.f, 0.f, 0.f);
        }
    };

    auto sts_tile = [&](int s, int it) {
        uint32_t* Ah = smu + s * STGU;
        uint32_t* Al = Ah + AHLU;
        uint32_t* Bh = smu + s * STGU + 2 * AHLU;
        uint32_t* Bl = Bh + BHLU;
        if (GATHER) {
            const int k0 = it << 5;
            if (INH) {
                const uint32_t* pw = (const uint32_t*)rPh;
                const uint32_t* qw = (const uint32_t*)rQh;
                #pragma unroll
                for (int qq = 0; qq < 4; qq++) {
                    int kk = lh + (qq << 2);
                    float4 bv = *(const float4*)(b1 + k0 + kk);
                    float2 p0 = __half22float2(*(const __half2*)&pw[2 * qq]);
                    float2 p1 = __half22float2(*(const __half2*)&pw[2 * qq + 1]);
                    float2 q0 = __half22float2(*(const __half2*)&qw[2 * qq]);
                    float2 q1 = __half22float2(*(const __half2*)&qw[2 * qq + 1]);
                    float v0 = eluf(p0.x + q0.x + bv.x);
                    float v1 = eluf(p0.y + q0.y + bv.y);
                    float v2 = eluf(p1.x + q1.x + bv.z);
                    float v3 = eluf(p1.y + q1.y + bv.w);
                    uint32_t h0, l0, h1, l1;
                    sp_hf(v0, v1, h0, l0);
                    sp_hf(v2, v3, h1, l1);
                    *(uint2*)&Ah[lr * APU + lgu + (qq << 1)] = make_uint2(h0, h1);
                    *(uint2*)&Al[lr * APU + lgu + (qq << 1)] = make_uint2(l0, l1);
                }
            } else {
                #pragma unroll
                for (int qq = 0; qq < 4; qq++) {
                    int kk = lh + (qq << 2);
                    float4 bv = *(const float4*)(b1 + k0 + kk);
                    float v0 = eluf(rA[qq].x + rQ[qq].x + bv.x);
                    float v1 = eluf(rA[qq].y + rQ[qq].y + bv.y);
                    float v2 = eluf(rA[qq].z + rQ[qq].z + bv.z);
                    float v3 = eluf(rA[qq].w + rQ[qq].w + bv.w);
                    uint32_t h0, l0, h1, l1;
                    sp_hf(v0, v1, h0, l0);
                    sp_hf(v2, v3, h1, l1);
                    *(uint2*)&Ah[lr * APU + lgu + (qq << 1)] = make_uint2(h0, h1);
                    *(uint2*)&Al[lr * APU + lgu + (qq << 1)] = make_uint2(l0, l1);
                }
            }
        } else if (INH) {
            #pragma unroll
            for (int i = 0; i < 4; i++)
                *(uint2*)&Ah[(lm + i * 32) * APU + luc] = rAh[i];
        } else {
            #pragma unroll
            for (int i = 0; i < 4; i++) {
                uint32_t h0, l0, h1, l1;
                sp_hf(rA[i].x, rA[i].y, h0, l0);
                sp_hf(rA[i].z, rA[i].w, h1, l1);
                *(uint2*)&Ah[(lm + i * 32) * APU + luc] = make_uint2(h0, h1);
                *(uint2*)&Al[(lm + i * 32) * APU + luc] = make_uint2(l0, l1);
            }
        }
        #pragma unroll
        for (int i = 0; i < 2; i++) {
            if (B3) {
                uint32_t h0, l0, h1, l1;
                sp_hf(rB[i].x, rB[i].y, h0, l0);
                sp_hf(rB[i].z, rB[i].w, h1, l1);
                *(uint2*)&Bh[(lm + i * 32) * APU + luc] = make_uint2(h0, h1);
                *(uint2*)&Bl[(lm + i * 32) * APU + luc] = make_uint2(l0, l1);
            } else {
                uint32_t h0 = hf1(rB[i].x, rB[i].y);
                uint32_t h1 = hf1(rB[i].z, rB[i].w);
                *(uint2*)&Bh[(lm + i * 32) * APU + luc] = make_uint2(h0, h1);
            }
        }
    };

    float acc[2][4][4];
    #pragma unroll
    for (int mt = 0; mt < 2; mt++)
        #pragma unroll
        for (int nt = 0; nt < 4; nt++)
            #pragma unroll
            for (int i = 0; i < 4; i++) acc[mt][nt][i] = 0.f;

    const int abase = (warp_m * 32 + g) * APU;
    const int bbase = (warp_n * 32 + g) * APU;

    ldg_tile(0);
    sts_tile(0, 0);
    for (int it = 0; it < iters; it++) {
        if (it + 1 < iters) ldg_tile(it + 1);
        __syncthreads();
        const int s = it & 1;
        const uint32_t* Ah = smu + s * STGU;
        const uint32_t* Al = Ah + AHLU;
        const uint32_t* Bh = smu + s * STGU + 2 * AHLU;
        const uint32_t* Bl = Bh + BHLU;
        #pragma unroll
        for (int ks = 0; ks < 2; ks++) {
            const int koff = (ks << 3) + q;
            uint32_t ah[2][4], al[2][4];
            #pragma unroll
            for (int mt = 0; mt < 2; mt++) {
                int rb = abase + mt * 16 * APU;
                ah[mt][0] = Ah[rb + koff];
                ah[mt][1] = Ah[rb + 8 * APU + koff];
                ah[mt][2] = Ah[rb + koff + 4];
                ah[mt][3] = Ah[rb + 8 * APU + koff + 4];
                if (ATERMS == 2) {
                    al[mt][0] = Al[rb + koff];
                    al[mt][1] = Al[rb + 8 * APU + koff];
                    al[mt][2] = Al[rb + koff + 4];
                    al[mt][3] = Al[rb + 8 * APU + koff + 4];
                }
            }
            uint32_t bh[4][2], bl[4][2];
            #pragma unroll
            for (int nt = 0; nt < 4; nt++) {
                int rb = bbase + nt * 8 * APU;
                bh[nt][0] = Bh[rb + koff];
                bh[nt][1] = Bh[rb + koff + 4];
                if (B3) {
                    bl[nt][0] = Bl[rb + koff];
                    bl[nt][1] = Bl[rb + koff + 4];
                }
            }
            #pragma unroll
            for (int mt = 0; mt < 2; mt++)
                #pragma unroll
                for (int nt = 0; nt < 4; nt++) {
                    mma16h(acc[mt][nt], ah[mt], bh[nt]);
                    if (ATERMS == 2) mma16h(acc[mt][nt], al[mt], bh[nt]);
                    if (B3) mma16h(acc[mt][nt], ah[mt], bl[nt]);
                }
        }
        if (it + 1 < iters) sts_tile((it + 1) & 1, it + 1);
    }

    #pragma unroll
    for (int mt = 0; mt < 2; mt++) {
        const int rbase = m0 + warp_m * 32 + mt * 16;
        #pragma unroll
        for (int nt = 0; nt < 4; nt++) {
            const int cl = warp_n * 32 + nt * 8 + 2 * q;
            const int gc = n0 + cl;
            float bb0 = 0.f, bb1 = 0.f;
            if (bias != nullptr) {
                if (gc < Nfull)     bb0 = bias[gc];
                if (gc + 1 < Nfull) bb1 = bias[gc + 1];
            }
            if (!RED) {
                float v0 = acc[mt][nt][0] + bb0, v1 = acc[mt][nt][1] + bb1;
                float v2 = acc[mt][nt][2] + bb0, v3 = acc[mt][nt][3] + bb1;
                if (ACT) { v0 = eluf(v0); v1 = eluf(v1); v2 = eluf(v2); v3 = eluf(v3); }
                if (OUTH) {
                    __half* o0 = (__half*)Co + (size_t)(rbase + g) * ldc + cofs;
                    __half* o1 = o0 + (size_t)8 * ldc;
                    if (gc + 1 < Nfull) {
                        *(__half2*)(o0 + gc) = __floats2half2_rn(v0, v1);
                        *(__half2*)(o1 + gc) = __floats2half2_rn(v2, v3);
                    } else if (gc < Nfull) {
                        o0[gc] = __float2half(v0);
                        o1[gc] = __float2half(v2);
                    }
                } else {
                    float* r0 = Co + (size_t)(rbase + g) * ldc + cofs;
                    float* r1 = r0 + (size_t)8 * ldc;
                    if (gc < Nfull)     { r0[gc] = v0;     r1[gc] = v2; }
                    if (gc + 1 < Nfull) { r0[gc + 1] = v1; r1[gc + 1] = v3; }
                }
            } else {
                #pragma unroll
                for (int half = 0; half < 2; half++) {
                    float v0 = (gc < Nfull)     ? eluf(acc[mt][nt][2 * half + 0] + bb0) : 0.f;
                    float v1 = (gc + 1 < Nfull) ? eluf(acc[mt][nt][2 * half + 1] + bb1) : 0.f;
                    v0 += __shfl_xor_sync(0xffffffffu, v0, 4);
                    v0 += __shfl_xor_sync(0xffffffffu, v0, 8);
                    v1 += __shfl_xor_sync(0xffffffffu, v1, 4);
                    v1 += __shfl_xor_sync(0xffffffffu, v1, 8);
                    if ((lane & 12) == 0) {
                        int p = (rbase + half * 8 + g) >> 2;
                        float o0 = 0.25f * v0, o1 = 0.25f * v1;
                        if (OUTH) {
                            __half* op = (__half*)Co + (size_t)p * ldc + cofs;
                            if (gc + 1 < Nfull) *(__half2*)(op + gc) = __floats2half2_rn(o0, o1);
                            else if (gc < Nfull) op[gc] = __float2half(o0);
                        } else {
                            float* op = Co + (size_t)p * ldc + cofs;
                            if (gc < Nfull)     op[gc] = o0;
                            if (gc + 1 < Nfull) op[gc + 1] = o1;
                            if (Xh2 != nullptr) {
                                __half* oh = Xh2 + (size_t)p * XLD + cofs;
                                if (gc + 1 < Nfull) *(__half2*)(oh + gc) = __floats2half2_rn(o0, o1);
                                else if (gc < Nfull) oh[gc] = __float2half(o0);
                            }
                        }
                    }
                }
            }
        }
    }
}

// ============================ final tiny GEMM ==============================
__global__ void head3_k(const float* __restrict__ H2, const float* __restrict__ w,
                        const float* __restrict__ b, float* __restrict__ out) {
    int gtid = blockIdx.x * blockDim.x + threadIdx.x;
    int warp = gtid >> 5;
    int lane = threadIdx.x & 31;
    if (warp >= NPTS) return;
    const float* hr = H2 + (size_t)warp * 228;
    float a0 = 0.f, a1 = 0.f;
    for (int c = lane; c < 226; c += 32) {
        float h = hr[c];
        a0 += h * w[2 * c];
        a1 += h * w[2 * c + 1];
    }
    #pragma unroll
    for (int o = 16; o; o >>= 1) {
        a0 += __shfl_xor_sync(0xffffffffu, a0, o);
        a1 += __shfl_xor_sync(0xffffffffu, a1, o);
    }
    if (lane == 0) {
        out[2 * warp + 0] = a0 + b[0];
        out[2 * warp + 1] = a1 + b[1];
    }
}

// ============================ launcher =====================================
extern "C" void kernel_launch(void* const* d_in, const int* in_sizes, int n_in,
                              void* d_out, int out_size) {
    const float* coords   = (const float*)d_in[0];
    const float* features = (const float*)d_in[1];
    const float* c1w1 = (const float*)d_in[2];
    const float* c1b1 = (const float*)d_in[3];
    const float* c1w2 = (const float*)d_in[4];
    const float* c1b2 = (const float*)d_in[5];
    const float* c2w1 = (const float*)d_in[6];
    const float* c2b1 = (const float*)d_in[7];
    const float* c2w2 = (const float*)d_in[8];
    const float* c2b2 = (const float*)d_in[9];
    const float* c3w1 = (const float*)d_in[10];
    const float* c3b1 = (const float*)d_in[11];
    const float* c3w2 = (const float*)d_in[12];
    const float* c3b2 = (const float*)d_in[13];
    const float* ow1  = (const float*)d_in[14];
    const float* ob1  = (const float*)d_in[15];
    const float* ow2  = (const float*)d_in[16];
    const float* ob2  = (const float*)d_in[17];
    const float* ow3  = (const float*)d_in[18];
    const float* ob3  = (const float*)d_in[19];

    float *pX, *pPQ, *pH1, *pWt; int* pidx; __half* pXh;
    cudaGetSymbolAddress((void**)&pX,  g_X453);
    cudaGetSymbolAddress((void**)&pXh, g_Xh);
    cudaGetSymbolAddress((void**)&pPQ, g_PQ);
    cudaGetSymbolAddress((void**)&pH1, g_H1);
    cudaGetSymbolAddress((void**)&pWt, g_Wt);
    cudaGetSymbolAddress((void**)&pidx, g_idx);

    const int SMEM_3 = 2 * (2 * AHLU + 2 * BHLU) * 4;   // 61,440 B
    const int SMEM_2 = 2 * (2 * AHLU + 1 * BHLU) * 4;   // 51,200 B
    cudaFuncSetAttribute(hfgemm_k<0, 0, 0, 0, 0, 1>, cudaFuncAttributeMaxDynamicSharedMemorySize, SMEM_3);
    cudaFuncSetAttribute(hfgemm_k<1, 1, 1, 0, 0, 1>, cudaFuncAttributeMaxDynamicSharedMemorySize, SMEM_3);
    cudaFuncSetAttribute(hfgemm_k<0, 0, 0, 1, 1, 0>, cudaFuncAttributeMaxDynamicSharedMemorySize, SMEM_2);
    cudaFuncSetAttribute(hfgemm_k<1, 1, 1, 1, 1, 0>, cudaFuncAttributeMaxDynamicSharedMemorySize, SMEM_2);
    cudaFuncSetAttribute(hfgemm_k<0, 1, 0, 1, 1, 0>, cudaFuncAttributeMaxDynamicSharedMemorySize, SMEM_2);
    cudaFuncSetAttribute(hfgemm_k<0, 1, 0, 1, 0, 0>, cudaFuncAttributeMaxDynamicSharedMemorySize, SMEM_2);

    const int MT_P = NPTS / 128;   // 1024
    const int MT_E = NEDG / 128;   // 4096

    copy_features_k<<<(NPTS * 5 + 255) / 256, 256>>>(features, pX, pXh);

    // ===== EdgeConv 1 (C=5, H=32, O=64) — feeds knn2: fp16 3-term =====
    knn_k<2, 4><<<512, 256>>>(coords, 2, 0, pidx);
    prep_pq_k<<<(64 * 32 + 255) / 256, 256>>>(c1w1, pWt, 5, 32, 32);
    hfgemm_k<0, 0, 0, 0, 0, 1><<<dim3(1, MT_P), 256, SMEM_3>>>(pX, XLD, 5, nullptr, 0, 0, nullptr, nullptr,
                                                               pWt, 32, nullptr, pPQ, 64, 0, 64, nullptr);
    prep_wt_k<<<(64 * 32 + 255) / 256, 256>>>(c1w2, pWt, 32, 64, 32);
    hfgemm_k<1, 1, 1, 0, 0, 1><<<dim3(1, MT_E), 256, SMEM_3>>>(nullptr, 0, 32, pPQ, 64, 32, c1b1, pidx,
                                                               pWt, 32, c1b2, pX, XLD, O1_OFS, 64, pXh);

    // ===== EdgeConv 2 (C=64, H=96, O=128) — feeds knn3: fp16 3-term =====
    knn_k<64, 64><<<512, 256>>>(pX, XLD, O1_OFS, pidx);
    prep_pq_k<<<(192 * 64 + 255) / 256, 256>>>(c2w1, pWt, 64, 96, 64);
    hfgemm_k<0, 0, 0, 0, 0, 1><<<dim3(3, MT_P), 256, SMEM_3>>>(pX + O1_OFS, XLD, 64, nullptr, 0, 0, nullptr, nullptr,
                                                               pWt, 64, nullptr, pPQ, 192, 0, 192, nullptr);
    prep_wt_k<<<(128 * 96 + 255) / 256, 256>>>(c2w2, pWt, 96, 128, 96);
    hfgemm_k<1, 1, 1, 0, 0, 1><<<dim3(2, MT_E), 256, SMEM_3>>>(nullptr, 0, 96, pPQ, 192, 96, c2b1, pidx,
                                                               pWt, 96, c2b2, pX, XLD, O2_OFS, 128, pXh);

    // ===== EdgeConv 3 — post-KNN: fp16; PQ3 from Xh (1-term); out3 fp16-only =====
    knn_k<128, 128><<<512, 256>>>(pX, XLD, O2_OFS, pidx);
    prep_pq_k<<<(384 * 128 + 255) / 256, 256>>>(c3w1, pWt, 128, 192, 128);
    hfgemm_k<0, 0, 0, 1, 1, 0><<<dim3(6, MT_P), 256, SMEM_2>>>((const float*)(pXh + O2_OFS), XLD, 128,
                                                               nullptr, 0, 0, nullptr, nullptr,
                                                               pWt, 128, nullptr, pPQ, 384, 0, 384, nullptr);
    prep_wt_k<<<(256 * 192 + 255) / 256, 256>>>(c3w2, pWt, 192, 256, 192);
    hfgemm_k<1, 1, 1, 1, 1, 0><<<dim3(4, MT_E), 256, SMEM_2>>>(nullptr, 0, 192, pPQ, 384, 192, c3b1, pidx,
                                                               pWt, 192, c3b2, (float*)pXh, XLD, O3_OFS, 256, nullptr);

    // ===== Head — A from Xh (fp16 exact, 1-term); H1 fp16 =====
    prep_head_k<<<(453 * 480 + 255) / 256, 256>>>(ow1, pWt, 453, 480);
    hfgemm_k<0, 1, 0, 1, 1, 0><<<dim3(8, MT_P), 256, SMEM_2>>>((const float*)pXh, XLD, 456,
                                                               nullptr, 0, 0, nullptr, nullptr,
                                                               pWt, 480, ob1, pH1, 456, 0, 453, nullptr);
    prep_wt_k<<<(226 * 480 + 255) / 256, 256>>>(ow2, pWt, 453, 226, 480);
    hfgemm_k<0, 1, 0, 1, 0, 0><<<dim3(4, MT_P), 256, SMEM_2>>>(pH1, 456, 456, nullptr, 0, 0, nullptr, nullptr,
                                                               pWt, 480, ob2, pPQ, 228, 0, 226, nullptr);
    head3_k<<<(NPTS * 32) / 256, 256>>>(pPQ, ow3, ob3, (float*)d_out);
}

// round 14
// speedup vs baseline: 1.2675x; 1.0259x over previous
#include <cuda_runtime.h>
#include <cuda_fp16.h>
#include <cstdint>
#include <math.h>

// ============================ problem constants ============================
#define NPTS 131072          // B*N = 1024*128
#define NEDG 524288          // NPTS * K(=4)

// Concat buffer layout (all segment starts 16B-aligned; pads never written => 0)
#define F_OFS  0
#define O1_OFS 8
#define O2_OFS 72
#define O3_OFS 200
#define XLD    456

// ============================ device scratch ===============================
__device__ float  g_X453[(size_t)NPTS * XLD];   // fp32 concat (KNN reads)
__device__ __half g_Xh[(size_t)NPTS * XLD];     // fp16 mirror (post-KNN A source)
__device__ float  g_PQ[(size_t)NPTS * 384];     // fp32 PQ1/PQ2; fp16 PQ3; head3 partials
__device__ float  g_H1[(size_t)NPTS * 456];     // fp16 H1 (ld 456 halves)
__device__ int    g_idx[NPTS * 4];
__device__ float  g_Wt[512 * 480];

__device__ __forceinline__ float eluf(float x) { return x > 0.f ? x : expm1f(x); }

// ============================ small helpers ================================
__device__ __forceinline__ void sp_hf(float a0, float a1, uint32_t& h, uint32_t& l) {
    __half2 hh = __floats2half2_rn(a0, a1);
    float r0 = a0 - __half2float(__low2half(hh));
    float r1 = a1 - __half2float(__high2half(hh));
    __half2 ll = __floats2half2_rn(r0, r1);
    h = *reinterpret_cast<uint32_t*>(&hh);
    l = *reinterpret_cast<uint32_t*>(&ll);
}
__device__ __forceinline__ uint32_t hf1(float a0, float a1) {
    __half2 hh = __floats2half2_rn(a0, a1);
    return *reinterpret_cast<uint32_t*>(&hh);
}
__device__ __forceinline__ void mma16h(float* c, const uint32_t* a, const uint32_t* b) {
    asm volatile("mma.sync.aligned.m16n8k16.row.col.f32.f16.f16.f32 "
                 "{%0,%1,%2,%3}, {%4,%5,%6,%7}, {%8,%9}, {%0,%1,%2,%3};"
                 : "+f"(c[0]), "+f"(c[1]), "+f"(c[2]), "+f"(c[3])
                 : "r"(a[0]), "r"(a[1]), "r"(a[2]), "r"(a[3]), "r"(b[0]), "r"(b[1]));
}

// ============================ elementwise helpers ==========================
__global__ void copy_features_k(const float* __restrict__ f, float* __restrict__ X,
                                __half* __restrict__ Xh) {
    int e = blockIdx.x * blockDim.x + threadIdx.x;
    if (e < NPTS * 5) {
        int r = e / 5, c = e % 5;
        X[(size_t)r * XLD + c] = f[e];
        Xh[(size_t)r * XLD + c] = __float2half(f[e]);
    }
}
__global__ void prep_pq_k(const float* __restrict__ w1, float* __restrict__ wt, int C, int H, int Kpad) {
    int e = blockIdx.x * blockDim.x + threadIdx.x;
    if (e >= 2 * H * Kpad) return;
    int n = e / Kpad, k = e % Kpad;
    float v = 0.f;
    if (k < C) v = (n < H) ? (w1[k * H + n] - w1[(C + k) * H + n]) : w1[(C + k) * H + (n - H)];
    wt[(size_t)n * Kpad + k] = v;
}
__global__ void prep_wt_k(const float* __restrict__ w, float* __restrict__ wt, int K, int N, int Kpad) {
    int e = blockIdx.x * blockDim.x + threadIdx.x;
    if (e >= N * Kpad) return;
    int n = e / Kpad, k = e % Kpad;
    wt[(size_t)n * Kpad + k] = (k < K) ? w[(size_t)k * N + n] : 0.f;
}
__global__ void prep_head_k(const float* __restrict__ w, float* __restrict__ wt, int N, int Kpad) {
    int e = blockIdx.x * blockDim.x + threadIdx.x;
    if (e >= N * Kpad) return;
    int n = e / Kpad, kp = e % Kpad;
    float v = 0.f;
    if (kp < 5)                   v = w[(size_t)kp * N + n];
    else if (kp >= 8 && kp < 456) v = w[(size_t)(kp - 3) * N + n];
    wt[(size_t)n * Kpad + kp] = v;
}

// ============================ KNN (k=4; 2 batches per block; FROZEN) =======
template<int C, int CP>
__global__ void __launch_bounds__(256) knn_k(const float* __restrict__ x, int ld, int cofs,
                                             int* __restrict__ idxout) {
    constexpr int PAD = CP + 4;
    __shared__ __align__(16) float sx[2][32][PAD];
    __shared__ float sn[2][128];
    int half = threadIdx.x >> 7;
    int tid = threadIdx.x & 127;
    int b = blockIdx.x * 2 + half;
    const float* xb = x + (size_t)b * 128 * ld + cofs;
    float4 xi[CP / 4];

    for (int t = 0; t < 4; t++) {
        for (int e = tid; e < 32 * CP; e += 128) {
            int r = e / CP, c = e % CP;
            sx[half][r][c] = (c < C) ? xb[(size_t)(t * 32 + r) * ld + c] : 0.f;
        }
        __syncthreads();
        if ((tid >> 5) == t) {
            int r = tid & 31;
            #pragma unroll
            for (int c4 = 0; c4 < CP / 4; c4++) xi[c4] = *(const float4*)&sx[half][r][4 * c4];
        }
        __syncthreads();
    }
    float ni = 0.f;
    #pragma unroll
    for (int c4 = 0; c4 < CP / 4; c4++)
        ni += xi[c4].x * xi[c4].x + xi[c4].y * xi[c4].y + xi[c4].z * xi[c4].z + xi[c4].w * xi[c4].w;
    sn[half][tid] = ni;
    __syncthreads();

    float bd0 = 1e30f, bd1 = 1e30f, bd2 = 1e30f, bd3 = 1e30f;
    int   bi0 = 0,     bi1 = 0,     bi2 = 0,     bi3 = 0;

    for (int t = 0; t < 4; t++) {
        for (int e = tid; e < 32 * CP; e += 128) {
            int r = e / CP, c = e % CP;
            sx[half][r][c] = (c < C) ? xb[(size_t)(t * 32 + r) * ld + c] : 0.f;
        }
        __syncthreads();
        for (int jl = 0; jl < 32; jl++) {
            int j = t * 32 + jl;
            float dot = 0.f;
            #pragma unroll
            for (int c4 = 0; c4 < CP / 4; c4++) {
                float4 xj = *(const float4*)&sx[half][jl][4 * c4];
                dot += xi[c4].x * xj.x + xi[c4].y * xj.y + xi[c4].z * xj.z + xi[c4].w * xj.w;
            }
            float d = ni + sn[half][j] - 2.f * dot;
            if (j == tid) d = 1e30f;
            if (d < bd3) {
                if (d < bd2) {
                    bd3 = bd2; bi3 = bi2;
                    if (d < bd1) {
                        bd2 = bd1; bi2 = bi1;
                        if (d < bd0) { bd1 = bd0; bi1 = bi0; bd0 = d; bi0 = j; }
                        else         { bd1 = d; bi1 = j; }
                    } else { bd2 = d; bi2 = j; }
                } else { bd3 = d; bi3 = j; }
            }
        }
        __syncthreads();
    }
    int base = (b * 128 + tid) * 4;
    int gb = b * 128;
    idxout[base + 0] = gb + bi0;
    idxout[base + 1] = gb + bi1;
    idxout[base + 2] = gb + bi2;
    idxout[base + 3] = gb + bi3;
}

// ============================ fp16 GEMM (unified) ==========================
// A: fp32 source -> hi+lo fp16 planes; fp16 source (INH, dense) -> exact 1 plane.
// B: B3=1 -> hi+lo planes (3-term); B3=0 -> single plane (2-/1-term).
// OUTH: fp16 output. Xh2: fp16 mirror for RED fp32 out.
// H3: fused final-layer epilogue — partial dots with w3 into Part (no C store).
#define APU 20
#define AHLU (128 * APU)
#define BHLU (64 * APU)
template<int GATHER, int ACT, int RED, int INH, int OUTH, int B3, int H3>
__global__ void __launch_bounds__(256, 2) hfgemm_k(
    const float* __restrict__ A, int lda, int Kval,
    const float* __restrict__ PQ, int ldpq, int qofs,
    const float* __restrict__ b1, const int* __restrict__ eidx,
    const float* __restrict__ Wt, int Kpad,
    const float* __restrict__ bias,
    float* __restrict__ Co, int ldc, int cofs, int Nfull,
    __half* __restrict__ Xh2,
    const float* __restrict__ w3, float* __restrict__ Part)
{
    constexpr int ATERMS = (INH && !GATHER) ? 1 : 2;
    constexpr int STGU = 2 * AHLU + (B3 ? 2 : 1) * BHLU;
    extern __shared__ uint32_t smu[];
    const int tid = threadIdx.x;
    const int wid = tid >> 5, lane = tid & 31;
    const int g = lane >> 2, q = lane & 3;
    const int warp_m = wid >> 1, warp_n = wid & 1;
    const int m0 = blockIdx.y * 128;
    const int n0 = blockIdx.x * 64;
    const int iters = Kpad >> 5;

    const int lm = tid >> 3, lkc = (tid & 7) << 2;
    const int luc = (tid & 7) << 1;
    const int lr = tid >> 1, lh = (tid & 1) << 4;
    const int lgu = (tid & 1) << 3;

    const float *Pp = nullptr, *Qp = nullptr;
    const __half *Pph = nullptr, *Qph = nullptr;
    if (GATHER) {
        int mg = m0 + lr;
        if (INH) {
            Pph = (const __half*)PQ + (size_t)(mg >> 2) * ldpq;
            Qph = (const __half*)PQ + (size_t)eidx[mg] * ldpq + qofs;
        } else {
            Pp = PQ + (size_t)(mg >> 2) * ldpq;
            Qp = PQ + (size_t)eidx[mg] * ldpq + qofs;
        }
    }

    float4 rA[4], rQ[4], rB[2];
    uint2 rAh[4];
    uint4 rPh[2], rQh[2];

    auto ldg_tile = [&](int it) {
        const int k0 = it << 5;
        if (GATHER) {
            if (INH) {
                rPh[0] = *(const uint4*)(Pph + k0 + lh);
                rPh[1] = *(const uint4*)(Pph + k0 + lh + 8);
                rQh[0] = *(const uint4*)(Qph + k0 + lh);
                rQh[1] = *(const uint4*)(Qph + k0 + lh + 8);
            } else {
                #pragma unroll
                for (int qq = 0; qq < 4; qq++) {
                    int kk = k0 + lh + (qq << 2);
                    rA[qq] = *(const float4*)(Pp + kk);
                    rQ[qq] = *(const float4*)(Qp + kk);
                }
            }
        } else if (INH) {
            #pragma unroll
            for (int i = 0; i < 4; i++) {
                int gk = k0 + lkc;
                const __half* src = (const __half*)A + (size_t)(m0 + lm + i * 32) * lda + gk;
                if (gk + 3 < Kval) rAh[i] = *(const uint2*)src;
                else               rAh[i] = make_uint2(0u, 0u);
            }
        } else {
            #pragma unroll
            for (int i = 0; i < 4; i++) {
                int gk = k0 + lkc;
                const float* src = A + (size_t)(m0 + lm + i * 32) * lda + gk;
                if (gk + 3 < Kval) {
                    rA[i] = *(const float4*)src;
                } else {
                    rA[i] = make_float4(0.f, 0.f, 0.f, 0.f);
                    if (gk + 0 < Kval) rA[i].x = src[0];
                    if (gk + 1 < Kval) rA[i].y = src[1];
                    if (gk + 2 < Kval) rA[i].z = src[2];
                }
            }
        }
        #pragma unroll
        for (int i = 0; i < 2; i++) {
            int gn = n0 + lm + i * 32;
            if (gn < Nfull) rB[i] = *(const float4*)(Wt + (size_t)gn * Kpad + (it << 5) + lkc);
            else            rB[i] = make_float4(0.f, 0.f, 0.f, 0.f);
        }
    };

    auto sts_tile = [&](int s, int it) {
        uint32_t* Ah = smu + s * STGU;
        uint32_t* Al = Ah + AHLU;
        uint32_t* Bh = smu + s * STGU + 2 * AHLU;
        uint32_t* Bl = Bh + BHLU;
        if (GATHER) {
            const int k0 = it << 5;
            if (INH) {
                const uint32_t* pw = (const uint32_t*)rPh;
                const uint32_t* qw = (const uint32_t*)rQh;
                #pragma unroll
                for (int qq = 0; qq < 4; qq++) {
                    int kk = lh + (qq << 2);
                    float4 bv = *(const float4*)(b1 + k0 + kk);
                    float2 p0 = __half22float2(*(const __half2*)&pw[2 * qq]);
                    float2 p1 = __half22float2(*(const __half2*)&pw[2 * qq + 1]);
                    float2 q0 = __half22float2(*(const __half2*)&qw[2 * qq]);
                    float2 q1 = __half22float2(*(const __half2*)&qw[2 * qq + 1]);
                    float v0 = eluf(p0.x + q0.x + bv.x);
                    float v1 = eluf(p0.y + q0.y + bv.y);
                    float v2 = eluf(p1.x + q1.x + bv.z);
                    float v3 = eluf(p1.y + q1.y + bv.w);
                    uint32_t h0, l0, h1, l1;
                    sp_hf(v0, v1, h0, l0);
                    sp_hf(v2, v3, h1, l1);
                    *(uint2*)&Ah[lr * APU + lgu + (qq << 1)] = make_uint2(h0, h1);
                    *(uint2*)&Al[lr * APU + lgu + (qq << 1)] = make_uint2(l0, l1);
                }
            } else {
                #pragma unroll
                for (int qq = 0; qq < 4; qq++) {
                    int kk = lh + (qq << 2);
                    float4 bv = *(const float4*)(b1 + k0 + kk);
                    float v0 = eluf(rA[qq].x + rQ[qq].x + bv.x);
                    float v1 = eluf(rA[qq].y + rQ[qq].y + bv.y);
                    float v2 = eluf(rA[qq].z + rQ[qq].z + bv.z);
                    float v3 = eluf(rA[qq].w + rQ[qq].w + bv.w);
                    uint32_t h0, l0, h1, l1;
                    sp_hf(v0, v1, h0, l0);
                    sp_hf(v2, v3, h1, l1);
                    *(uint2*)&Ah[lr * APU + lgu + (qq << 1)] = make_uint2(h0, h1);
                    *(uint2*)&Al[lr * APU + lgu + (qq << 1)] = make_uint2(l0, l1);
                }
            }
        } else if (INH) {
            #pragma unroll
            for (int i = 0; i < 4; i++)
                *(uint2*)&Ah[(lm + i * 32) * APU + luc] = rAh[i];
        } else {
            #pragma unroll
            for (int i = 0; i < 4; i++) {
                uint32_t h0, l0, h1, l1;
                sp_hf(rA[i].x, rA[i].y, h0, l0);
                sp_hf(rA[i].z, rA[i].w, h1, l1);
                *(uint2*)&Ah[(lm + i * 32) * APU + luc] = make_uint2(h0, h1);
                *(uint2*)&Al[(lm + i * 32) * APU + luc] = make_uint2(l0, l1);
            }
        }
        #pragma unroll
        for (int i = 0; i < 2; i++) {
            if (B3) {
                uint32_t h0, l0, h1, l1;
                sp_hf(rB[i].x, rB[i].y, h0, l0);
                sp_hf(rB[i].z, rB[i].w, h1, l1);
                *(uint2*)&Bh[(lm + i * 32) * APU + luc] = make_uint2(h0, h1);
                *(uint2*)&Bl[(lm + i * 32) * APU + luc] = make_uint2(l0, l1);
            } else {
                uint32_t h0 = hf1(rB[i].x, rB[i].y);
                uint32_t h1 = hf1(rB[i].z, rB[i].w);
                *(uint2*)&Bh[(lm + i * 32) * APU + luc] = make_uint2(h0, h1);
            }
        }
    };

    float acc[2][4][4];
    #pragma unroll
    for (int mt = 0; mt < 2; mt++)
        #pragma unroll
        for (int nt = 0; nt < 4; nt++)
            #pragma unroll
            for (int i = 0; i < 4; i++) acc[mt][nt][i] = 0.f;

    const int abase = (warp_m * 32 + g) * APU;
    const int bbase = (warp_n * 32 + g) * APU;

    ldg_tile(0);
    sts_tile(0, 0);
    for (int it = 0; it < iters; it++) {
        if (it + 1 < iters) ldg_tile(it + 1);
        __syncthreads();
        const int s = it & 1;
        const uint32_t* Ah = smu + s * STGU;
        const uint32_t* Al = Ah + AHLU;
        const uint32_t* Bh = smu + s * STGU + 2 * AHLU;
        const uint32_t* Bl = Bh + BHLU;
        #pragma unroll
        for (int ks = 0; ks < 2; ks++) {
            const int koff = (ks << 3) + q;
            uint32_t ah[2][4], al[2][4];
            #pragma unroll
            for (int mt = 0; mt < 2; mt++) {
                int rb = abase + mt * 16 * APU;
                ah[mt][0] = Ah[rb + koff];
                ah[mt][1] = Ah[rb + 8 * APU + koff];
                ah[mt][2] = Ah[rb + koff + 4];
                ah[mt][3] = Ah[rb + 8 * APU + koff + 4];
                if (ATERMS == 2) {
                    al[mt][0] = Al[rb + koff];
                    al[mt][1] = Al[rb + 8 * APU + koff];
                    al[mt][2] = Al[rb + koff + 4];
                    al[mt][3] = Al[rb + 8 * APU + koff + 4];
                }
            }
            uint32_t bh[4][2], bl[4][2];
            #pragma unroll
            for (int nt = 0; nt < 4; nt++) {
                int rb = bbase + nt * 8 * APU;
                bh[nt][0] = Bh[rb + koff];
                bh[nt][1] = Bh[rb + koff + 4];
                if (B3) {
                    bl[nt][0] = Bl[rb + koff];
                    bl[nt][1] = Bl[rb + koff + 4];
                }
            }
            #pragma unroll
            for (int mt = 0; mt < 2; mt++)
                #pragma unroll
                for (int nt = 0; nt < 4; nt++) {
                    mma16h(acc[mt][nt], ah[mt], bh[nt]);
                    if (ATERMS == 2) mma16h(acc[mt][nt], al[mt], bh[nt]);
                    if (B3) mma16h(acc[mt][nt], ah[mt], bl[nt]);
                }
        }
        if (it + 1 < iters) sts_tile((it + 1) & 1, it + 1);
    }

    // ============================== epilogue ==============================
    if (H3) {
        // fused final layer: partial dot products with w3 (2 outputs)
        #pragma unroll
        for (int mt = 0; mt < 2; mt++) {
            const int rbase = m0 + warp_m * 32 + mt * 16;
            float s00 = 0.f, s01 = 0.f, s10 = 0.f, s11 = 0.f;
            #pragma unroll
            for (int nt = 0; nt < 4; nt++) {
                const int gc = n0 + warp_n * 32 + nt * 8 + 2 * q;
                float w30 = 0.f, w31 = 0.f, w40 = 0.f, w41 = 0.f;
                float bb0 = 0.f, bb1 = 0.f;
                if (gc < Nfull)     { w30 = w3[2 * gc];     w31 = w3[2 * gc + 1]; bb0 = bias[gc]; }
                if (gc + 1 < Nfull) { w40 = w3[2 * gc + 2]; w41 = w3[2 * gc + 3]; bb1 = bias[gc + 1]; }
                float e0 = eluf(acc[mt][nt][0] + bb0), e1 = eluf(acc[mt][nt][1] + bb1);
                float e2 = eluf(acc[mt][nt][2] + bb0), e3 = eluf(acc[mt][nt][3] + bb1);
                s00 += e0 * w30 + e1 * w40;  s01 += e0 * w31 + e1 * w41;
                s10 += e2 * w30 + e3 * w40;  s11 += e2 * w31 + e3 * w41;
            }
            s00 += __shfl_xor_sync(0xffffffffu, s00, 1); s00 += __shfl_xor_sync(0xffffffffu, s00, 2);
            s01 += __shfl_xor_sync(0xffffffffu, s01, 1); s01 += __shfl_xor_sync(0xffffffffu, s01, 2);
            s10 += __shfl_xor_sync(0xffffffffu, s10, 1); s10 += __shfl_xor_sync(0xffffffffu, s10, 2);
            s11 += __shfl_xor_sync(0xffffffffu, s11, 1); s11 += __shfl_xor_sync(0xffffffffu, s11, 2);
            if (q == 0) {
                const int grp = blockIdx.x * 2 + warp_n;      // 0..7
                float* p0 = Part + (size_t)(rbase + g) * 16 + grp * 2;
                float* p1 = Part + (size_t)(rbase + g + 8) * 16 + grp * 2;
                p0[0] = s00; p0[1] = s01;
                p1[0] = s10; p1[1] = s11;
            }
        }
        return;
    }
    #pragma unroll
    for (int mt = 0; mt < 2; mt++) {
        const int rbase = m0 + warp_m * 32 + mt * 16;
        #pragma unroll
        for (int nt = 0; nt < 4; nt++) {
            const int cl = warp_n * 32 + nt * 8 + 2 * q;
            const int gc = n0 + cl;
            float bb0 = 0.f, bb1 = 0.f;
            if (bias != nullptr) {
                if (gc < Nfull)     bb0 = bias[gc];
                if (gc + 1 < Nfull) bb1 = bias[gc + 1];
            }
            if (!RED) {
                float v0 = acc[mt][nt][0] + bb0, v1 = acc[mt][nt][1] + bb1;
                float v2 = acc[mt][nt][2] + bb0, v3 = acc[mt][nt][3] + bb1;
                if (ACT) { v0 = eluf(v0); v1 = eluf(v1); v2 = eluf(v2); v3 = eluf(v3); }
                if (OUTH) {
                    __half* o0 = (__half*)Co + (size_t)(rbase + g) * ldc + cofs;
                    __half* o1 = o0 + (size_t)8 * ldc;
                    if (gc + 1 < Nfull) {
                        *(__half2*)(o0 + gc) = __floats2half2_rn(v0, v1);
                        *(__half2*)(o1 + gc) = __floats2half2_rn(v2, v3);
                    } else if (gc < Nfull) {
                        o0[gc] = __float2half(v0);
                        o1[gc] = __float2half(v2);
                    }
                } else {
                    float* r0 = Co + (size_t)(rbase + g) * ldc + cofs;
                    float* r1 = r0 + (size_t)8 * ldc;
                    if (gc < Nfull)     { r0[gc] = v0;     r1[gc] = v2; }
                    if (gc + 1 < Nfull) { r0[gc + 1] = v1; r1[gc + 1] = v3; }
                }
            } else {
                #pragma unroll
                for (int half = 0; half < 2; half++) {
                    float v0 = (gc < Nfull)     ? eluf(acc[mt][nt][2 * half + 0] + bb0) : 0.f;
                    float v1 = (gc + 1 < Nfull) ? eluf(acc[mt][nt][2 * half + 1] + bb1) : 0.f;
                    v0 += __shfl_xor_sync(0xffffffffu, v0, 4);
                    v0 += __shfl_xor_sync(0xffffffffu, v0, 8);
                    v1 += __shfl_xor_sync(0xffffffffu, v1, 4);
                    v1 += __shfl_xor_sync(0xffffffffu, v1, 8);
                    if ((lane & 12) == 0) {
                        int p = (rbase + half * 8 + g) >> 2;
                        float o0 = 0.25f * v0, o1 = 0.25f * v1;
                        if (OUTH) {
                            __half* op = (__half*)Co + (size_t)p * ldc + cofs;
                            if (gc + 1 < Nfull) *(__half2*)(op + gc) = __floats2half2_rn(o0, o1);
                            else if (gc < Nfull) op[gc] = __float2half(o0);
                        } else {
                            float* op = Co + (size_t)p * ldc + cofs;
                            if (gc < Nfull)     op[gc] = o0;
                            if (gc + 1 < Nfull) op[gc + 1] = o1;
                            if (Xh2 != nullptr) {
                                __half* oh = Xh2 + (size_t)p * XLD + cofs;
                                if (gc + 1 < Nfull) *(__half2*)(oh + gc) = __floats2half2_rn(o0, o1);
                                else if (gc < Nfull) oh[gc] = __float2half(o0);
                            }
                        }
                    }
                }
            }
        }
    }
}

// ============================ head3 partial reduce =========================
__global__ void head3r_k(const float* __restrict__ Part, const float* __restrict__ b,
                         float* __restrict__ out) {
    int p = blockIdx.x * blockDim.x + threadIdx.x;
    if (p >= NPTS) return;
    const float* pr = Part + (size_t)p * 16;
    float a0 = b[0], a1 = b[1];
    #pragma unroll
    for (int gp = 0; gp < 8; gp++) {
        a0 += pr[gp * 2];
        a1 += pr[gp * 2 + 1];
    }
    out[2 * p + 0] = a0;
    out[2 * p + 1] = a1;
}

// ============================ launcher =====================================
extern "C" void kernel_launch(void* const* d_in, const int* in_sizes, int n_in,
                              void* d_out, int out_size) {
    const float* coords   = (const float*)d_in[0];
    const float* features = (const float*)d_in[1];
    const float* c1w1 = (const float*)d_in[2];
    const float* c1b1 = (const float*)d_in[3];
    const float* c1w2 = (const float*)d_in[4];
    const float* c1b2 = (const float*)d_in[5];
    const float* c2w1 = (const float*)d_in[6];
    const float* c2b1 = (const float*)d_in[7];
    const float* c2w2 = (const float*)d_in[8];
    const float* c2b2 = (const float*)d_in[9];
    const float* c3w1 = (const float*)d_in[10];
    const float* c3b1 = (const float*)d_in[11];
    const float* c3w2 = (const float*)d_in[12];
    const float* c3b2 = (const float*)d_in[13];
    const float* ow1  = (const float*)d_in[14];
    const float* ob1  = (const float*)d_in[15];
    const float* ow2  = (const float*)d_in[16];
    const float* ob2  = (const float*)d_in[17];
    const float* ow3  = (const float*)d_in[18];
    const float* ob3  = (const float*)d_in[19];

    float *pX, *pPQ, *pH1, *pWt; int* pidx; __half* pXh;
    cudaGetSymbolAddress((void**)&pX,  g_X453);
    cudaGetSymbolAddress((void**)&pXh, g_Xh);
    cudaGetSymbolAddress((void**)&pPQ, g_PQ);
    cudaGetSymbolAddress((void**)&pH1, g_H1);
    cudaGetSymbolAddress((void**)&pWt, g_Wt);
    cudaGetSymbolAddress((void**)&pidx, g_idx);

    const int SMEM_3 = 2 * (2 * AHLU + 2 * BHLU) * 4;   // 61,440 B
    const int SMEM_2 = 2 * (2 * AHLU + 1 * BHLU) * 4;   // 51,200 B
    cudaFuncSetAttribute(hfgemm_k<0, 0, 0, 0, 0, 1, 0>, cudaFuncAttributeMaxDynamicSharedMemorySize, SMEM_3);
    cudaFuncSetAttribute(hfgemm_k<1, 1, 1, 0, 0, 1, 0>, cudaFuncAttributeMaxDynamicSharedMemorySize, SMEM_3);
    cudaFuncSetAttribute(hfgemm_k<0, 0, 0, 1, 1, 0, 0>, cudaFuncAttributeMaxDynamicSharedMemorySize, SMEM_2);
    cudaFuncSetAttribute(hfgemm_k<1, 1, 1, 1, 1, 0, 0>, cudaFuncAttributeMaxDynamicSharedMemorySize, SMEM_2);
    cudaFuncSetAttribute(hfgemm_k<0, 1, 0, 1, 1, 0, 0>, cudaFuncAttributeMaxDynamicSharedMemorySize, SMEM_2);
    cudaFuncSetAttribute(hfgemm_k<0, 1, 0, 1, 0, 0, 1>, cudaFuncAttributeMaxDynamicSharedMemorySize, SMEM_2);

    const int MT_P = NPTS / 128;   // 1024
    const int MT_E = NEDG / 128;   // 4096

    copy_features_k<<<(NPTS * 5 + 255) / 256, 256>>>(features, pX, pXh);

    // ===== EdgeConv 1 (C=5, H=32, O=64) — feeds knn2: fp16 3-term =====
    knn_k<2, 4><<<512, 256>>>(coords, 2, 0, pidx);
    prep_pq_k<<<(64 * 32 + 255) / 256, 256>>>(c1w1, pWt, 5, 32, 32);
    hfgemm_k<0, 0, 0, 0, 0, 1, 0><<<dim3(1, MT_P), 256, SMEM_3>>>(pX, XLD, 5, nullptr, 0, 0, nullptr, nullptr,
                                                                  pWt, 32, nullptr, pPQ, 64, 0, 64, nullptr, nullptr, nullptr);
    prep_wt_k<<<(64 * 32 + 255) / 256, 256>>>(c1w2, pWt, 32, 64, 32);
    hfgemm_k<1, 1, 1, 0, 0, 1, 0><<<dim3(1, MT_E), 256, SMEM_3>>>(nullptr, 0, 32, pPQ, 64, 32, c1b1, pidx,
                                                                  pWt, 32, c1b2, pX, XLD, O1_OFS, 64, pXh, nullptr, nullptr);

    // ===== EdgeConv 2 (C=64, H=96, O=128) — feeds knn3: fp16 3-term =====
    knn_k<64, 64><<<512, 256>>>(pX, XLD, O1_OFS, pidx);
    prep_pq_k<<<(192 * 64 + 255) / 256, 256>>>(c2w1, pWt, 64, 96, 64);
    hfgemm_k<0, 0, 0, 0, 0, 1, 0><<<dim3(3, MT_P), 256, SMEM_3>>>(pX + O1_OFS, XLD, 64, nullptr, 0, 0, nullptr, nullptr,
                                                                  pWt, 64, nullptr, pPQ, 192, 0, 192, nullptr, nullptr, nullptr);
    prep_wt_k<<<(128 * 96 + 255) / 256, 256>>>(c2w2, pWt, 96, 128, 96);
    hfgemm_k<1, 1, 1, 0, 0, 1, 0><<<dim3(2, MT_E), 256, SMEM_3>>>(nullptr, 0, 96, pPQ, 192, 96, c2b1, pidx,
                                                                  pWt, 96, c2b2, pX, XLD, O2_OFS, 128, pXh, nullptr, nullptr);

    // ===== EdgeConv 3 — post-KNN: fp16; PQ3 from Xh (1-term); out3 fp16-only =====
    knn_k<128, 128><<<512, 256>>>(pX, XLD, O2_OFS, pidx);
    prep_pq_k<<<(384 * 128 + 255) / 256, 256>>>(c3w1, pWt, 128, 192, 128);
    hfgemm_k<0, 0, 0, 1, 1, 0, 0><<<dim3(6, MT_P), 256, SMEM_2>>>((const float*)(pXh + O2_OFS), XLD, 128,
                                                                  nullptr, 0, 0, nullptr, nullptr,
                                                                  pWt, 128, nullptr, pPQ, 384, 0, 384, nullptr, nullptr, nullptr);
    prep_wt_k<<<(256 * 192 + 255) / 256, 256>>>(c3w2, pWt, 192, 256, 192);
    hfgemm_k<1, 1, 1, 1, 1, 0, 0><<<dim3(4, MT_E), 256, SMEM_2>>>(nullptr, 0, 192, pPQ, 384, 192, c3b1, pidx,
                                                                  pWt, 192, c3b2, (float*)pXh, XLD, O3_OFS, 256, nullptr, nullptr, nullptr);

    // ===== Head — h1: A from Xh (1-term), H1 fp16; h2: fused head3 epilogue =====
    prep_head_k<<<(453 * 480 + 255) / 256, 256>>>(ow1, pWt, 453, 480);
    hfgemm_k<0, 1, 0, 1, 1, 0, 0><<<dim3(8, MT_P), 256, SMEM_2>>>((const float*)pXh, XLD, 456,
                                                                  nullptr, 0, 0, nullptr, nullptr,
                                                                  pWt, 480, ob1, pH1, 456, 0, 453, nullptr, nullptr, nullptr);
    prep_wt_k<<<(226 * 480 + 255) / 256, 256>>>(ow2, pWt, 453, 226, 480);
    hfgemm_k<0, 1, 0, 1, 0, 0, 1><<<dim3(4, MT_P), 256, SMEM_2>>>(pH1, 456, 456, nullptr, 0, 0, nullptr, nullptr,
                                                                  pWt, 480, ob2, nullptr, 0, 0, 226, nullptr, ow3, pPQ);
    head3r_k<<<(NPTS + 255) / 256, 256>>>(pPQ, ob3, (float*)d_out);
}

// round 15
// speedup vs baseline: 1.2710x; 1.0027x over previous
#include <cuda_runtime.h>
#include <cuda_fp16.h>
#include <cstdint>
#include <math.h>

// ============================ problem constants ============================
#define NPTS 131072          // B*N = 1024*128
#define NEDG 524288          // NPTS * K(=4)

// Concat buffer layout (all segment starts 16B-aligned; pads never written => 0)
#define F_OFS  0
#define O1_OFS 8
#define O2_OFS 72
#define O3_OFS 200
#define XLD    456

// ============================ device scratch ===============================
__device__ float    g_X453[(size_t)NPTS * XLD];   // fp32 concat (KNN reads)
__device__ __half   g_Xh[(size_t)NPTS * XLD];     // fp16 mirror (post-KNN A source)
__device__ float    g_PQ[(size_t)NPTS * 384];     // fp32 PQ1/PQ2; fp16 PQ3; head3 partials
__device__ float    g_H1[(size_t)NPTS * 456];     // fp16 H1 (ld 456 halves)
__device__ int      g_idx[NPTS * 4];
__device__ uint32_t g_Wth[512 * 240];             // packed fp16 hi plane [n][Kpad/2]
__device__ uint32_t g_Wtl[512 * 240];             // packed fp16 lo plane

__device__ __forceinline__ float eluf(float x) { return x > 0.f ? x : expm1f(x); }

// ============================ small helpers ================================
__device__ __forceinline__ void sp_hf(float a0, float a1, uint32_t& h, uint32_t& l) {
    __half2 hh = __floats2half2_rn(a0, a1);
    float r0 = a0 - __half2float(__low2half(hh));
    float r1 = a1 - __half2float(__high2half(hh));
    __half2 ll = __floats2half2_rn(r0, r1);
    h = *reinterpret_cast<uint32_t*>(&hh);
    l = *reinterpret_cast<uint32_t*>(&ll);
}
__device__ __forceinline__ void mma16h(float* c, const uint32_t* a, const uint32_t* b) {
    asm volatile("mma.sync.aligned.m16n8k16.row.col.f32.f16.f16.f32 "
                 "{%0,%1,%2,%3}, {%4,%5,%6,%7}, {%8,%9}, {%0,%1,%2,%3};"
                 : "+f"(c[0]), "+f"(c[1]), "+f"(c[2]), "+f"(c[3])
                 : "r"(a[0]), "r"(a[1]), "r"(a[2]), "r"(a[3]), "r"(b[0]), "r"(b[1]));
}

// ============================ elementwise helpers ==========================
__global__ void copy_features_k(const float* __restrict__ f, float* __restrict__ X,
                                __half* __restrict__ Xh) {
    int e = blockIdx.x * blockDim.x + threadIdx.x;
    if (e < NPTS * 5) {
        int r = e / 5, c = e % 5;
        X[(size_t)r * XLD + c] = f[e];
        Xh[(size_t)r * XLD + c] = __float2half(f[e]);
    }
}
// PQ-combined weights -> packed fp16 hi/lo planes [n][Kpad/2]
__global__ void prep_pq_k(const float* __restrict__ w1, uint32_t* __restrict__ wh,
                          uint32_t* __restrict__ wl, int C, int H, int Kpad2) {
    int e = blockIdx.x * blockDim.x + threadIdx.x;
    if (e >= 2 * H * Kpad2) return;
    int n = e / Kpad2, j = e % Kpad2;
    float v0 = 0.f, v1 = 0.f;
    int k0 = 2 * j, k1 = 2 * j + 1;
    if (k0 < C) v0 = (n < H) ? (w1[k0 * H + n] - w1[(C + k0) * H + n]) : w1[(C + k0) * H + (n - H)];
    if (k1 < C) v1 = (n < H) ? (w1[k1 * H + n] - w1[(C + k1) * H + n]) : w1[(C + k1) * H + (n - H)];
    uint32_t h, l; sp_hf(v0, v1, h, l);
    wh[(size_t)n * Kpad2 + j] = h;
    wl[(size_t)n * Kpad2 + j] = l;
}
__global__ void prep_wt_k(const float* __restrict__ w, uint32_t* __restrict__ wh,
                          uint32_t* __restrict__ wl, int K, int N, int Kpad2) {
    int e = blockIdx.x * blockDim.x + threadIdx.x;
    if (e >= N * Kpad2) return;
    int n = e / Kpad2, j = e % Kpad2;
    int k0 = 2 * j, k1 = 2 * j + 1;
    float v0 = (k0 < K) ? w[(size_t)k0 * N + n] : 0.f;
    float v1 = (k1 < K) ? w[(size_t)k1 * N + n] : 0.f;
    uint32_t h, l; sp_hf(v0, v1, h, l);
    wh[(size_t)n * Kpad2 + j] = h;
    wl[(size_t)n * Kpad2 + j] = l;
}
// head-1 weights vs padded concat layout
__global__ void prep_head_k(const float* __restrict__ w, uint32_t* __restrict__ wh,
                            uint32_t* __restrict__ wl, int N, int Kpad2) {
    int e = blockIdx.x * blockDim.x + threadIdx.x;
    if (e >= N * Kpad2) return;
    int n = e / Kpad2, j = e % Kpad2;
    float v[2];
    #pragma unroll
    for (int i = 0; i < 2; i++) {
        int kp = 2 * j + i;
        float x = 0.f;
        if (kp < 5)                   x = w[(size_t)kp * N + n];
        else if (kp >= 8 && kp < 456) x = w[(size_t)(kp - 3) * N + n];
        v[i] = x;
    }
    uint32_t h, l; sp_hf(v[0], v[1], h, l);
    wh[(size_t)n * Kpad2 + j] = h;
    wl[(size_t)n * Kpad2 + j] = l;
}

// ============================ KNN (k=4; 2 batches per block; FROZEN) =======
template<int C, int CP>
__global__ void __launch_bounds__(256) knn_k(const float* __restrict__ x, int ld, int cofs,
                                             int* __restrict__ idxout) {
    constexpr int PAD = CP + 4;
    __shared__ __align__(16) float sx[2][32][PAD];
    __shared__ float sn[2][128];
    int half = threadIdx.x >> 7;
    int tid = threadIdx.x & 127;
    int b = blockIdx.x * 2 + half;
    const float* xb = x + (size_t)b * 128 * ld + cofs;
    float4 xi[CP / 4];

    for (int t = 0; t < 4; t++) {
        for (int e = tid; e < 32 * CP; e += 128) {
            int r = e / CP, c = e % CP;
            sx[half][r][c] = (c < C) ? xb[(size_t)(t * 32 + r) * ld + c] : 0.f;
        }
        __syncthreads();
        if ((tid >> 5) == t) {
            int r = tid & 31;
            #pragma unroll
            for (int c4 = 0; c4 < CP / 4; c4++) xi[c4] = *(const float4*)&sx[half][r][4 * c4];
        }
        __syncthreads();
    }
    float ni = 0.f;
    #pragma unroll
    for (int c4 = 0; c4 < CP / 4; c4++)
        ni += xi[c4].x * xi[c4].x + xi[c4].y * xi[c4].y + xi[c4].z * xi[c4].z + xi[c4].w * xi[c4].w;
    sn[half][tid] = ni;
    __syncthreads();

    float bd0 = 1e30f, bd1 = 1e30f, bd2 = 1e30f, bd3 = 1e30f;
    int   bi0 = 0,     bi1 = 0,     bi2 = 0,     bi3 = 0;

    for (int t = 0; t < 4; t++) {
        for (int e = tid; e < 32 * CP; e += 128) {
            int r = e / CP, c = e % CP;
            sx[half][r][c] = (c < C) ? xb[(size_t)(t * 32 + r) * ld + c] : 0.f;
        }
        __syncthreads();
        for (int jl = 0; jl < 32; jl++) {
            int j = t * 32 + jl;
            float dot = 0.f;
            #pragma unroll
            for (int c4 = 0; c4 < CP / 4; c4++) {
                float4 xj = *(const float4*)&sx[half][jl][4 * c4];
                dot += xi[c4].x * xj.x + xi[c4].y * xj.y + xi[c4].z * xj.z + xi[c4].w * xj.w;
            }
            float d = ni + sn[half][j] - 2.f * dot;
            if (j == tid) d = 1e30f;
            if (d < bd3) {
                if (d < bd2) {
                    bd3 = bd2; bi3 = bi2;
                    if (d < bd1) {
                        bd2 = bd1; bi2 = bi1;
                        if (d < bd0) { bd1 = bd0; bi1 = bi0; bd0 = d; bi0 = j; }
                        else         { bd1 = d; bi1 = j; }
                    } else { bd2 = d; bi2 = j; }
                } else { bd3 = d; bi3 = j; }
            }
        }
        __syncthreads();
    }
    int base = (b * 128 + tid) * 4;
    int gb = b * 128;
    idxout[base + 0] = gb + bi0;
    idxout[base + 1] = gb + bi1;
    idxout[base + 2] = gb + bi2;
    idxout[base + 3] = gb + bi3;
}

// ============================ fp16 GEMM (unified) ==========================
// A: fp32 source -> hi+lo fp16 planes; fp16 source (INH, dense) -> exact 1 plane.
// B: pre-packed fp16 planes from prep; B3=1 uses hi+lo (3-term), B3=0 hi only.
// OUTH: fp16 output. Xh2: fp16 mirror for RED fp32 out.
// H3: fused final-layer epilogue — partial dots with w3 into Part.
#define APU 20
#define AHLU (128 * APU)
#define BHLU (64 * APU)
template<int GATHER, int ACT, int RED, int INH, int OUTH, int B3, int H3>
__global__ void __launch_bounds__(256, 2) hfgemm_k(
    const float* __restrict__ A, int lda, int Kval,
    const float* __restrict__ PQ, int ldpq, int qofs,
    const float* __restrict__ b1, const int* __restrict__ eidx,
    const uint32_t* __restrict__ Wth, const uint32_t* __restrict__ Wtl, int Kpad,
    const float* __restrict__ bias,
    float* __restrict__ Co, int ldc, int cofs, int Nfull,
    __half* __restrict__ Xh2,
    const float* __restrict__ w3, float* __restrict__ Part)
{
    constexpr int ATERMS = (INH && !GATHER) ? 1 : 2;
    constexpr int STGU = 2 * AHLU + (B3 ? 2 : 1) * BHLU;
    extern __shared__ uint32_t smu[];
    const int tid = threadIdx.x;
    const int wid = tid >> 5, lane = tid & 31;
    const int g = lane >> 2, q = lane & 3;
    const int warp_m = wid >> 1, warp_n = wid & 1;
    const int m0 = blockIdx.y * 128;
    const int n0 = blockIdx.x * 64;
    const int iters = Kpad >> 5;
    const int Kpad2 = Kpad >> 1;

    const int lm = tid >> 3, lkc = (tid & 7) << 2;
    const int luc = (tid & 7) << 1;
    const int lr = tid >> 1, lh = (tid & 1) << 4;
    const int lgu = (tid & 1) << 3;

    const float *Pp = nullptr, *Qp = nullptr;
    const __half *Pph = nullptr, *Qph = nullptr;
    if (GATHER) {
        int mg = m0 + lr;
        if (INH) {
            Pph = (const __half*)PQ + (size_t)(mg >> 2) * ldpq;
            Qph = (const __half*)PQ + (size_t)eidx[mg] * ldpq + qofs;
        } else {
            Pp = PQ + (size_t)(mg >> 2) * ldpq;
            Qp = PQ + (size_t)eidx[mg] * ldpq + qofs;
        }
    }

    float4 rA[4], rQ[4];
    uint2 rAh[4];
    uint4 rPh[2], rQh[2];
    uint2 rBh[2], rBl[2];

    auto ldg_tile = [&](int it) {
        const int k0 = it << 5;
        if (GATHER) {
            if (INH) {
                rPh[0] = *(const uint4*)(Pph + k0 + lh);
                rPh[1] = *(const uint4*)(Pph + k0 + lh + 8);
                rQh[0] = *(const uint4*)(Qph + k0 + lh);
                rQh[1] = *(const uint4*)(Qph + k0 + lh + 8);
            } else {
                #pragma unroll
                for (int qq = 0; qq < 4; qq++) {
                    int kk = k0 + lh + (qq << 2);
                    rA[qq] = *(const float4*)(Pp + kk);
                    rQ[qq] = *(const float4*)(Qp + kk);
                }
            }
        } else if (INH) {
            #pragma unroll
            for (int i = 0; i < 4; i++) {
                int gk = k0 + lkc;
                const __half* src = (const __half*)A + (size_t)(m0 + lm + i * 32) * lda + gk;
                if (gk + 3 < Kval) rAh[i] = *(const uint2*)src;
                else               rAh[i] = make_uint2(0u, 0u);
            }
        } else {
            #pragma unroll
            for (int i = 0; i < 4; i++) {
                int gk = k0 + lkc;
                const float* src = A + (size_t)(m0 + lm + i * 32) * lda + gk;
                if (gk + 3 < Kval) {
                    rA[i] = *(const float4*)src;
                } else {
                    rA[i] = make_float4(0.f, 0.f, 0.f, 0.f);
                    if (gk + 0 < Kval) rA[i].x = src[0];
                    if (gk + 1 < Kval) rA[i].y = src[1];
                    if (gk + 2 < Kval) rA[i].z = src[2];
                }
            }
        }
        const int ku = (k0 + lkc) >> 1;
        #pragma unroll
        for (int i = 0; i < 2; i++) {
            int gn = n0 + lm + i * 32;
            if (gn < Nfull) {
                rBh[i] = *(const uint2*)(Wth + (size_t)gn * Kpad2 + ku);
                if (B3) rBl[i] = *(const uint2*)(Wtl + (size_t)gn * Kpad2 + ku);
            } else {
                rBh[i] = make_uint2(0u, 0u);
                if (B3) rBl[i] = make_uint2(0u, 0u);
            }
        }
    };

    auto sts_tile = [&](int s, int it) {
        uint32_t* Ah = smu + s * STGU;
        uint32_t* Al = Ah + AHLU;
        uint32_t* Bh = smu + s * STGU + 2 * AHLU;
        uint32_t* Bl = Bh + BHLU;
        if (GATHER) {
            const int k0 = it << 5;
            if (INH) {
                const uint32_t* pw = (const uint32_t*)rPh;
                const uint32_t* qw = (const uint32_t*)rQh;
                #pragma unroll
                for (int qq = 0; qq < 4; qq++) {
                    int kk = lh + (qq << 2);
                    float4 bv = *(const float4*)(b1 + k0 + kk);
                    float2 p0 = __half22float2(*(const __half2*)&pw[2 * qq]);
                    float2 p1 = __half22float2(*(const __half2*)&pw[2 * qq + 1]);
                    float2 q0 = __half22float2(*(const __half2*)&qw[2 * qq]);
                    float2 q1 = __half22float2(*(const __half2*)&qw[2 * qq + 1]);
                    float v0 = eluf(p0.x + q0.x + bv.x);
                    float v1 = eluf(p0.y + q0.y + bv.y);
                    float v2 = eluf(p1.x + q1.x + bv.z);
                    float v3 = eluf(p1.y + q1.y + bv.w);
                    uint32_t h0, l0, h1, l1;
                    sp_hf(v0, v1, h0, l0);
                    sp_hf(v2, v3, h1, l1);
                    *(uint2*)&Ah[lr * APU + lgu + (qq << 1)] = make_uint2(h0, h1);
                    *(uint2*)&Al[lr * APU + lgu + (qq << 1)] = make_uint2(l0, l1);
                }
            } else {
                #pragma unroll
                for (int qq = 0; qq < 4; qq++) {
                    int kk = lh + (qq << 2);
                    float4 bv = *(const float4*)(b1 + k0 + kk);
                    float v0 = eluf(rA[qq].x + rQ[qq].x + bv.x);
                    float v1 = eluf(rA[qq].y + rQ[qq].y + bv.y);
                    float v2 = eluf(rA[qq].z + rQ[qq].z + bv.z);
                    float v3 = eluf(rA[qq].w + rQ[qq].w + bv.w);
                    uint32_t h0, l0, h1, l1;
                    sp_hf(v0, v1, h0, l0);
                    sp_hf(v2, v3, h1, l1);
                    *(uint2*)&Ah[lr * APU + lgu + (qq << 1)] = make_uint2(h0, h1);
                    *(uint2*)&Al[lr * APU + lgu + (qq << 1)] = make_uint2(l0, l1);
                }
            }
        } else if (INH) {
            #pragma unroll
            for (int i = 0; i < 4; i++)
                *(uint2*)&Ah[(lm + i * 32) * APU + luc] = rAh[i];
        } else {
            #pragma unroll
            for (int i = 0; i < 4; i++) {
                uint32_t h0, l0, h1, l1;
                sp_hf(rA[i].x, rA[i].y, h0, l0);
                sp_hf(rA[i].z, rA[i].w, h1, l1);
                *(uint2*)&Ah[(lm + i * 32) * APU + luc] = make_uint2(h0, h1);
                *(uint2*)&Al[(lm + i * 32) * APU + luc] = make_uint2(l0, l1);
            }
        }
        #pragma unroll
        for (int i = 0; i < 2; i++) {
            *(uint2*)&Bh[(lm + i * 32) * APU + luc] = rBh[i];
            if (B3) *(uint2*)&Bl[(lm + i * 32) * APU + luc] = rBl[i];
        }
    };

    float acc[2][4][4];
    #pragma unroll
    for (int mt = 0; mt < 2; mt++)
        #pragma unroll
        for (int nt = 0; nt < 4; nt++)
            #pragma unroll
            for (int i = 0; i < 4; i++) acc[mt][nt][i] = 0.f;

    const int abase = (warp_m * 32 + g) * APU;
    const int bbase = (warp_n * 32 + g) * APU;

    ldg_tile(0);
    sts_tile(0, 0);
    for (int it = 0; it < iters; it++) {
        if (it + 1 < iters) ldg_tile(it + 1);
        __syncthreads();
        const int s = it & 1;
        const uint32_t* Ah = smu + s * STGU;
        const uint32_t* Al = Ah + AHLU;
        const uint32_t* Bh = smu + s * STGU + 2 * AHLU;
        const uint32_t* Bl = Bh + BHLU;
        #pragma unroll
        for (int ks = 0; ks < 2; ks++) {
            const int koff = (ks << 3) + q;
            uint32_t ah[2][4], al[2][4];
            #pragma unroll
            for (int mt = 0; mt < 2; mt++) {
                int rb = abase + mt * 16 * APU;
                ah[mt][0] = Ah[rb + koff];
                ah[mt][1] = Ah[rb + 8 * APU + koff];
                ah[mt][2] = Ah[rb + koff + 4];
                ah[mt][3] = Ah[rb + 8 * APU + koff + 4];
                if (ATERMS == 2) {
                    al[mt][0] = Al[rb + koff];
                    al[mt][1] = Al[rb + 8 * APU + koff];
                    al[mt][2] = Al[rb + koff + 4];
                    al[mt][3] = Al[rb + 8 * APU + koff + 4];
                }
            }
            uint32_t bh[4][2], bl[4][2];
            #pragma unroll
            for (int nt = 0; nt < 4; nt++) {
                int rb = bbase + nt * 8 * APU;
                bh[nt][0] = Bh[rb + koff];
                bh[nt][1] = Bh[rb + koff + 4];
                if (B3) {
                    bl[nt][0] = Bl[rb + koff];
                    bl[nt][1] = Bl[rb + koff + 4];
                }
            }
            #pragma unroll
            for (int mt = 0; mt < 2; mt++)
                #pragma unroll
                for (int nt = 0; nt < 4; nt++) {
                    mma16h(acc[mt][nt], ah[mt], bh[nt]);
                    if (ATERMS == 2) mma16h(acc[mt][nt], al[mt], bh[nt]);
                    if (B3) mma16h(acc[mt][nt], ah[mt], bl[nt]);
                }
        }
        if (it + 1 < iters) sts_tile((it + 1) & 1, it + 1);
    }

    // ============================== epilogue ==============================
    if (H3) {
        #pragma unroll
        for (int mt = 0; mt < 2; mt++) {
            const int rbase = m0 + warp_m * 32 + mt * 16;
            float s00 = 0.f, s01 = 0.f, s10 = 0.f, s11 = 0.f;
            #pragma unroll
            for (int nt = 0; nt < 4; nt++) {
                const int gc = n0 + warp_n * 32 + nt * 8 + 2 * q;
                float w30 = 0.f, w31 = 0.f, w40 = 0.f, w41 = 0.f;
                float bb0 = 0.f, bb1 = 0.f;
                if (gc < Nfull)     { w30 = w3[2 * gc];     w31 = w3[2 * gc + 1]; bb0 = bias[gc]; }
                if (gc + 1 < Nfull) { w40 = w3[2 * gc + 2]; w41 = w3[2 * gc + 3]; bb1 = bias[gc + 1]; }
                float e0 = eluf(acc[mt][nt][0] + bb0), e1 = eluf(acc[mt][nt][1] + bb1);
                float e2 = eluf(acc[mt][nt][2] + bb0), e3 = eluf(acc[mt][nt][3] + bb1);
                s00 += e0 * w30 + e1 * w40;  s01 += e0 * w31 + e1 * w41;
                s10 += e2 * w30 + e3 * w40;  s11 += e2 * w31 + e3 * w41;
            }
            s00 += __shfl_xor_sync(0xffffffffu, s00, 1); s00 += __shfl_xor_sync(0xffffffffu, s00, 2);
            s01 += __shfl_xor_sync(0xffffffffu, s01, 1); s01 += __shfl_xor_sync(0xffffffffu, s01, 2);
            s10 += __shfl_xor_sync(0xffffffffu, s10, 1); s10 += __shfl_xor_sync(0xffffffffu, s10, 2);
            s11 += __shfl_xor_sync(0xffffffffu, s11, 1); s11 += __shfl_xor_sync(0xffffffffu, s11, 2);
            if (q == 0) {
                const int grp = blockIdx.x * 2 + warp_n;      // 0..7
                float* p0 = Part + (size_t)(rbase + g) * 16 + grp * 2;
                float* p1 = Part + (size_t)(rbase + g + 8) * 16 + grp * 2;
                p0[0] = s00; p0[1] = s01;
                p1[0] = s10; p1[1] = s11;
            }
        }
        return;
    }
    #pragma unroll
    for (int mt = 0; mt < 2; mt++) {
        const int rbase = m0 + warp_m * 32 + mt * 16;
        #pragma unroll
        for (int nt = 0; nt < 4; nt++) {
            const int cl = warp_n * 32 + nt * 8 + 2 * q;
            const int gc = n0 + cl;
            float bb0 = 0.f, bb1 = 0.f;
            if (bias != nullptr) {
                if (gc < Nfull)     bb0 = bias[gc];
                if (gc + 1 < Nfull) bb1 = bias[gc + 1];
            }
            if (!RED) {
                float v0 = acc[mt][nt][0] + bb0, v1 = acc[mt][nt][1] + bb1;
                float v2 = acc[mt][nt][2] + bb0, v3 = acc[mt][nt][3] + bb1;
                if (ACT) { v0 = eluf(v0); v1 = eluf(v1); v2 = eluf(v2); v3 = eluf(v3); }
                if (OUTH) {
                    __half* o0 = (__half*)Co + (size_t)(rbase + g) * ldc + cofs;
                    __half* o1 = o0 + (size_t)8 * ldc;
                    if (gc + 1 < Nfull) {
                        *(__half2*)(o0 + gc) = __floats2half2_rn(v0, v1);
                        *(__half2*)(o1 + gc) = __floats2half2_rn(v2, v3);
                    } else if (gc < Nfull) {
                        o0[gc] = __float2half(v0);
                        o1[gc] = __float2half(v2);
                    }
                } else {
                    float* r0 = Co + (size_t)(rbase + g) * ldc + cofs;
                    float* r1 = r0 + (size_t)8 * ldc;
                    if (gc < Nfull)     { r0[gc] = v0;     r1[gc] = v2; }
                    if (gc + 1 < Nfull) { r0[gc + 1] = v1; r1[gc + 1] = v3; }
                }
            } else {
                #pragma unroll
                for (int half = 0; half < 2; half++) {
                    float v0 = (gc < Nfull)     ? eluf(acc[mt][nt][2 * half + 0] + bb0) : 0.f;
                    float v1 = (gc + 1 < Nfull) ? eluf(acc[mt][nt][2 * half + 1] + bb1) : 0.f;
                    v0 += __shfl_xor_sync(0xffffffffu, v0, 4);
                    v0 += __shfl_xor_sync(0xffffffffu, v0, 8);
                    v1 += __shfl_xor_sync(0xffffffffu, v1, 4);
                    v1 += __shfl_xor_sync(0xffffffffu, v1, 8);
                    if ((lane & 12) == 0) {
                        int p = (rbase + half * 8 + g) >> 2;
                        float o0 = 0.25f * v0, o1 = 0.25f * v1;
                        if (OUTH) {
                            __half* op = (__half*)Co + (size_t)p * ldc + cofs;
                            if (gc + 1 < Nfull) *(__half2*)(op + gc) = __floats2half2_rn(o0, o1);
                            else if (gc < Nfull) op[gc] = __float2half(o0);
                        } else {
                            float* op = Co + (size_t)p * ldc + cofs;
                            if (gc < Nfull)     op[gc] = o0;
                            if (gc + 1 < Nfull) op[gc + 1] = o1;
                            if (Xh2 != nullptr) {
                                __half* oh = Xh2 + (size_t)p * XLD + cofs;
                                if (gc + 1 < Nfull) *(__half2*)(oh + gc) = __floats2half2_rn(o0, o1);
                                else if (gc < Nfull) oh[gc] = __float2half(o0);
                            }
                        }
                    }
                }
            }
        }
    }
}

// ============================ head3 partial reduce =========================
__global__ void head3r_k(const float* __restrict__ Part, const float* __restrict__ b,
                         float* __restrict__ out) {
    int p = blockIdx.x * blockDim.x + threadIdx.x;
    if (p >= NPTS) return;
    const float* pr = Part + (size_t)p * 16;
    float a0 = b[0], a1 = b[1];
    #pragma unroll
    for (int gp = 0; gp < 8; gp++) {
        a0 += pr[gp * 2];
        a1 += pr[gp * 2 + 1];
    }
    out[2 * p + 0] = a0;
    out[2 * p + 1] = a1;
}

// ============================ launcher =====================================
extern "C" void kernel_launch(void* const* d_in, const int* in_sizes, int n_in,
                              void* d_out, int out_size) {
    const float* coords   = (const float*)d_in[0];
    const float* features = (const float*)d_in[1];
    const float* c1w1 = (const float*)d_in[2];
    const float* c1b1 = (const float*)d_in[3];
    const float* c1w2 = (const float*)d_in[4];
    const float* c1b2 = (const float*)d_in[5];
    const float* c2w1 = (const float*)d_in[6];
    const float* c2b1 = (const float*)d_in[7];
    const float* c2w2 = (const float*)d_in[8];
    const float* c2b2 = (const float*)d_in[9];
    const float* c3w1 = (const float*)d_in[10];
    const float* c3b1 = (const float*)d_in[11];
    const float* c3w2 = (const float*)d_in[12];
    const float* c3b2 = (const float*)d_in[13];
    const float* ow1  = (const float*)d_in[14];
    const float* ob1  = (const float*)d_in[15];
    const float* ow2  = (const float*)d_in[16];
    const float* ob2  = (const float*)d_in[17];
    const float* ow3  = (const float*)d_in[18];
    const float* ob3  = (const float*)d_in[19];

    float *pX, *pPQ, *pH1; int* pidx; __half* pXh; uint32_t *pWh, *pWl;
    cudaGetSymbolAddress((void**)&pX,  g_X453);
    cudaGetSymbolAddress((void**)&pXh, g_Xh);
    cudaGetSymbolAddress((void**)&pPQ, g_PQ);
    cudaGetSymbolAddress((void**)&pH1, g_H1);
    cudaGetSymbolAddress((void**)&pWh, g_Wth);
    cudaGetSymbolAddress((void**)&pWl, g_Wtl);
    cudaGetSymbolAddress((void**)&pidx, g_idx);

    const int SMEM_3 = 2 * (2 * AHLU + 2 * BHLU) * 4;   // 61,440 B
    const int SMEM_2 = 2 * (2 * AHLU + 1 * BHLU) * 4;   // 51,200 B
    cudaFuncSetAttribute(hfgemm_k<0, 0, 0, 0, 0, 1, 0>, cudaFuncAttributeMaxDynamicSharedMemorySize, SMEM_3);
    cudaFuncSetAttribute(hfgemm_k<1, 1, 1, 0, 0, 1, 0>, cudaFuncAttributeMaxDynamicSharedMemorySize, SMEM_3);
    cudaFuncSetAttribute(hfgemm_k<0, 0, 0, 1, 1, 0, 0>, cudaFuncAttributeMaxDynamicSharedMemorySize, SMEM_2);
    cudaFuncSetAttribute(hfgemm_k<1, 1, 1, 1, 1, 0, 0>, cudaFuncAttributeMaxDynamicSharedMemorySize, SMEM_2);
    cudaFuncSetAttribute(hfgemm_k<0, 1, 0, 1, 1, 0, 0>, cudaFuncAttributeMaxDynamicSharedMemorySize, SMEM_2);
    cudaFuncSetAttribute(hfgemm_k<0, 1, 0, 1, 0, 0, 1>, cudaFuncAttributeMaxDynamicSharedMemorySize, SMEM_2);

    const int MT_P = NPTS / 128;   // 1024
    const int MT_E = NEDG / 128;   // 4096

    copy_features_k<<<(NPTS * 5 + 255) / 256, 256>>>(features, pX, pXh);

    // ===== EdgeConv 1 (C=5, H=32, O=64) — feeds knn2: fp16 3-term =====
    knn_k<2, 4><<<512, 256>>>(coords, 2, 0, pidx);
    prep_pq_k<<<(64 * 16 + 255) / 256, 256>>>(c1w1, pWh, pWl, 5, 32, 16);
    hfgemm_k<0, 0, 0, 0, 0, 1, 0><<<dim3(1, MT_P), 256, SMEM_3>>>(pX, XLD, 5, nullptr, 0, 0, nullptr, nullptr,
                                                                  pWh, pWl, 32, nullptr, pPQ, 64, 0, 64, nullptr, nullptr, nullptr);
    prep_wt_k<<<(64 * 16 + 255) / 256, 256>>>(c1w2, pWh, pWl, 32, 64, 16);
    hfgemm_k<1, 1, 1, 0, 0, 1, 0><<<dim3(1, MT_E), 256, SMEM_3>>>(nullptr, 0, 32, pPQ, 64, 32, c1b1, pidx,
                                                                  pWh, pWl, 32, c1b2, pX, XLD, O1_OFS, 64, pXh, nullptr, nullptr);

    // ===== EdgeConv 2 (C=64, H=96, O=128) — feeds knn3: fp16 3-term =====
    knn_k<64, 64><<<512, 256>>>(pX, XLD, O1_OFS, pidx);
    prep_pq_k<<<(192 * 32 + 255) / 256, 256>>>(c2w1, pWh, pWl, 64, 96, 32);
    hfgemm_k<0, 0, 0, 0, 0, 1, 0><<<dim3(3, MT_P), 256, SMEM_3>>>(pX + O1_OFS, XLD, 64, nullptr, 0, 0, nullptr, nullptr,
                                                                  pWh, pWl, 64, nullptr, pPQ, 192, 0, 192, nullptr, nullptr, nullptr);
    prep_wt_k<<<(128 * 48 + 255) / 256, 256>>>(c2w2, pWh, pWl, 96, 128, 48);
    hfgemm_k<1, 1, 1, 0, 0, 1, 0><<<dim3(2, MT_E), 256, SMEM_3>>>(nullptr, 0, 96, pPQ, 192, 96, c2b1, pidx,
                                                                  pWh, pWl, 96, c2b2, pX, XLD, O2_OFS, 128, pXh, nullptr, nullptr);

    // ===== EdgeConv 3 — post-KNN: fp16; PQ3 from Xh (1-term); out3 fp16-only =====
    knn_k<128, 128><<<512, 256>>>(pX, XLD, O2_OFS, pidx);
    prep_pq_k<<<(384 * 64 + 255) / 256, 256>>>(c3w1, pWh, pWl, 128, 192, 64);
    hfgemm_k<0, 0, 0, 1, 1, 0, 0><<<dim3(6, MT_P), 256, SMEM_2>>>((const float*)(pXh + O2_OFS), XLD, 128,
                                                                  nullptr, 0, 0, nullptr, nullptr,
                                                                  pWh, pWl, 128, nullptr, pPQ, 384, 0, 384, nullptr, nullptr, nullptr);
    prep_wt_k<<<(256 * 96 + 255) / 256, 256>>>(c3w2, pWh, pWl, 192, 256, 96);
    hfgemm_k<1, 1, 1, 1, 1, 0, 0><<<dim3(4, MT_E), 256, SMEM_2>>>(nullptr, 0, 192, pPQ, 384, 192, c3b1, pidx,
                                                                  pWh, pWl, 192, c3b2, (float*)pXh, XLD, O3_OFS, 256, nullptr, nullptr, nullptr);

    // ===== Head — h1: A from Xh (1-term), H1 fp16; h2: fused head3 epilogue =====
    prep_head_k<<<(453 * 240 + 255) / 256, 256>>>(ow1, pWh, pWl, 453, 240);
    hfgemm_k<0, 1, 0, 1, 1, 0, 0><<<dim3(8, MT_P), 256, SMEM_2>>>((const float*)pXh, XLD, 456,
                                                                  nullptr, 0, 0, nullptr, nullptr,
                                                                  pWh, pWl, 480, ob1, pH1, 456, 0, 453, nullptr, nullptr, nullptr);
    prep_wt_k<<<(226 * 240 + 255) / 256, 256>>>(ow2, pWh, pWl, 453, 226, 240);
    hfgemm_k<0, 1, 0, 1, 0, 0, 1><<<dim3(4, MT_P), 256, SMEM_2>>>(pH1, 456, 456, nullptr, 0, 0, nullptr, nullptr,
                                                                  pWh, pWl, 480, ob2, nullptr, 0, 0, 226, nullptr, ow3, pPQ);
    head3r_k<<<(NPTS + 255) / 256, 256>>>(pPQ, ob3, (float*)d_out);
}

// round 16
// speedup vs baseline: 1.2719x; 1.0007x over previous
#include <cuda_runtime.h>
#include <cuda_fp16.h>
#include <cstdint>
#include <math.h>

// ============================ problem constants ============================
#define NPTS 131072          // B*N = 1024*128
#define NEDG 524288          // NPTS * K(=4)

// Concat buffer layout (all segment starts 16B-aligned; pads never written => 0)
#define F_OFS  0
#define O1_OFS 8
#define O2_OFS 72
#define O3_OFS 200
#define XLD    456

// packed-weight plane offsets (u32 units); all preps hoisted to graph front
#define OW_PQ1 0            // 64  x 16
#define OW_G1  1024         // 64  x 16
#define OW_PQ2 2048         // 192 x 32
#define OW_G2  8192         // 128 x 48
#define OW_PQ3 14336        // 384 x 64
#define OW_G3  38912        // 256 x 96
#define OW_H1  63488        // 453 x 240 (padded-K head layout)
#define OW_H2  172208       // 226 x 240
#define OW_TOT 226448

// ============================ device scratch ===============================
__device__ float    g_X453[(size_t)NPTS * XLD];   // fp32 concat (KNN reads)
__device__ __half   g_Xh[(size_t)NPTS * XLD];     // fp16 mirror (post-KNN A source)
__device__ float    g_PQ[(size_t)NPTS * 384];     // fp32 PQ1/PQ2; fp16 PQ3; head3 partials
__device__ float    g_H1[(size_t)NPTS * 456];     // fp16 H1 (ld 456 halves)
__device__ int      g_idx[NPTS * 4];
__device__ uint32_t g_Wth[OW_TOT];                // packed fp16 hi plane
__device__ uint32_t g_Wtl[OW_TOT];                // packed fp16 lo plane

__device__ __forceinline__ float eluf(float x) { return x > 0.f ? x : expm1f(x); }

// ============================ small helpers ================================
__device__ __forceinline__ void sp_hf(float a0, float a1, uint32_t& h, uint32_t& l) {
    __half2 hh = __floats2half2_rn(a0, a1);
    float r0 = a0 - __half2float(__low2half(hh));
    float r1 = a1 - __half2float(__high2half(hh));
    __half2 ll = __floats2half2_rn(r0, r1);
    h = *reinterpret_cast<uint32_t*>(&hh);
    l = *reinterpret_cast<uint32_t*>(&ll);
}
__device__ __forceinline__ void mma16h(float* c, const uint32_t* a, const uint32_t* b) {
    asm volatile("mma.sync.aligned.m16n8k16.row.col.f32.f16.f16.f32 "
                 "{%0,%1,%2,%3}, {%4,%5,%6,%7}, {%8,%9}, {%0,%1,%2,%3};"
                 : "+f"(c[0]), "+f"(c[1]), "+f"(c[2]), "+f"(c[3])
                 : "r"(a[0]), "r"(a[1]), "r"(a[2]), "r"(a[3]), "r"(b[0]), "r"(b[1]));
}

// ============================ elementwise helpers ==========================
__global__ void copy_features_k(const float* __restrict__ f, float* __restrict__ X,
                                __half* __restrict__ Xh) {
    int e = blockIdx.x * blockDim.x + threadIdx.x;
    if (e < NPTS * 5) {
        int r = e / 5, c = e % 5;
        X[(size_t)r * XLD + c] = f[e];
        Xh[(size_t)r * XLD + c] = __float2half(f[e]);
    }
}
// PQ-combined weights -> packed fp16 hi/lo planes [n][Kpad/2]
__global__ void prep_pq_k(const float* __restrict__ w1, uint32_t* __restrict__ wh,
                          uint32_t* __restrict__ wl, int C, int H, int Kpad2) {
    int e = blockIdx.x * blockDim.x + threadIdx.x;
    if (e >= 2 * H * Kpad2) return;
    int n = e / Kpad2, j = e % Kpad2;
    float v0 = 0.f, v1 = 0.f;
    int k0 = 2 * j, k1 = 2 * j + 1;
    if (k0 < C) v0 = (n < H) ? (w1[k0 * H + n] - w1[(C + k0) * H + n]) : w1[(C + k0) * H + (n - H)];
    if (k1 < C) v1 = (n < H) ? (w1[k1 * H + n] - w1[(C + k1) * H + n]) : w1[(C + k1) * H + (n - H)];
    uint32_t h, l; sp_hf(v0, v1, h, l);
    wh[(size_t)n * Kpad2 + j] = h;
    wl[(size_t)n * Kpad2 + j] = l;
}
__global__ void prep_wt_k(const float* __restrict__ w, uint32_t* __restrict__ wh,
                          uint32_t* __restrict__ wl, int K, int N, int Kpad2) {
    int e = blockIdx.x * blockDim.x + threadIdx.x;
    if (e >= N * Kpad2) return;
    int n = e / Kpad2, j = e % Kpad2;
    int k0 = 2 * j, k1 = 2 * j + 1;
    float v0 = (k0 < K) ? w[(size_t)k0 * N + n] : 0.f;
    float v1 = (k1 < K) ? w[(size_t)k1 * N + n] : 0.f;
    uint32_t h, l; sp_hf(v0, v1, h, l);
    wh[(size_t)n * Kpad2 + j] = h;
    wl[(size_t)n * Kpad2 + j] = l;
}
// head-1 weights vs padded concat layout
__global__ void prep_head_k(const float* __restrict__ w, uint32_t* __restrict__ wh,
                            uint32_t* __restrict__ wl, int N, int Kpad2) {
    int e = blockIdx.x * blockDim.x + threadIdx.x;
    if (e >= N * Kpad2) return;
    int n = e / Kpad2, j = e % Kpad2;
    float v[2];
    #pragma unroll
    for (int i = 0; i < 2; i++) {
        int kp = 2 * j + i;
        float x = 0.f;
        if (kp < 5)                   x = w[(size_t)kp * N + n];
        else if (kp >= 8 && kp < 456) x = w[(size_t)(kp - 3) * N + n];
        v[i] = x;
    }
    uint32_t h, l; sp_hf(v[0], v[1], h, l);
    wh[(size_t)n * Kpad2 + j] = h;
    wl[(size_t)n * Kpad2 + j] = l;
}

// ============================ KNN (k=4; 2 batches per block; FROZEN) =======
template<int C, int CP>
__global__ void __launch_bounds__(256) knn_k(const float* __restrict__ x, int ld, int cofs,
                                             int* __restrict__ idxout) {
    constexpr int PAD = CP + 4;
    __shared__ __align__(16) float sx[2][32][PAD];
    __shared__ float sn[2][128];
    int half = threadIdx.x >> 7;
    int tid = threadIdx.x & 127;
    int b = blockIdx.x * 2 + half;
    const float* xb = x + (size_t)b * 128 * ld + cofs;
    float4 xi[CP / 4];

    for (int t = 0; t < 4; t++) {
        for (int e = tid; e < 32 * CP; e += 128) {
            int r = e / CP, c = e % CP;
            sx[half][r][c] = (c < C) ? xb[(size_t)(t * 32 + r) * ld + c] : 0.f;
        }
        __syncthreads();
        if ((tid >> 5) == t) {
            int r = tid & 31;
            #pragma unroll
            for (int c4 = 0; c4 < CP / 4; c4++) xi[c4] = *(const float4*)&sx[half][r][4 * c4];
        }
        __syncthreads();
    }
    float ni = 0.f;
    #pragma unroll
    for (int c4 = 0; c4 < CP / 4; c4++)
        ni += xi[c4].x * xi[c4].x + xi[c4].y * xi[c4].y + xi[c4].z * xi[c4].z + xi[c4].w * xi[c4].w;
    sn[half][tid] = ni;
    __syncthreads();

    float bd0 = 1e30f, bd1 = 1e30f, bd2 = 1e30f, bd3 = 1e30f;
    int   bi0 = 0,     bi1 = 0,     bi2 = 0,     bi3 = 0;

    for (int t = 0; t < 4; t++) {
        for (int e = tid; e < 32 * CP; e += 128) {
            int r = e / CP, c = e % CP;
            sx[half][r][c] = (c < C) ? xb[(size_t)(t * 32 + r) * ld + c] : 0.f;
        }
        __syncthreads();
        for (int jl = 0; jl < 32; jl++) {
            int j = t * 32 + jl;
            float dot = 0.f;
            #pragma unroll
            for (int c4 = 0; c4 < CP / 4; c4++) {
                float4 xj = *(const float4*)&sx[half][jl][4 * c4];
                dot += xi[c4].x * xj.x + xi[c4].y * xj.y + xi[c4].z * xj.z + xi[c4].w * xj.w;
            }
            float d = ni + sn[half][j] - 2.f * dot;
            if (j == tid) d = 1e30f;
            if (d < bd3) {
                if (d < bd2) {
                    bd3 = bd2; bi3 = bi2;
                    if (d < bd1) {
                        bd2 = bd1; bi2 = bi1;
                        if (d < bd0) { bd1 = bd0; bi1 = bi0; bd0 = d; bi0 = j; }
                        else         { bd1 = d; bi1 = j; }
                    } else { bd2 = d; bi2 = j; }
                } else { bd3 = d; bi3 = j; }
            }
        }
        __syncthreads();
    }
    int base = (b * 128 + tid) * 4;
    int gb = b * 128;
    idxout[base + 0] = gb + bi0;
    idxout[base + 1] = gb + bi1;
    idxout[base + 2] = gb + bi2;
    idxout[base + 3] = gb + bi3;
}

// ============================ fp16 GEMM (unified) ==========================
// A: fp32 source -> hi+lo fp16 planes; fp16 source (INH, dense) -> exact 1 plane.
// B: pre-packed fp16 planes; B3=1 uses hi+lo (3-term), B3=0 hi only.
// OUTH: fp16 output. Xh2: fp16 mirror for RED fp32 out.
// H3: fused final-layer epilogue — partial dots with w3 into Part.
#define APU 20
#define AHLU (128 * APU)
#define BHLU (64 * APU)
template<int GATHER, int ACT, int RED, int INH, int OUTH, int B3, int H3>
__global__ void __launch_bounds__(256, 2) hfgemm_k(
    const float* __restrict__ A, int lda, int Kval,
    const float* __restrict__ PQ, int ldpq, int qofs,
    const float* __restrict__ b1, const int* __restrict__ eidx,
    const uint32_t* __restrict__ Wth, const uint32_t* __restrict__ Wtl, int Kpad,
    const float* __restrict__ bias,
    float* __restrict__ Co, int ldc, int cofs, int Nfull,
    __half* __restrict__ Xh2,
    const float* __restrict__ w3, float* __restrict__ Part)
{
    constexpr int ATERMS = (INH && !GATHER) ? 1 : 2;
    constexpr int STGU = 2 * AHLU + (B3 ? 2 : 1) * BHLU;
    extern __shared__ uint32_t smu[];
    const int tid = threadIdx.x;
    const int wid = tid >> 5, lane = tid & 31;
    const int g = lane >> 2, q = lane & 3;
    const int warp_m = wid >> 1, warp_n = wid & 1;
    const int m0 = blockIdx.y * 128;
    const int n0 = blockIdx.x * 64;
    const int iters = Kpad >> 5;
    const int Kpad2 = Kpad >> 1;

    const int lm = tid >> 3, lkc = (tid & 7) << 2;
    const int luc = (tid & 7) << 1;
    const int lr = tid >> 1, lh = (tid & 1) << 4;
    const int lgu = (tid & 1) << 3;

    const float *Pp = nullptr, *Qp = nullptr;
    const __half *Pph = nullptr, *Qph = nullptr;
    if (GATHER) {
        int mg = m0 + lr;
        if (INH) {
            Pph = (const __half*)PQ + (size_t)(mg >> 2) * ldpq;
            Qph = (const __half*)PQ + (size_t)eidx[mg] * ldpq + qofs;
        } else {
            Pp = PQ + (size_t)(mg >> 2) * ldpq;
            Qp = PQ + (size_t)eidx[mg] * ldpq + qofs;
        }
    }

    float4 rA[4], rQ[4];
    uint2 rAh[4];
    uint4 rPh[2], rQh[2];
    uint2 rBh[2], rBl[2];

    auto ldg_tile = [&](int it) {
        const int k0 = it << 5;
        if (GATHER) {
            if (INH) {
                rPh[0] = *(const uint4*)(Pph + k0 + lh);
                rPh[1] = *(const uint4*)(Pph + k0 + lh + 8);
                rQh[0] = *(const uint4*)(Qph + k0 + lh);
                rQh[1] = *(const uint4*)(Qph + k0 + lh + 8);
            } else {
                #pragma unroll
                for (int qq = 0; qq < 4; qq++) {
                    int kk = k0 + lh + (qq << 2);
                    rA[qq] = *(const float4*)(Pp + kk);
                    rQ[qq] = *(const float4*)(Qp + kk);
                }
            }
        } else if (INH) {
            #pragma unroll
            for (int i = 0; i < 4; i++) {
                int gk = k0 + lkc;
                const __half* src = (const __half*)A + (size_t)(m0 + lm + i * 32) * lda + gk;
                if (gk + 3 < Kval) rAh[i] = *(const uint2*)src;
                else               rAh[i] = make_uint2(0u, 0u);
            }
        } else {
            #pragma unroll
            for (int i = 0; i < 4; i++) {
                int gk = k0 + lkc;
                const float* src = A + (size_t)(m0 + lm + i * 32) * lda + gk;
                if (gk + 3 < Kval) {
                    rA[i] = *(const float4*)src;
                } else {
                    rA[i] = make_float4(0.f, 0.f, 0.f, 0.f);
                    if (gk + 0 < Kval) rA[i].x = src[0];
                    if (gk + 1 < Kval) rA[i].y = src[1];
                    if (gk + 2 < Kval) rA[i].z = src[2];
                }
            }
        }
        const int ku = (k0 + lkc) >> 1;
        #pragma unroll
        for (int i = 0; i < 2; i++) {
            int gn = n0 + lm + i * 32;
            if (gn < Nfull) {
                rBh[i] = *(const uint2*)(Wth + (size_t)gn * Kpad2 + ku);
                if (B3) rBl[i] = *(const uint2*)(Wtl + (size_t)gn * Kpad2 + ku);
            } else {
                rBh[i] = make_uint2(0u, 0u);
                if (B3) rBl[i] = make_uint2(0u, 0u);
            }
        }
    };

    auto sts_tile = [&](int s, int it) {
        uint32_t* Ah = smu + s * STGU;
        uint32_t* Al = Ah + AHLU;
        uint32_t* Bh = smu + s * STGU + 2 * AHLU;
        uint32_t* Bl = Bh + BHLU;
        if (GATHER) {
            const int k0 = it << 5;
            if (INH) {
                const uint32_t* pw = (const uint32_t*)rPh;
                const uint32_t* qw = (const uint32_t*)rQh;
                #pragma unroll
                for (int qq = 0; qq < 4; qq++) {
                    int kk = lh + (qq << 2);
                    float4 bv = *(const float4*)(b1 + k0 + kk);
                    float2 p0 = __half22float2(*(const __half2*)&pw[2 * qq]);
                    float2 p1 = __half22float2(*(const __half2*)&pw[2 * qq + 1]);
                    float2 q0 = __half22float2(*(const __half2*)&qw[2 * qq]);
                    float2 q1 = __half22float2(*(const __half2*)&qw[2 * qq + 1]);
                    float v0 = eluf(p0.x + q0.x + bv.x);
                    float v1 = eluf(p0.y + q0.y + bv.y);
                    float v2 = eluf(p1.x + q1.x + bv.z);
                    float v3 = eluf(p1.y + q1.y + bv.w);
                    uint32_t h0, l0, h1, l1;
                    sp_hf(v0, v1, h0, l0);
                    sp_hf(v2, v3, h1, l1);
                    *(uint2*)&Ah[lr * APU + lgu + (qq << 1)] = make_uint2(h0, h1);
                    *(uint2*)&Al[lr * APU + lgu + (qq << 1)] = make_uint2(l0, l1);
                }
            } else {
                #pragma unroll
                for (int qq = 0; qq < 4; qq++) {
                    int kk = lh + (qq << 2);
                    float4 bv = *(const float4*)(b1 + k0 + kk);
                    float v0 = eluf(rA[qq].x + rQ[qq].x + bv.x);
                    float v1 = eluf(rA[qq].y + rQ[qq].y + bv.y);
                    float v2 = eluf(rA[qq].z + rQ[qq].z + bv.z);
                    float v3 = eluf(rA[qq].w + rQ[qq].w + bv.w);
                    uint32_t h0, l0, h1, l1;
                    sp_hf(v0, v1, h0, l0);
                    sp_hf(v2, v3, h1, l1);
                    *(uint2*)&Ah[lr * APU + lgu + (qq << 1)] = make_uint2(h0, h1);
                    *(uint2*)&Al[lr * APU + lgu + (qq << 1)] = make_uint2(l0, l1);
                }
            }
        } else if (INH) {
            #pragma unroll
            for (int i = 0; i < 4; i++)
                *(uint2*)&Ah[(lm + i * 32) * APU + luc] = rAh[i];
        } else {
            #pragma unroll
            for (int i = 0; i < 4; i++) {
                uint32_t h0, l0, h1, l1;
                sp_hf(rA[i].x, rA[i].y, h0, l0);
                sp_hf(rA[i].z, rA[i].w, h1, l1);
                *(uint2*)&Ah[(lm + i * 32) * APU + luc] = make_uint2(h0, h1);
                *(uint2*)&Al[(lm + i * 32) * APU + luc] = make_uint2(l0, l1);
            }
        }
        #pragma unroll
        for (int i = 0; i < 2; i++) {
            *(uint2*)&Bh[(lm + i * 32) * APU + luc] = rBh[i];
            if (B3) *(uint2*)&Bl[(lm + i * 32) * APU + luc] = rBl[i];
        }
    };

    float acc[2][4][4];
    #pragma unroll
    for (int mt = 0; mt < 2; mt++)
        #pragma unroll
        for (int nt = 0; nt < 4; nt++)
            #pragma unroll
            for (int i = 0; i < 4; i++) acc[mt][nt][i] = 0.f;

    const int abase = (warp_m * 32 + g) * APU;
    const int bbase = (warp_n * 32 + g) * APU;

    ldg_tile(0);
    sts_tile(0, 0);
    for (int it = 0; it < iters; it++) {
        if (it + 1 < iters) ldg_tile(it + 1);
        __syncthreads();
        const int s = it & 1;
        const uint32_t* Ah = smu + s * STGU;
        const uint32_t* Al = Ah + AHLU;
        const uint32_t* Bh = smu + s * STGU + 2 * AHLU;
        const uint32_t* Bl = Bh + BHLU;
        #pragma unroll
        for (int ks = 0; ks < 2; ks++) {
            const int koff = (ks << 3) + q;
            uint32_t ah[2][4], al[2][4];
            #pragma unroll
            for (int mt = 0; mt < 2; mt++) {
                int rb = abase + mt * 16 * APU;
                ah[mt][0] = Ah[rb + koff];
                ah[mt][1] = Ah[rb + 8 * APU + koff];
                ah[mt][2] = Ah[rb + koff + 4];
                ah[mt][3] = Ah[rb + 8 * APU + koff + 4];
                if (ATERMS == 2) {
                    al[mt][0] = Al[rb + koff];
                    al[mt][1] = Al[rb + 8 * APU + koff];
                    al[mt][2] = Al[rb + koff + 4];
                    al[mt][3] = Al[rb + 8 * APU + koff + 4];
                }
            }
            uint32_t bh[4][2], bl[4][2];
            #pragma unroll
            for (int nt = 0; nt < 4; nt++) {
                int rb = bbase + nt * 8 * APU;
                bh[nt][0] = Bh[rb + koff];
                bh[nt][1] = Bh[rb + koff + 4];
                if (B3) {
                    bl[nt][0] = Bl[rb + koff];
                    bl[nt][1] = Bl[rb + koff + 4];
                }
            }
            #pragma unroll
            for (int mt = 0; mt < 2; mt++)
                #pragma unroll
                for (int nt = 0; nt < 4; nt++) {
                    mma16h(acc[mt][nt], ah[mt], bh[nt]);
                    if (ATERMS == 2) mma16h(acc[mt][nt], al[mt], bh[nt]);
                    if (B3) mma16h(acc[mt][nt], ah[mt], bl[nt]);
                }
        }
        if (it + 1 < iters) sts_tile((it + 1) & 1, it + 1);
    }

    // ============================== epilogue ==============================
    if (H3) {
        #pragma unroll
        for (int mt = 0; mt < 2; mt++) {
            const int rbase = m0 + warp_m * 32 + mt * 16;
            float s00 = 0.f, s01 = 0.f, s10 = 0.f, s11 = 0.f;
            #pragma unroll
            for (int nt = 0; nt < 4; nt++) {
                const int gc = n0 + warp_n * 32 + nt * 8 + 2 * q;
                float w30 = 0.f, w31 = 0.f, w40 = 0.f, w41 = 0.f;
                float bb0 = 0.f, bb1 = 0.f;
                if (gc < Nfull)     { w30 = w3[2 * gc];     w31 = w3[2 * gc + 1]; bb0 = bias[gc]; }
                if (gc + 1 < Nfull) { w40 = w3[2 * gc + 2]; w41 = w3[2 * gc + 3]; bb1 = bias[gc + 1]; }
                float e0 = eluf(acc[mt][nt][0] + bb0), e1 = eluf(acc[mt][nt][1] + bb1);
                float e2 = eluf(acc[mt][nt][2] + bb0), e3 = eluf(acc[mt][nt][3] + bb1);
                s00 += e0 * w30 + e1 * w40;  s01 += e0 * w31 + e1 * w41;
                s10 += e2 * w30 + e3 * w40;  s11 += e2 * w31 + e3 * w41;
            }
            s00 += __shfl_xor_sync(0xffffffffu, s00, 1); s00 += __shfl_xor_sync(0xffffffffu, s00, 2);
            s01 += __shfl_xor_sync(0xffffffffu, s01, 1); s01 += __shfl_xor_sync(0xffffffffu, s01, 2);
            s10 += __shfl_xor_sync(0xffffffffu, s10, 1); s10 += __shfl_xor_sync(0xffffffffu, s10, 2);
            s11 += __shfl_xor_sync(0xffffffffu, s11, 1); s11 += __shfl_xor_sync(0xffffffffu, s11, 2);
            if (q == 0) {
                const int grp = blockIdx.x * 2 + warp_n;      // 0..7
                float* p0 = Part + (size_t)(rbase + g) * 16 + grp * 2;
                float* p1 = Part + (size_t)(rbase + g + 8) * 16 + grp * 2;
                p0[0] = s00; p0[1] = s01;
                p1[0] = s10; p1[1] = s11;
            }
        }
        return;
    }
    #pragma unroll
    for (int mt = 0; mt < 2; mt++) {
        const int rbase = m0 + warp_m * 32 + mt * 16;
        #pragma unroll
        for (int nt = 0; nt < 4; nt++) {
            const int cl = warp_n * 32 + nt * 8 + 2 * q;
            const int gc = n0 + cl;
            float bb0 = 0.f, bb1 = 0.f;
            if (bias != nullptr) {
                if (gc < Nfull)     bb0 = bias[gc];
                if (gc + 1 < Nfull) bb1 = bias[gc + 1];
            }
            if (!RED) {
                float v0 = acc[mt][nt][0] + bb0, v1 = acc[mt][nt][1] + bb1;
                float v2 = acc[mt][nt][2] + bb0, v3 = acc[mt][nt][3] + bb1;
                if (ACT) { v0 = eluf(v0); v1 = eluf(v1); v2 = eluf(v2); v3 = eluf(v3); }
                if (OUTH) {
                    __half* o0 = (__half*)Co + (size_t)(rbase + g) * ldc + cofs;
                    __half* o1 = o0 + (size_t)8 * ldc;
                    if (gc + 1 < Nfull) {
                        *(__half2*)(o0 + gc) = __floats2half2_rn(v0, v1);
                        *(__half2*)(o1 + gc) = __floats2half2_rn(v2, v3);
                    } else if (gc < Nfull) {
                        o0[gc] = __float2half(v0);
                        o1[gc] = __float2half(v2);
                    }
                } else {
                    float* r0 = Co + (size_t)(rbase + g) * ldc + cofs;
                    float* r1 = r0 + (size_t)8 * ldc;
                    if (gc < Nfull)     { r0[gc] = v0;     r1[gc] = v2; }
                    if (gc + 1 < Nfull) { r0[gc + 1] = v1; r1[gc + 1] = v3; }
                }
            } else {
                #pragma unroll
                for (int half = 0; half < 2; half++) {
                    float v0 = (gc < Nfull)     ? eluf(acc[mt][nt][2 * half + 0] + bb0) : 0.f;
                    float v1 = (gc + 1 < Nfull) ? eluf(acc[mt][nt][2 * half + 1] + bb1) : 0.f;
                    v0 += __shfl_xor_sync(0xffffffffu, v0, 4);
                    v0 += __shfl_xor_sync(0xffffffffu, v0, 8);
                    v1 += __shfl_xor_sync(0xffffffffu, v1, 4);
                    v1 += __shfl_xor_sync(0xffffffffu, v1, 8);
                    if ((lane & 12) == 0) {
                        int p = (rbase + half * 8 + g) >> 2;
                        float o0 = 0.25f * v0, o1 = 0.25f * v1;
                        if (OUTH) {
                            __half* op = (__half*)Co + (size_t)p * ldc + cofs;
                            if (gc + 1 < Nfull) *(__half2*)(op + gc) = __floats2half2_rn(o0, o1);
                            else if (gc < Nfull) op[gc] = __float2half(o0);
                        } else {
                            float* op = Co + (size_t)p * ldc + cofs;
                            if (gc < Nfull)     op[gc] = o0;
                            if (gc + 1 < Nfull) op[gc + 1] = o1;
                            if (Xh2 != nullptr) {
                                __half* oh = Xh2 + (size_t)p * XLD + cofs;
                                if (gc + 1 < Nfull) *(__half2*)(oh + gc) = __floats2half2_rn(o0, o1);
                                else if (gc < Nfull) oh[gc] = __float2half(o0);
                            }
                        }
                    }
                }
            }
        }
    }
}

// ============================ head3 partial reduce =========================
__global__ void head3r_k(const float* __restrict__ Part, const float* __restrict__ b,
                         float* __restrict__ out) {
    int p = blockIdx.x * blockDim.x + threadIdx.x;
    if (p >= NPTS) return;
    const float* pr = Part + (size_t)p * 16;
    float a0 = b[0], a1 = b[1];
    #pragma unroll
    for (int gp = 0; gp < 8; gp++) {
        a0 += pr[gp * 2];
        a1 += pr[gp * 2 + 1];
    }
    out[2 * p + 0] = a0;
    out[2 * p + 1] = a1;
}

// ============================ launcher =====================================
extern "C" void kernel_launch(void* const* d_in, const int* in_sizes, int n_in,
                              void* d_out, int out_size) {
    const float* coords   = (const float*)d_in[0];
    const float* features = (const float*)d_in[1];
    const float* c1w1 = (const float*)d_in[2];
    const float* c1b1 = (const float*)d_in[3];
    const float* c1w2 = (const float*)d_in[4];
    const float* c1b2 = (const float*)d_in[5];
    const float* c2w1 = (const float*)d_in[6];
    const float* c2b1 = (const float*)d_in[7];
    const float* c2w2 = (const float*)d_in[8];
    const float* c2b2 = (const float*)d_in[9];
    const float* c3w1 = (const float*)d_in[10];
    const float* c3b1 = (const float*)d_in[11];
    const float* c3w2 = (const float*)d_in[12];
    const float* c3b2 = (const float*)d_in[13];
    const float* ow1  = (const float*)d_in[14];
    const float* ob1  = (const float*)d_in[15];
    const float* ow2  = (const float*)d_in[16];
    const float* ob2  = (const float*)d_in[17];
    const float* ow3  = (const float*)d_in[18];
    const float* ob3  = (const float*)d_in[19];

    float *pX, *pPQ, *pH1; int* pidx; __half* pXh; uint32_t *pWh, *pWl;
    cudaGetSymbolAddress((void**)&pX,  g_X453);
    cudaGetSymbolAddress((void**)&pXh, g_Xh);
    cudaGetSymbolAddress((void**)&pPQ, g_PQ);
    cudaGetSymbolAddress((void**)&pH1, g_H1);
    cudaGetSymbolAddress((void**)&pWh, g_Wth);
    cudaGetSymbolAddress((void**)&pWl, g_Wtl);
    cudaGetSymbolAddress((void**)&pidx, g_idx);

    const int SMEM_3 = 2 * (2 * AHLU + 2 * BHLU) * 4;   // 61,440 B
    const int SMEM_2 = 2 * (2 * AHLU + 1 * BHLU) * 4;   // 51,200 B
    cudaFuncSetAttribute(hfgemm_k<0, 0, 0, 0, 0, 1, 0>, cudaFuncAttributeMaxDynamicSharedMemorySize, SMEM_3);
    cudaFuncSetAttribute(hfgemm_k<1, 1, 1, 0, 0, 1, 0>, cudaFuncAttributeMaxDynamicSharedMemorySize, SMEM_3);
    cudaFuncSetAttribute(hfgemm_k<0, 0, 0, 1, 1, 0, 0>, cudaFuncAttributeMaxDynamicSharedMemorySize, SMEM_2);
    cudaFuncSetAttribute(hfgemm_k<1, 1, 1, 1, 1, 0, 0>, cudaFuncAttributeMaxDynamicSharedMemorySize, SMEM_2);
    cudaFuncSetAttribute(hfgemm_k<0, 1, 0, 1, 1, 0, 0>, cudaFuncAttributeMaxDynamicSharedMemorySize, SMEM_2);
    cudaFuncSetAttribute(hfgemm_k<0, 1, 0, 1, 0, 0, 1>, cudaFuncAttributeMaxDynamicSharedMemorySize, SMEM_2);

    const int MT_P = NPTS / 128;   // 1024
    const int MT_E = NEDG / 128;   // 4096

    // ===== hoisted weight preps (depend only on inputs; run up front) =====
    prep_pq_k<<<(64 * 16 + 255) / 256, 256>>>(c1w1, pWh + OW_PQ1, pWl + OW_PQ1, 5, 32, 16);
    prep_wt_k<<<(64 * 16 + 255) / 256, 256>>>(c1w2, pWh + OW_G1, pWl + OW_G1, 32, 64, 16);
    prep_pq_k<<<(192 * 32 + 255) / 256, 256>>>(c2w1, pWh + OW_PQ2, pWl + OW_PQ2, 64, 96, 32);
    prep_wt_k<<<(128 * 48 + 255) / 256, 256>>>(c2w2, pWh + OW_G2, pWl + OW_G2, 96, 128, 48);
    prep_pq_k<<<(384 * 64 + 255) / 256, 256>>>(c3w1, pWh + OW_PQ3, pWl + OW_PQ3, 128, 192, 64);
    prep_wt_k<<<(256 * 96 + 255) / 256, 256>>>(c3w2, pWh + OW_G3, pWl + OW_G3, 192, 256, 96);
    prep_head_k<<<(453 * 240 + 255) / 256, 256>>>(ow1, pWh + OW_H1, pWl + OW_H1, 453, 240);
    prep_wt_k<<<(226 * 240 + 255) / 256, 256>>>(ow2, pWh + OW_H2, pWl + OW_H2, 453, 226, 240);

    copy_features_k<<<(NPTS * 5 + 255) / 256, 256>>>(features, pX, pXh);

    // ===== EdgeConv 1 (C=5, H=32, O=64) — feeds knn2: fp16 3-term =====
    knn_k<2, 4><<<512, 256>>>(coords, 2, 0, pidx);
    hfgemm_k<0, 0, 0, 0, 0, 1, 0><<<dim3(1, MT_P), 256, SMEM_3>>>(pX, XLD, 5, nullptr, 0, 0, nullptr, nullptr,
                                                                  pWh + OW_PQ1, pWl + OW_PQ1, 32, nullptr, pPQ, 64, 0, 64, nullptr, nullptr, nullptr);
    hfgemm_k<1, 1, 1, 0, 0, 1, 0><<<dim3(1, MT_E), 256, SMEM_3>>>(nullptr, 0, 32, pPQ, 64, 32, c1b1, pidx,
                                                                  pWh + OW_G1, pWl + OW_G1, 32, c1b2, pX, XLD, O1_OFS, 64, pXh, nullptr, nullptr);

    // ===== EdgeConv 2 (C=64, H=96, O=128) — feeds knn3: fp16 3-term =====
    knn_k<64, 64><<<512, 256>>>(pX, XLD, O1_OFS, pidx);
    hfgemm_k<0, 0, 0, 0, 0, 1, 0><<<dim3(3, MT_P), 256, SMEM_3>>>(pX + O1_OFS, XLD, 64, nullptr, 0, 0, nullptr, nullptr,
                                                                  pWh + OW_PQ2, pWl + OW_PQ2, 64, nullptr, pPQ, 192, 0, 192, nullptr, nullptr, nullptr);
    hfgemm_k<1, 1, 1, 0, 0, 1, 0><<<dim3(2, MT_E), 256, SMEM_3>>>(nullptr, 0, 96, pPQ, 192, 96, c2b1, pidx,
                                                                  pWh + OW_G2, pWl + OW_G2, 96, c2b2, pX, XLD, O2_OFS, 128, pXh, nullptr, nullptr);

    // ===== EdgeConv 3 — post-KNN: fp16; PQ3 from Xh (1-term); out3 fp16-only =====
    knn_k<128, 128><<<512, 256>>>(pX, XLD, O2_OFS, pidx);
    hfgemm_k<0, 0, 0, 1, 1, 0, 0><<<dim3(6, MT_P), 256, SMEM_2>>>((const float*)(pXh + O2_OFS), XLD, 128,
                                                                  nullptr, 0, 0, nullptr, nullptr,
                                                                  pWh + OW_PQ3, pWl + OW_PQ3, 128, nullptr, pPQ, 384, 0, 384, nullptr, nullptr, nullptr);
    hfgemm_k<1, 1, 1, 1, 1, 0, 0><<<dim3(4, MT_E), 256, SMEM_2>>>(nullptr, 0, 192, pPQ, 384, 192, c3b1, pidx,
                                                                  pWh + OW_G3, pWl + OW_G3, 192, c3b2, (float*)pXh, XLD, O3_OFS, 256, nullptr, nullptr, nullptr);

    // ===== Head — h1: A from Xh (1-term), H1 fp16; h2: fused head3 epilogue =====
    hfgemm_k<0, 1, 0, 1, 1, 0, 0><<<dim3(8, MT_P), 256, SMEM_2>>>((const float*)pXh, XLD, 456,
                                                                  nullptr, 0, 0, nullptr, nullptr,
                                                                  pWh + OW_H1, pWl + OW_H1, 480, ob1, pH1, 456, 0, 453, nullptr, nullptr, nullptr);
    hfgemm_k<0, 1, 0, 1, 0, 0, 1><<<dim3(4, MT_P), 256, SMEM_2>>>(pH1, 456, 456, nullptr, 0, 0, nullptr, nullptr,
                                                                  pWh + OW_H2, pWl + OW_H2, 480, ob2, nullptr, 0, 0, 226, nullptr, ow3, pPQ);
    head3r_k<<<(NPTS + 255) / 256, 256>>>(pPQ, ob3, (float*)d_out);
}